// round 9
// baseline (speedup 1.0000x reference)
#include <cuda_runtime.h>
#include <cuda_fp16.h>
#include <cstdint>

#define BATCH 4
#define SEQ   4096
#define CH    1024
#define NH    16
#define HD    64
#define BS    64
#define NB    (SEQ / BS)          // 64
#define MROWS (BATCH * SEQ)       // 16384

// ---------------- scratch (device globals: allocation-free) ----------------
__device__ float g_Q[(size_t)MROWS * CH];
__device__ float g_K[(size_t)MROWS * CH];
__device__ float g_V[(size_t)MROWS * CH];
__device__ __half g_Ahi[(size_t)MROWS * CH];
__device__ __half g_Alo[(size_t)MROWS * CH];
__device__ __half g_Phi[(size_t)MROWS * CH];
__device__ __half g_Plo[(size_t)MROWS * CH];
__device__ __half g_Whi[(size_t)4 * CH * CH];

// =================== helpers ===================
__device__ __forceinline__ uint32_t smem_u32(const void* p) {
    uint32_t a;
    asm("{ .reg .u64 t; cvta.to.shared.u64 t, %1; cvt.u32.u64 %0, t; }"
        : "=r"(a) : "l"(p));
    return a;
}
__device__ __forceinline__ void cp16(uint32_t dst, const void* src) {
    asm volatile("cp.async.cg.shared.global [%0], [%1], 16;" :: "r"(dst), "l"(src));
}
__device__ __forceinline__ void cp_commit() {
    asm volatile("cp.async.commit_group;" ::: "memory");
}
template <int N>
__device__ __forceinline__ void cp_wait() {
    asm volatile("cp.async.wait_group %0;" :: "n"(N) : "memory");
}
__device__ __forceinline__ void ldsm4(uint32_t& r0, uint32_t& r1, uint32_t& r2,
                                      uint32_t& r3, uint32_t addr) {
    asm volatile("ldmatrix.sync.aligned.m8n8.x4.shared.b16 {%0,%1,%2,%3}, [%4];"
                 : "=r"(r0), "=r"(r1), "=r"(r2), "=r"(r3) : "r"(addr));
}
__device__ __forceinline__ void mma16816(float* c, const uint32_t* a,
                                         uint32_t b0, uint32_t b1) {
    asm volatile(
        "mma.sync.aligned.m16n8k16.row.col.f32.f16.f16.f32 "
        "{%0,%1,%2,%3}, {%4,%5,%6,%7}, {%8,%9}, {%0,%1,%2,%3};"
        : "+f"(c[0]), "+f"(c[1]), "+f"(c[2]), "+f"(c[3])
        : "r"(a[0]), "r"(a[1]), "r"(a[2]), "r"(a[3]), "r"(b0), "r"(b1));
}

// =================== fp32 -> fp16 hi/lo splitter (8 elems/thread) ==========
__global__ __launch_bounds__(256) void split_f16(
    const float* __restrict__ in, __half* __restrict__ hi,
    __half* __restrict__ lo, int n)
{
    int i = (blockIdx.x * 256 + threadIdx.x) * 8;
    if (i >= n) return;
    float4 v0 = *(const float4*)(in + i);
    float4 v1 = *(const float4*)(in + i + 4);
    float vv[8] = {v0.x, v0.y, v0.z, v0.w, v1.x, v1.y, v1.z, v1.w};
    __half hh[8], ll[8];
#pragma unroll
    for (int t = 0; t < 8; t++) {
        hh[t] = __float2half(vv[t]);
        ll[t] = __float2half(vv[t] - __half2float(hh[t]));
    }
#pragma unroll
    for (int t = 0; t < 8; t += 2) {
        __half2 hp; hp.x = hh[t]; hp.y = hh[t + 1];
        __half2 lp; lp.x = ll[t]; lp.y = ll[t + 1];
        *(__half2*)(hi + i + t) = hp;
        *(__half2*)(lo + i + t) = lp;
    }
}
__global__ __launch_bounds__(256) void to_f16_w4(
    const float* __restrict__ w0, const float* __restrict__ w1,
    const float* __restrict__ w2, const float* __restrict__ w3,
    __half* __restrict__ hi)
{
    const int seg = blockIdx.x >> 10;
    const int loc = (int)(blockIdx.x & 1023) * 1024 + threadIdx.x * 4;
    const float* in = (seg == 0) ? w0 : (seg == 1) ? w1 : (seg == 2) ? w2 : w3;
    float4 v = *(const float4*)(in + loc);
    __half2 hp0; hp0.x = __float2half(v.x); hp0.y = __float2half(v.y);
    __half2 hp1; hp1.x = __float2half(v.z); hp1.y = __float2half(v.w);
    __half* out = hi + (size_t)seg * CH * CH + loc;
    *(__half2*)(out)     = hp0;
    *(__half2*)(out + 2) = hp1;
}

// =================== HMMA GEMM core (BM=BN=128, BK=32, 8 warps) =============
#define BKH 32
#define NKC (CH / BKH)            // 32
#define HT_BYTES 8192
#define HSTAGE (3 * HT_BYTES)
#define HGEMM_SMEM (3 * HSTAGE)   // 73728

__device__ __forceinline__ uint32_t sw_off(int row, int chunk) {
    return (uint32_t)(row * 64 + ((chunk ^ ((row >> 1) & 3)) << 4));
}

__device__ __forceinline__ void gemm_body(
    const __half* __restrict__ Ahi_t, const __half* __restrict__ Alo_t,
    const __half* __restrict__ Bh_t,
    const float* __restrict__ bias, float* __restrict__ Out,
    int bm, int bn, char* dsm)
{
    const uint32_t base = smem_u32(dsm);
    const int tid  = threadIdx.x;
    const int wid  = tid >> 5;
    const int lane = tid & 31;
    const int wm = (wid & 3) * 32;
    const int wn = (wid >> 2) * 64;

    const __half* srcs[3] = { Ahi_t, Alo_t, Bh_t };

    auto load_stage = [&](int st, int kc) {
        const uint32_t sb = base + st * HSTAGE;
#pragma unroll
        for (int p = 0; p < 6; p++) {
            int idx = p * 256 + tid;
            int buf = idx >> 9;
            int rem = idx & 511;
            int row = rem >> 2;
            int ch  = rem & 3;
            const __half* s = srcs[buf] + (size_t)row * CH + kc * BKH + ch * 8;
            cp16(sb + buf * HT_BYTES + sw_off(row, ch), s);
        }
        cp_commit();
    };

    float acc[2][8][4];
#pragma unroll
    for (int mi = 0; mi < 2; mi++)
#pragma unroll
        for (int ni = 0; ni < 8; ni++)
#pragma unroll
            for (int t = 0; t < 4; t++) acc[mi][ni][t] = 0.0f;

    load_stage(0, 0);
    load_stage(1, 1);

    const int lr = lane & 15;
    const int lc = lane >> 4;

    for (int kc = 0; kc < NKC; kc++) {
        if (kc < NKC - 1) cp_wait<1>(); else cp_wait<0>();
        __syncthreads();

        const uint32_t sb = base + (kc % 3) * HSTAGE;
        const uint32_t aHib = sb;
        const uint32_t aLob = sb + HT_BYTES;
        const uint32_t bHib = sb + 2 * HT_BYTES;

#pragma unroll
        for (int ks = 0; ks < 2; ks++) {
            const int chnk = ks * 2 + lc;
            uint32_t ah[2][4], al[2][4], bh[4][4];
#pragma unroll
            for (int mi = 0; mi < 2; mi++) {
                uint32_t off = sw_off(wm + mi * 16 + lr, chnk);
                ldsm4(ah[mi][0], ah[mi][1], ah[mi][2], ah[mi][3], aHib + off);
                ldsm4(al[mi][0], al[mi][1], al[mi][2], al[mi][3], aLob + off);
            }
#pragma unroll
            for (int g = 0; g < 4; g++) {
                uint32_t off = sw_off(wn + g * 16 + lr, chnk);
                ldsm4(bh[g][0], bh[g][1], bh[g][2], bh[g][3], bHib + off);
            }
#pragma unroll
            for (int mi = 0; mi < 2; mi++)
#pragma unroll
                for (int ni = 0; ni < 8; ni++) {
                    const int g = ni >> 1, w = ni & 1;
                    mma16816(acc[mi][ni], ah[mi], bh[g][w], bh[g][w + 2]);
                    mma16816(acc[mi][ni], al[mi], bh[g][w], bh[g][w + 2]);
                }
        }
        if (kc + 2 < NKC) load_stage((kc + 2) % 3, kc + 2);
    }

#pragma unroll
    for (int mi = 0; mi < 2; mi++) {
        const int r0 = bm + wm + mi * 16 + (lane >> 2);
#pragma unroll
        for (int ni = 0; ni < 8; ni++) {
            const int c = bn + wn + ni * 8 + (lane & 3) * 2;
            const float b0 = bias[c], b1 = bias[c + 1];
            float2 v0 = make_float2(acc[mi][ni][0] + b0, acc[mi][ni][1] + b1);
            float2 v1 = make_float2(acc[mi][ni][2] + b0, acc[mi][ni][3] + b1);
            *(float2*)(Out + (size_t)r0 * CH + c)       = v0;
            *(float2*)(Out + (size_t)(r0 + 8) * CH + c) = v1;
        }
    }
}

__global__ __launch_bounds__(256, 2) void gemm_qkv(
    const __half* __restrict__ Ahi, const __half* __restrict__ Alo,
    const __half* __restrict__ Wall,
    const float* __restrict__ bq, const float* __restrict__ bk,
    const float* __restrict__ bv,
    float* __restrict__ Qo, float* __restrict__ Ko, float* __restrict__ Vo)
{
    extern __shared__ char dsm[];
    const int bng = blockIdx.x * 128;
    const int sel = bng >> 10;
    const int bn  = bng & 1023;
    const int bm  = blockIdx.y * 128;
    const float* bias = (sel == 0) ? bq : (sel == 1) ? bk : bv;
    float* Out = (sel == 0) ? Qo : (sel == 1) ? Ko : Vo;
    const __half* Bh = Wall + (size_t)sel * CH * CH + (size_t)bn * CH;
    gemm_body(Ahi + (size_t)bm * CH, Alo + (size_t)bm * CH, Bh, bias, Out, bm, bn, dsm);
}

__global__ __launch_bounds__(256, 2) void gemm_hmma(
    const __half* __restrict__ Ahi, const __half* __restrict__ Alo,
    const __half* __restrict__ Bh,
    const float* __restrict__ bias, float* __restrict__ Out)
{
    extern __shared__ char dsm[];
    const int bm = blockIdx.y * 128;
    const int bn = blockIdx.x * 128;
    gemm_body(Ahi + (size_t)bm * CH, Alo + (size_t)bm * CH,
              Bh + (size_t)bn * CH, bias, Out, bm, bn, dsm);
}

// ---------------- attention: 128-col window, all tiles resident ------------
// smem: qT[64][68] f32 | kT[64][132] f32 | vs[128][68] f32 | Ps[64][132] f16
#define QT_STRIDE 68
#define KT_STRIDE 132
#define VS_STRIDE 68
#define PS_STRIDE 132
#define WIN 128
#define QT_OFF 0
#define KT_OFF (64 * QT_STRIDE)                 // 4352
#define VS_OFF (KT_OFF + 64 * KT_STRIDE)        // 12800
#define PS_OFF (VS_OFF + 128 * VS_STRIDE)       // 21504
#define SMEM_FLOATS (PS_OFF + (64 * PS_STRIDE) / 2)  // 25728
#define ATTN_SMEM_BYTES (SMEM_FLOATS * 4)       // 102912

__global__ __launch_bounds__(256, 2) void attn_kernel(
    const float* __restrict__ Q, const float* __restrict__ K,
    const float* __restrict__ V,
    __half* __restrict__ Ohi, __half* __restrict__ Olo)
{
    extern __shared__ float sm[];
    float*  qT  = sm + QT_OFF;
    float*  kT  = sm + KT_OFF;
    float*  vs  = sm + VS_OFF;
    __half* Ps  = (__half*)(sm + PS_OFF);

    const int tid  = threadIdx.x;
    const int warp = tid >> 5;
    const int lane = tid & 31;
    const int n = blockIdx.x;
    const int h = blockIdx.y;
    const int b = blockIdx.z;
    const size_t base = (size_t)b * SEQ * CH + (size_t)h * HD;

    // ---- load q (transposed), k (transposed), v (natural) up-front
#pragma unroll
    for (int p = 0; p < 4; p++) {
        int idx = tid + p * 256;
        int i   = idx >> 4;
        int dd0 = (idx & 15) << 2;
        float4 v4 = *(const float4*)(Q + base + (size_t)(n * BS + i) * CH + dd0);
        qT[(dd0 + 0) * QT_STRIDE + i] = v4.x;
        qT[(dd0 + 1) * QT_STRIDE + i] = v4.y;
        qT[(dd0 + 2) * QT_STRIDE + i] = v4.z;
        qT[(dd0 + 3) * QT_STRIDE + i] = v4.w;
    }
#pragma unroll
    for (int p = 0; p < 8; p++) {
        int idx = tid + p * 256;
        int j   = idx >> 4;
        int dd0 = (idx & 15) << 2;
        int kpos = (n - 1) * BS + j;
        float4 v4 = make_float4(0.f, 0.f, 0.f, 0.f);
        if (kpos >= 0)
            v4 = *(const float4*)(K + base + (size_t)kpos * CH + dd0);
        kT[(dd0 + 0) * KT_STRIDE + j] = v4.x;
        kT[(dd0 + 1) * KT_STRIDE + j] = v4.y;
        kT[(dd0 + 2) * KT_STRIDE + j] = v4.z;
        kT[(dd0 + 3) * KT_STRIDE + j] = v4.w;
    }
#pragma unroll
    for (int p = 0; p < 8; p++) {
        int idx = tid + p * 256;
        int j   = idx >> 4;
        int dd0 = (idx & 15) << 2;
        int kpos = (n - 1) * BS + j;
        float4 v4 = make_float4(0.f, 0.f, 0.f, 0.f);
        if (kpos >= 0)
            v4 = *(const float4*)(V + base + (size_t)kpos * CH + dd0);
        *(float4*)&vs[j * VS_STRIDE + dd0] = v4;
    }
    __syncthreads();

    // ---- score: warp owns 8 rows (i0), lane owns 4 cols (j0)
    const int i0 = warp << 3;
    const int j0 = lane << 2;
    float acc[8][4];
#pragma unroll
    for (int ii = 0; ii < 8; ii++)
#pragma unroll
        for (int jj = 0; jj < 4; jj++) acc[ii][jj] = 0.0f;

#pragma unroll 4
    for (int dd = 0; dd < 64; dd++) {
        float4 a0 = *(const float4*)&qT[dd * QT_STRIDE + i0];      // broadcast
        float4 a1 = *(const float4*)&qT[dd * QT_STRIDE + i0 + 4];  // broadcast
        float4 b4 = *(const float4*)&kT[dd * KT_STRIDE + j0];
        float a[8] = {a0.x, a0.y, a0.z, a0.w, a1.x, a1.y, a1.z, a1.w};
        float bb[4] = {b4.x, b4.y, b4.z, b4.w};
#pragma unroll
        for (int ii = 0; ii < 8; ii++)
#pragma unroll
            for (int jj = 0; jj < 4; jj++)
                acc[ii][jj] += a[ii] * bb[jj];
    }

    const float scale = 0.125f;
    float mrow[8];
#pragma unroll
    for (int ii = 0; ii < 8; ii++) {
        const int i = i0 + ii;
        mrow[ii] = -1e30f;
#pragma unroll
        for (int jj = 0; jj < 4; jj++) {
            const int j = j0 + jj;
            bool valid = (j <= i + BS) && (n > 0 || j >= BS);
            acc[ii][jj] = valid ? acc[ii][jj] * scale : -1e30f;
            mrow[ii] = fmaxf(mrow[ii], acc[ii][jj]);
        }
    }
#pragma unroll
    for (int ii = 0; ii < 8; ii++) {
        mrow[ii] = fmaxf(mrow[ii], __shfl_xor_sync(0xffffffffu, mrow[ii], 1));
        mrow[ii] = fmaxf(mrow[ii], __shfl_xor_sync(0xffffffffu, mrow[ii], 2));
        mrow[ii] = fmaxf(mrow[ii], __shfl_xor_sync(0xffffffffu, mrow[ii], 4));
        mrow[ii] = fmaxf(mrow[ii], __shfl_xor_sync(0xffffffffu, mrow[ii], 8));
        mrow[ii] = fmaxf(mrow[ii], __shfl_xor_sync(0xffffffffu, mrow[ii], 16));
    }
    float srow[8];
#pragma unroll
    for (int ii = 0; ii < 8; ii++) {
        srow[ii] = 0.f;
#pragma unroll
        for (int jj = 0; jj < 4; jj++) {
            acc[ii][jj] = __expf(acc[ii][jj] - mrow[ii]);
            srow[ii] += acc[ii][jj];
        }
    }
#pragma unroll
    for (int ii = 0; ii < 8; ii++) {
        srow[ii] += __shfl_xor_sync(0xffffffffu, srow[ii], 1);
        srow[ii] += __shfl_xor_sync(0xffffffffu, srow[ii], 2);
        srow[ii] += __shfl_xor_sync(0xffffffffu, srow[ii], 4);
        srow[ii] += __shfl_xor_sync(0xffffffffu, srow[ii], 8);
        srow[ii] += __shfl_xor_sync(0xffffffffu, srow[ii], 16);
        const float inv = 1.0f / srow[ii];
        __half2 p01, p23;
        p01.x = __float2half(acc[ii][0] * inv);
        p01.y = __float2half(acc[ii][1] * inv);
        p23.x = __float2half(acc[ii][2] * inv);
        p23.y = __float2half(acc[ii][3] * inv);
        __half* prow = Ps + (i0 + ii) * PS_STRIDE + j0;
        *(__half2*)(prow)     = p01;
        *(__half2*)(prow + 2) = p23;
    }
    __syncthreads();

    // ---- PV: warp owns 8 rows, lane owns 2 cols; P broadcast over j-pairs
    const int c0 = lane << 1;
    float o[8][2];
#pragma unroll
    for (int ii = 0; ii < 8; ii++) { o[ii][0] = 0.f; o[ii][1] = 0.f; }

    const int jlim = (i0 + 72 < WIN) ? (i0 + 72) : WIN;   // rows' causal edge
#pragma unroll 4
    for (int j = 0; j < jlim; j += 2) {
        float2 va = *(const float2*)&vs[j * VS_STRIDE + c0];
        float2 vb = *(const float2*)&vs[(j + 1) * VS_STRIDE + c0];
#pragma unroll
        for (int ii = 0; ii < 8; ii++) {
            __half2 ph = *(const __half2*)&Ps[(i0 + ii) * PS_STRIDE + j];  // broadcast
            float2 pf = __half22float2(ph);
            o[ii][0] += pf.x * va.x + pf.y * vb.x;
            o[ii][1] += pf.x * va.y + pf.y * vb.y;
        }
    }
#pragma unroll
    for (int ii = 0; ii < 8; ii++) {
        const size_t oidx = base + (size_t)(n * BS + i0 + ii) * CH + c0;
        __half h0 = __float2half(o[ii][0]);
        __half h1 = __float2half(o[ii][1]);
        __half2 hp; hp.x = h0; hp.y = h1;
        __half2 lp;
        lp.x = __float2half(o[ii][0] - __half2float(h0));
        lp.y = __float2half(o[ii][1] - __half2float(h1));
        *(__half2*)(Ohi + oidx) = hp;
        *(__half2*)(Olo + oidx) = lp;
    }
}

// ---------------------------------------------------------------------------
extern "C" void kernel_launch(void* const* d_in, const int* in_sizes, int n_in,
                              void* d_out, int out_size)
{
    const float* x  = (const float*)d_in[0];
    const float* Wq = (const float*)d_in[1];
    const float* bq = (const float*)d_in[2];
    const float* Wk = (const float*)d_in[3];
    const float* bk = (const float*)d_in[4];
    const float* Wv = (const float*)d_in[5];
    const float* bv = (const float*)d_in[6];
    const float* Wo = (const float*)d_in[7];
    const float* bo = (const float*)d_in[8];
    float* out = (float*)d_out;

    float *qp, *kp, *vp;
    __half *ahi, *alo, *phi, *plo, *whi;
    cudaGetSymbolAddress((void**)&qp,  g_Q);
    cudaGetSymbolAddress((void**)&kp,  g_K);
    cudaGetSymbolAddress((void**)&vp,  g_V);
    cudaGetSymbolAddress((void**)&ahi, g_Ahi);
    cudaGetSymbolAddress((void**)&alo, g_Alo);
    cudaGetSymbolAddress((void**)&phi, g_Phi);
    cudaGetSymbolAddress((void**)&plo, g_Plo);
    cudaGetSymbolAddress((void**)&whi, g_Whi);

    cudaFuncSetAttribute(attn_kernel,
                         cudaFuncAttributeMaxDynamicSharedMemorySize, ATTN_SMEM_BYTES);
    cudaFuncSetAttribute(gemm_hmma,
                         cudaFuncAttributeMaxDynamicSharedMemorySize, HGEMM_SMEM);
    cudaFuncSetAttribute(gemm_qkv,
                         cudaFuncAttributeMaxDynamicSharedMemorySize, HGEMM_SMEM);

    const int NX = MROWS * CH;
    const int NW = CH * CH;

    split_f16<<<NX / 2048, 256>>>(x, ahi, alo, NX);
    to_f16_w4<<<4096, 256>>>(Wq, Wk, Wv, Wo, whi);

    gemm_qkv<<<dim3(24, MROWS / 128), 256, HGEMM_SMEM>>>(
        ahi, alo, whi, bq, bk, bv, qp, kp, vp);

    attn_kernel<<<dim3(NB, NH, BATCH), 256, ATTN_SMEM_BYTES>>>(qp, kp, vp, phi, plo);

    gemm_hmma<<<dim3(8, MROWS / 128), 256, HGEMM_SMEM>>>(
        phi, plo, whi + 3 * (size_t)NW, bo, out);
}

// round 10
// speedup vs baseline: 1.0479x; 1.0479x over previous
#include <cuda_runtime.h>
#include <cuda_fp16.h>
#include <cstdint>

#define BATCH 4
#define SEQ   4096
#define CH    1024
#define NH    16
#define HD    64
#define BS    64
#define NB    (SEQ / BS)          // 64
#define MROWS (BATCH * SEQ)       // 16384

// ---------------- scratch (device globals: allocation-free) ----------------
__device__ float g_Q[(size_t)MROWS * CH];
__device__ float g_K[(size_t)MROWS * CH];
__device__ float g_V[(size_t)MROWS * CH];
__device__ __half g_Ahi[(size_t)MROWS * CH];
__device__ __half g_Alo[(size_t)MROWS * CH];
__device__ __half g_Phi[(size_t)MROWS * CH];
__device__ __half g_Plo[(size_t)MROWS * CH];
__device__ __half g_Whi[(size_t)4 * CH * CH];

// =================== helpers ===================
__device__ __forceinline__ uint32_t smem_u32(const void* p) {
    uint32_t a;
    asm("{ .reg .u64 t; cvta.to.shared.u64 t, %1; cvt.u32.u64 %0, t; }"
        : "=r"(a) : "l"(p));
    return a;
}
__device__ __forceinline__ void cp16(uint32_t dst, const void* src) {
    asm volatile("cp.async.cg.shared.global [%0], [%1], 16;" :: "r"(dst), "l"(src));
}
__device__ __forceinline__ void cp_commit() {
    asm volatile("cp.async.commit_group;" ::: "memory");
}
template <int N>
__device__ __forceinline__ void cp_wait() {
    asm volatile("cp.async.wait_group %0;" :: "n"(N) : "memory");
}
__device__ __forceinline__ void ldsm4(uint32_t& r0, uint32_t& r1, uint32_t& r2,
                                      uint32_t& r3, uint32_t addr) {
    asm volatile("ldmatrix.sync.aligned.m8n8.x4.shared.b16 {%0,%1,%2,%3}, [%4];"
                 : "=r"(r0), "=r"(r1), "=r"(r2), "=r"(r3) : "r"(addr));
}
__device__ __forceinline__ void mma16816(float* c, const uint32_t* a,
                                         uint32_t b0, uint32_t b1) {
    asm volatile(
        "mma.sync.aligned.m16n8k16.row.col.f32.f16.f16.f32 "
        "{%0,%1,%2,%3}, {%4,%5,%6,%7}, {%8,%9}, {%0,%1,%2,%3};"
        : "+f"(c[0]), "+f"(c[1]), "+f"(c[2]), "+f"(c[3])
        : "r"(a[0]), "r"(a[1]), "r"(a[2]), "r"(a[3]), "r"(b0), "r"(b1));
}

// =================== fp32 -> fp16 hi/lo splitter ===================
__global__ __launch_bounds__(256) void split_f16(
    const float* __restrict__ in, __half* __restrict__ hi,
    __half* __restrict__ lo, int n)
{
    int i = (blockIdx.x * 256 + threadIdx.x) * 4;
    if (i >= n) return;
    float4 v = *(const float4*)(in + i);
    __half h0 = __float2half(v.x);
    __half h1 = __float2half(v.y);
    __half h2 = __float2half(v.z);
    __half h3 = __float2half(v.w);
    __half2 hp0; hp0.x = h0; hp0.y = h1;
    __half2 hp1; hp1.x = h2; hp1.y = h3;
    __half2 lp0; lp0.x = __float2half(v.x - __half2float(h0));
    lp0.y = __float2half(v.y - __half2float(h1));
    __half2 lp1; lp1.x = __float2half(v.z - __half2float(h2));
    lp1.y = __float2half(v.w - __half2float(h3));
    *(__half2*)(hi + i)     = hp0;
    *(__half2*)(hi + i + 2) = hp1;
    *(__half2*)(lo + i)     = lp0;
    *(__half2*)(lo + i + 2) = lp1;
}
__global__ __launch_bounds__(256) void to_f16_w4(
    const float* __restrict__ w0, const float* __restrict__ w1,
    const float* __restrict__ w2, const float* __restrict__ w3,
    __half* __restrict__ hi)
{
    const int seg = blockIdx.x >> 10;
    const int loc = (int)(blockIdx.x & 1023) * 1024 + threadIdx.x * 4;
    const float* in = (seg == 0) ? w0 : (seg == 1) ? w1 : (seg == 2) ? w2 : w3;
    float4 v = *(const float4*)(in + loc);
    __half2 hp0; hp0.x = __float2half(v.x); hp0.y = __float2half(v.y);
    __half2 hp1; hp1.x = __float2half(v.z); hp1.y = __float2half(v.w);
    __half* out = hi + (size_t)seg * CH * CH + loc;
    *(__half2*)(out)     = hp0;
    *(__half2*)(out + 2) = hp1;
}

// =================== HMMA GEMM core (BM=BN=128, BK=32, 8 warps) =============
#define BKH 32
#define NKC (CH / BKH)            // 32
#define HT_BYTES 8192
#define HSTAGE (3 * HT_BYTES)
#define HGEMM_SMEM (3 * HSTAGE)   // 73728

__device__ __forceinline__ uint32_t sw_off(int row, int chunk) {
    return (uint32_t)(row * 64 + ((chunk ^ ((row >> 1) & 3)) << 4));
}

__device__ __forceinline__ void gemm_body(
    const __half* __restrict__ Ahi_t, const __half* __restrict__ Alo_t,
    const __half* __restrict__ Bh_t,
    const float* __restrict__ bias, float* __restrict__ Out,
    int bm, int bn, char* dsm)
{
    const uint32_t base = smem_u32(dsm);
    const int tid  = threadIdx.x;
    const int wid  = tid >> 5;
    const int lane = tid & 31;
    const int wm = (wid & 3) * 32;
    const int wn = (wid >> 2) * 64;

    const __half* srcs[3] = { Ahi_t, Alo_t, Bh_t };

    auto load_stage = [&](int st, int kc) {
        const uint32_t sb = base + st * HSTAGE;
#pragma unroll
        for (int p = 0; p < 6; p++) {
            int idx = p * 256 + tid;
            int buf = idx >> 9;
            int rem = idx & 511;
            int row = rem >> 2;
            int ch  = rem & 3;
            const __half* s = srcs[buf] + (size_t)row * CH + kc * BKH + ch * 8;
            cp16(sb + buf * HT_BYTES + sw_off(row, ch), s);
        }
        cp_commit();
    };

    float acc[2][8][4];
#pragma unroll
    for (int mi = 0; mi < 2; mi++)
#pragma unroll
        for (int ni = 0; ni < 8; ni++)
#pragma unroll
            for (int t = 0; t < 4; t++) acc[mi][ni][t] = 0.0f;

    load_stage(0, 0);
    load_stage(1, 1);

    const int lr = lane & 15;
    const int lc = lane >> 4;

    for (int kc = 0; kc < NKC; kc++) {
        if (kc < NKC - 1) cp_wait<1>(); else cp_wait<0>();
        __syncthreads();

        const uint32_t sb = base + (kc % 3) * HSTAGE;
        const uint32_t aHib = sb;
        const uint32_t aLob = sb + HT_BYTES;
        const uint32_t bHib = sb + 2 * HT_BYTES;

#pragma unroll
        for (int ks = 0; ks < 2; ks++) {
            const int chnk = ks * 2 + lc;
            uint32_t ah[2][4], al[2][4], bh[4][4];
#pragma unroll
            for (int mi = 0; mi < 2; mi++) {
                uint32_t off = sw_off(wm + mi * 16 + lr, chnk);
                ldsm4(ah[mi][0], ah[mi][1], ah[mi][2], ah[mi][3], aHib + off);
                ldsm4(al[mi][0], al[mi][1], al[mi][2], al[mi][3], aLob + off);
            }
#pragma unroll
            for (int g = 0; g < 4; g++) {
                uint32_t off = sw_off(wn + g * 16 + lr, chnk);
                ldsm4(bh[g][0], bh[g][1], bh[g][2], bh[g][3], bHib + off);
            }
#pragma unroll
            for (int mi = 0; mi < 2; mi++)
#pragma unroll
                for (int ni = 0; ni < 8; ni++) {
                    const int g = ni >> 1, w = ni & 1;
                    mma16816(acc[mi][ni], ah[mi], bh[g][w], bh[g][w + 2]);
                    mma16816(acc[mi][ni], al[mi], bh[g][w], bh[g][w + 2]);
                }
        }
        if (kc + 2 < NKC) load_stage((kc + 2) % 3, kc + 2);
    }

#pragma unroll
    for (int mi = 0; mi < 2; mi++) {
        const int r0 = bm + wm + mi * 16 + (lane >> 2);
#pragma unroll
        for (int ni = 0; ni < 8; ni++) {
            const int c = bn + wn + ni * 8 + (lane & 3) * 2;
            const float b0 = bias[c], b1 = bias[c + 1];
            float2 v0 = make_float2(acc[mi][ni][0] + b0, acc[mi][ni][1] + b1);
            float2 v1 = make_float2(acc[mi][ni][2] + b0, acc[mi][ni][3] + b1);
            *(float2*)(Out + (size_t)r0 * CH + c)       = v0;
            *(float2*)(Out + (size_t)(r0 + 8) * CH + c) = v1;
        }
    }
}

__global__ __launch_bounds__(256, 2) void gemm_qkv(
    const __half* __restrict__ Ahi, const __half* __restrict__ Alo,
    const __half* __restrict__ Wall,
    const float* __restrict__ bq, const float* __restrict__ bk,
    const float* __restrict__ bv,
    float* __restrict__ Qo, float* __restrict__ Ko, float* __restrict__ Vo)
{
    extern __shared__ char dsm[];
    const int bng = blockIdx.x * 128;
    const int sel = bng >> 10;
    const int bn  = bng & 1023;
    const int bm  = blockIdx.y * 128;
    const float* bias = (sel == 0) ? bq : (sel == 1) ? bk : bv;
    float* Out = (sel == 0) ? Qo : (sel == 1) ? Ko : Vo;
    const __half* Bh = Wall + (size_t)sel * CH * CH + (size_t)bn * CH;
    gemm_body(Ahi + (size_t)bm * CH, Alo + (size_t)bm * CH, Bh, bias, Out, bm, bn, dsm);
}

__global__ __launch_bounds__(256, 2) void gemm_hmma(
    const __half* __restrict__ Ahi, const __half* __restrict__ Alo,
    const __half* __restrict__ Bh,
    const float* __restrict__ bias, float* __restrict__ Out)
{
    extern __shared__ char dsm[];
    const int bm = blockIdx.y * 128;
    const int bn = blockIdx.x * 128;
    gemm_body(Ahi + (size_t)bm * CH, Alo + (size_t)bm * CH,
              Bh + (size_t)bn * CH, bias, Out, bm, bn, dsm);
}

// ---------------- attention: 128-col window (blocks n-1, n only) -----------
#define QT_STRIDE 68
#define KT_STRIDE 132
#define VS_STRIDE 68
#define PS_STRIDE 132
#define WIN 128
#define QT_OFF 0
#define KV_OFF (64 * QT_STRIDE)
#define KV_FLOATS 8704
#define PS_OFF (KV_OFF + KV_FLOATS)
#define SMEM_FLOATS (PS_OFF + (64 * PS_STRIDE) / 2)
#define ATTN_SMEM_BYTES (SMEM_FLOATS * 4)         // 69120

__global__ __launch_bounds__(256, 3) void attn_kernel(
    const float* __restrict__ Q, const float* __restrict__ K,
    const float* __restrict__ V,
    __half* __restrict__ Ohi, __half* __restrict__ Olo)
{
    extern __shared__ float sm[];
    float*  qT  = sm + QT_OFF;
    float*  kT  = sm + KV_OFF;
    float*  vs  = sm + KV_OFF;
    __half* Ps  = (__half*)(sm + PS_OFF);

    const int tid  = threadIdx.x;
    const int warp = tid >> 5;
    const int lane = tid & 31;
    const int n = blockIdx.x;
    const int h = blockIdx.y;
    const int b = blockIdx.z;
    const size_t base = (size_t)b * SEQ * CH + (size_t)h * HD;

#pragma unroll
    for (int p = 0; p < 4; p++) {
        int idx = tid + p * 256;
        int i   = idx >> 4;
        int dd0 = (idx & 15) << 2;
        float4 v4 = *(const float4*)(Q + base + (size_t)(n * BS + i) * CH + dd0);
        qT[(dd0 + 0) * QT_STRIDE + i] = v4.x;
        qT[(dd0 + 1) * QT_STRIDE + i] = v4.y;
        qT[(dd0 + 2) * QT_STRIDE + i] = v4.z;
        qT[(dd0 + 3) * QT_STRIDE + i] = v4.w;
    }
#pragma unroll
    for (int p = 0; p < 8; p++) {
        int idx = tid + p * 256;
        int j   = idx >> 4;
        int dd0 = (idx & 15) << 2;
        int kpos = (n - 1) * BS + j;
        float4 v4 = make_float4(0.f, 0.f, 0.f, 0.f);
        if (kpos >= 0)
            v4 = *(const float4*)(K + base + (size_t)kpos * CH + dd0);
        kT[(dd0 + 0) * KT_STRIDE + j] = v4.x;
        kT[(dd0 + 1) * KT_STRIDE + j] = v4.y;
        kT[(dd0 + 2) * KT_STRIDE + j] = v4.z;
        kT[(dd0 + 3) * KT_STRIDE + j] = v4.w;
    }
    __syncthreads();

    // ---- score: warp owns 8 rows (i0=warp*8), lane owns 4 cols (j0=lane*4)
    const int i0 = warp << 3;
    const int j0 = lane << 2;
    float acc[8][4];
#pragma unroll
    for (int ii = 0; ii < 8; ii++)
#pragma unroll
        for (int jj = 0; jj < 4; jj++) acc[ii][jj] = 0.0f;

#pragma unroll 4
    for (int dd = 0; dd < 64; dd++) {
        float4 a0 = *(const float4*)&qT[dd * QT_STRIDE + i0];      // broadcast
        float4 a1 = *(const float4*)&qT[dd * QT_STRIDE + i0 + 4];  // broadcast
        float4 b4 = *(const float4*)&kT[dd * KT_STRIDE + j0];
        float a[8] = {a0.x, a0.y, a0.z, a0.w, a1.x, a1.y, a1.z, a1.w};
        float bb[4] = {b4.x, b4.y, b4.z, b4.w};
#pragma unroll
        for (int ii = 0; ii < 8; ii++)
#pragma unroll
            for (int jj = 0; jj < 4; jj++)
                acc[ii][jj] += a[ii] * bb[jj];
    }

    const float scale = 0.125f;
    float mrow[8];
#pragma unroll
    for (int ii = 0; ii < 8; ii++) {
        const int i = i0 + ii;
        mrow[ii] = -1e30f;
#pragma unroll
        for (int jj = 0; jj < 4; jj++) {
            const int j = j0 + jj;
            bool valid = (j <= i + BS) && (n > 0 || j >= BS);
            acc[ii][jj] = valid ? acc[ii][jj] * scale : -1e30f;
            mrow[ii] = fmaxf(mrow[ii], acc[ii][jj]);
        }
    }
#pragma unroll
    for (int ii = 0; ii < 8; ii++) {
        mrow[ii] = fmaxf(mrow[ii], __shfl_xor_sync(0xffffffffu, mrow[ii], 1));
        mrow[ii] = fmaxf(mrow[ii], __shfl_xor_sync(0xffffffffu, mrow[ii], 2));
        mrow[ii] = fmaxf(mrow[ii], __shfl_xor_sync(0xffffffffu, mrow[ii], 4));
        mrow[ii] = fmaxf(mrow[ii], __shfl_xor_sync(0xffffffffu, mrow[ii], 8));
        mrow[ii] = fmaxf(mrow[ii], __shfl_xor_sync(0xffffffffu, mrow[ii], 16));
    }
    float srow[8];
#pragma unroll
    for (int ii = 0; ii < 8; ii++) {
        srow[ii] = 0.f;
#pragma unroll
        for (int jj = 0; jj < 4; jj++) {
            acc[ii][jj] = __expf(acc[ii][jj] - mrow[ii]);
            srow[ii] += acc[ii][jj];
        }
    }
#pragma unroll
    for (int ii = 0; ii < 8; ii++) {
        srow[ii] += __shfl_xor_sync(0xffffffffu, srow[ii], 1);
        srow[ii] += __shfl_xor_sync(0xffffffffu, srow[ii], 2);
        srow[ii] += __shfl_xor_sync(0xffffffffu, srow[ii], 4);
        srow[ii] += __shfl_xor_sync(0xffffffffu, srow[ii], 8);
        srow[ii] += __shfl_xor_sync(0xffffffffu, srow[ii], 16);
        const float inv = 1.0f / srow[ii];
        __half2 p01, p23;
        p01.x = __float2half(acc[ii][0] * inv);
        p01.y = __float2half(acc[ii][1] * inv);
        p23.x = __float2half(acc[ii][2] * inv);
        p23.y = __float2half(acc[ii][3] * inv);
        __half* prow = Ps + (i0 + ii) * PS_STRIDE + j0;
        *(__half2*)(prow)     = p01;
        *(__half2*)(prow + 2) = p23;
    }
    __syncthreads();

    // v window over kT region
#pragma unroll
    for (int p = 0; p < 8; p++) {
        int idx = tid + p * 256;
        int j   = idx >> 4;
        int dd0 = (idx & 15) << 2;
        int kpos = (n - 1) * BS + j;
        float4 v4 = make_float4(0.f, 0.f, 0.f, 0.f);
        if (kpos >= 0)
            v4 = *(const float4*)(V + base + (size_t)kpos * CH + dd0);
        *(float4*)&vs[j * VS_STRIDE + dd0] = v4;
    }
    __syncthreads();

    // ---- PV: 4 rows per 16-thread group, j in pairs with half2 P reads
    const int i0p = (tid >> 4) << 2;
    const int c0  = (tid & 15) << 2;
    float o[4][4];
#pragma unroll
    for (int ii = 0; ii < 4; ii++)
#pragma unroll
        for (int cc = 0; cc < 4; cc++) o[ii][cc] = 0.0f;

    const int jlim = (i0p + 68 < WIN) ? (i0p + 68) : WIN;   // even
#pragma unroll 2
    for (int j = 0; j < jlim; j += 2) {
        float4 va = *(const float4*)&vs[j * VS_STRIDE + c0];
        float4 vb = *(const float4*)&vs[(j + 1) * VS_STRIDE + c0];
#pragma unroll
        for (int ii = 0; ii < 4; ii++) {
            float2 pf = __half22float2(*(const __half2*)&Ps[(i0p + ii) * PS_STRIDE + j]);
            o[ii][0] += pf.x * va.x + pf.y * vb.x;
            o[ii][1] += pf.x * va.y + pf.y * vb.y;
            o[ii][2] += pf.x * va.z + pf.y * vb.z;
            o[ii][3] += pf.x * va.w + pf.y * vb.w;
        }
    }
#pragma unroll
    for (int ii = 0; ii < 4; ii++) {
        const size_t oidx = base + (size_t)(n * BS + i0p + ii) * CH + c0;
        __half h0 = __float2half(o[ii][0]);
        __half h1 = __float2half(o[ii][1]);
        __half h2 = __float2half(o[ii][2]);
        __half h3 = __float2half(o[ii][3]);
        __half2 hp0; hp0.x = h0; hp0.y = h1;
        __half2 hp1; hp1.x = h2; hp1.y = h3;
        __half2 lp0, lp1;
        lp0.x = __float2half(o[ii][0] - __half2float(h0));
        lp0.y = __float2half(o[ii][1] - __half2float(h1));
        lp1.x = __float2half(o[ii][2] - __half2float(h2));
        lp1.y = __float2half(o[ii][3] - __half2float(h3));
        *(__half2*)(Ohi + oidx)     = hp0;
        *(__half2*)(Ohi + oidx + 2) = hp1;
        *(__half2*)(Olo + oidx)     = lp0;
        *(__half2*)(Olo + oidx + 2) = lp1;
    }
}

// ---------------------------------------------------------------------------
extern "C" void kernel_launch(void* const* d_in, const int* in_sizes, int n_in,
                              void* d_out, int out_size)
{
    const float* x  = (const float*)d_in[0];
    const float* Wq = (const float*)d_in[1];
    const float* bq = (const float*)d_in[2];
    const float* Wk = (const float*)d_in[3];
    const float* bk = (const float*)d_in[4];
    const float* Wv = (const float*)d_in[5];
    const float* bv = (const float*)d_in[6];
    const float* Wo = (const float*)d_in[7];
    const float* bo = (const float*)d_in[8];
    float* out = (float*)d_out;

    float *qp, *kp, *vp;
    __half *ahi, *alo, *phi, *plo, *whi;
    cudaGetSymbolAddress((void**)&qp,  g_Q);
    cudaGetSymbolAddress((void**)&kp,  g_K);
    cudaGetSymbolAddress((void**)&vp,  g_V);
    cudaGetSymbolAddress((void**)&ahi, g_Ahi);
    cudaGetSymbolAddress((void**)&alo, g_Alo);
    cudaGetSymbolAddress((void**)&phi, g_Phi);
    cudaGetSymbolAddress((void**)&plo, g_Plo);
    cudaGetSymbolAddress((void**)&whi, g_Whi);

    cudaFuncSetAttribute(attn_kernel,
                         cudaFuncAttributeMaxDynamicSharedMemorySize, ATTN_SMEM_BYTES);
    cudaFuncSetAttribute(gemm_hmma,
                         cudaFuncAttributeMaxDynamicSharedMemorySize, HGEMM_SMEM);
    cudaFuncSetAttribute(gemm_qkv,
                         cudaFuncAttributeMaxDynamicSharedMemorySize, HGEMM_SMEM);

    const int NX = MROWS * CH;
    const int NW = CH * CH;

    split_f16<<<NX / 1024, 256>>>(x, ahi, alo, NX);
    to_f16_w4<<<4096, 256>>>(Wq, Wk, Wv, Wo, whi);

    gemm_qkv<<<dim3(24, MROWS / 128), 256, HGEMM_SMEM>>>(
        ahi, alo, whi, bq, bk, bv, qp, kp, vp);

    attn_kernel<<<dim3(NB, NH, BATCH), 256, ATTN_SMEM_BYTES>>>(qp, kp, vp, phi, plo);

    gemm_hmma<<<dim3(8, MROWS / 128), 256, HGEMM_SMEM>>>(
        phi, plo, whi + 3 * (size_t)NW, bo, out);
}

// round 11
// speedup vs baseline: 1.0531x; 1.0050x over previous
#include <cuda_runtime.h>
#include <cuda_fp16.h>
#include <cstdint>

#define BATCH 4
#define SEQ   4096
#define CH    1024
#define NH    16
#define HD    64
#define BS    64
#define NB    (SEQ / BS)          // 64
#define MROWS (BATCH * SEQ)       // 16384

// ---------------- scratch (device globals: allocation-free) ----------------
__device__ float g_Q[(size_t)MROWS * CH];
__device__ float g_K[(size_t)MROWS * CH];
__device__ float g_V[(size_t)MROWS * CH];
__device__ __half g_Ahi[(size_t)MROWS * CH];
__device__ __half g_Alo[(size_t)MROWS * CH];
__device__ __half g_Phi[(size_t)MROWS * CH];
__device__ __half g_Plo[(size_t)MROWS * CH];
__device__ __half g_Whi[(size_t)4 * CH * CH];

// =================== helpers ===================
__device__ __forceinline__ uint32_t smem_u32(const void* p) {
    uint32_t a;
    asm("{ .reg .u64 t; cvta.to.shared.u64 t, %1; cvt.u32.u64 %0, t; }"
        : "=r"(a) : "l"(p));
    return a;
}
__device__ __forceinline__ void cp16(uint32_t dst, const void* src) {
    asm volatile("cp.async.cg.shared.global [%0], [%1], 16;" :: "r"(dst), "l"(src));
}
__device__ __forceinline__ void cp_commit() {
    asm volatile("cp.async.commit_group;" ::: "memory");
}
template <int N>
__device__ __forceinline__ void cp_wait() {
    asm volatile("cp.async.wait_group %0;" :: "n"(N) : "memory");
}
__device__ __forceinline__ void ldsm4(uint32_t& r0, uint32_t& r1, uint32_t& r2,
                                      uint32_t& r3, uint32_t addr) {
    asm volatile("ldmatrix.sync.aligned.m8n8.x4.shared.b16 {%0,%1,%2,%3}, [%4];"
                 : "=r"(r0), "=r"(r1), "=r"(r2), "=r"(r3) : "r"(addr));
}
__device__ __forceinline__ void mma16816(float* c, const uint32_t* a,
                                         uint32_t b0, uint32_t b1) {
    asm volatile(
        "mma.sync.aligned.m16n8k16.row.col.f32.f16.f16.f32 "
        "{%0,%1,%2,%3}, {%4,%5,%6,%7}, {%8,%9}, {%0,%1,%2,%3};"
        : "+f"(c[0]), "+f"(c[1]), "+f"(c[2]), "+f"(c[3])
        : "r"(a[0]), "r"(a[1]), "r"(a[2]), "r"(a[3]), "r"(b0), "r"(b1));
}
// ---- packed f32x2 (FFMA2) helpers ----
__device__ __forceinline__ unsigned long long pack2(float x, float y) {
    unsigned long long r;
    asm("mov.b64 %0, {%1, %2};" : "=l"(r) : "f"(x), "f"(y));
    return r;
}
__device__ __forceinline__ void unpack2(unsigned long long v, float& x, float& y) {
    asm("mov.b64 {%0, %1}, %2;" : "=f"(x), "=f"(y) : "l"(v));
}
__device__ __forceinline__ void fma2(unsigned long long& d, unsigned long long a,
                                     unsigned long long b) {
    asm("fma.rn.f32x2 %0, %1, %2, %0;" : "+l"(d) : "l"(a), "l"(b));
}

// =================== fp32 -> fp16 hi/lo splitter ===================
__global__ __launch_bounds__(256) void split_f16(
    const float* __restrict__ in, __half* __restrict__ hi,
    __half* __restrict__ lo, int n)
{
    int i = (blockIdx.x * 256 + threadIdx.x) * 4;
    if (i >= n) return;
    float4 v = *(const float4*)(in + i);
    __half h0 = __float2half(v.x);
    __half h1 = __float2half(v.y);
    __half h2 = __float2half(v.z);
    __half h3 = __float2half(v.w);
    __half2 hp0; hp0.x = h0; hp0.y = h1;
    __half2 hp1; hp1.x = h2; hp1.y = h3;
    __half2 lp0; lp0.x = __float2half(v.x - __half2float(h0));
    lp0.y = __float2half(v.y - __half2float(h1));
    __half2 lp1; lp1.x = __float2half(v.z - __half2float(h2));
    lp1.y = __float2half(v.w - __half2float(h3));
    *(__half2*)(hi + i)     = hp0;
    *(__half2*)(hi + i + 2) = hp1;
    *(__half2*)(lo + i)     = lp0;
    *(__half2*)(lo + i + 2) = lp1;
}
__global__ __launch_bounds__(256) void to_f16_w4(
    const float* __restrict__ w0, const float* __restrict__ w1,
    const float* __restrict__ w2, const float* __restrict__ w3,
    __half* __restrict__ hi)
{
    const int seg = blockIdx.x >> 10;
    const int loc = (int)(blockIdx.x & 1023) * 1024 + threadIdx.x * 4;
    const float* in = (seg == 0) ? w0 : (seg == 1) ? w1 : (seg == 2) ? w2 : w3;
    float4 v = *(const float4*)(in + loc);
    __half2 hp0; hp0.x = __float2half(v.x); hp0.y = __float2half(v.y);
    __half2 hp1; hp1.x = __float2half(v.z); hp1.y = __float2half(v.w);
    __half* out = hi + (size_t)seg * CH * CH + loc;
    *(__half2*)(out)     = hp0;
    *(__half2*)(out + 2) = hp1;
}

// =================== HMMA GEMM core (BM=BN=128, BK=32, 8 warps) =============
#define BKH 32
#define NKC (CH / BKH)            // 32
#define HT_BYTES 8192
#define HSTAGE (3 * HT_BYTES)
#define HGEMM_SMEM (3 * HSTAGE)   // 73728

__device__ __forceinline__ uint32_t sw_off(int row, int chunk) {
    return (uint32_t)(row * 64 + ((chunk ^ ((row >> 1) & 3)) << 4));
}

__device__ __forceinline__ void gemm_body(
    const __half* __restrict__ Ahi_t, const __half* __restrict__ Alo_t,
    const __half* __restrict__ Bh_t,
    const float* __restrict__ bias, float* __restrict__ Out,
    int bm, int bn, char* dsm)
{
    const uint32_t base = smem_u32(dsm);
    const int tid  = threadIdx.x;
    const int wid  = tid >> 5;
    const int lane = tid & 31;
    const int wm = (wid & 3) * 32;
    const int wn = (wid >> 2) * 64;

    const __half* srcs[3] = { Ahi_t, Alo_t, Bh_t };

    auto load_stage = [&](int st, int kc) {
        const uint32_t sb = base + st * HSTAGE;
#pragma unroll
        for (int p = 0; p < 6; p++) {
            int idx = p * 256 + tid;
            int buf = idx >> 9;
            int rem = idx & 511;
            int row = rem >> 2;
            int ch  = rem & 3;
            const __half* s = srcs[buf] + (size_t)row * CH + kc * BKH + ch * 8;
            cp16(sb + buf * HT_BYTES + sw_off(row, ch), s);
        }
        cp_commit();
    };

    float acc[2][8][4];
#pragma unroll
    for (int mi = 0; mi < 2; mi++)
#pragma unroll
        for (int ni = 0; ni < 8; ni++)
#pragma unroll
            for (int t = 0; t < 4; t++) acc[mi][ni][t] = 0.0f;

    load_stage(0, 0);
    load_stage(1, 1);

    const int lr = lane & 15;
    const int lc = lane >> 4;

    for (int kc = 0; kc < NKC; kc++) {
        if (kc < NKC - 1) cp_wait<1>(); else cp_wait<0>();
        __syncthreads();

        const uint32_t sb = base + (kc % 3) * HSTAGE;
        const uint32_t aHib = sb;
        const uint32_t aLob = sb + HT_BYTES;
        const uint32_t bHib = sb + 2 * HT_BYTES;

#pragma unroll
        for (int ks = 0; ks < 2; ks++) {
            const int chnk = ks * 2 + lc;
            uint32_t ah[2][4], al[2][4], bh[4][4];
#pragma unroll
            for (int mi = 0; mi < 2; mi++) {
                uint32_t off = sw_off(wm + mi * 16 + lr, chnk);
                ldsm4(ah[mi][0], ah[mi][1], ah[mi][2], ah[mi][3], aHib + off);
                ldsm4(al[mi][0], al[mi][1], al[mi][2], al[mi][3], aLob + off);
            }
#pragma unroll
            for (int g = 0; g < 4; g++) {
                uint32_t off = sw_off(wn + g * 16 + lr, chnk);
                ldsm4(bh[g][0], bh[g][1], bh[g][2], bh[g][3], bHib + off);
            }
#pragma unroll
            for (int mi = 0; mi < 2; mi++)
#pragma unroll
                for (int ni = 0; ni < 8; ni++) {
                    const int g = ni >> 1, w = ni & 1;
                    mma16816(acc[mi][ni], ah[mi], bh[g][w], bh[g][w + 2]);
                    mma16816(acc[mi][ni], al[mi], bh[g][w], bh[g][w + 2]);
                }
        }
        if (kc + 2 < NKC) load_stage((kc + 2) % 3, kc + 2);
    }

#pragma unroll
    for (int mi = 0; mi < 2; mi++) {
        const int r0 = bm + wm + mi * 16 + (lane >> 2);
#pragma unroll
        for (int ni = 0; ni < 8; ni++) {
            const int c = bn + wn + ni * 8 + (lane & 3) * 2;
            const float b0 = bias[c], b1 = bias[c + 1];
            float2 v0 = make_float2(acc[mi][ni][0] + b0, acc[mi][ni][1] + b1);
            float2 v1 = make_float2(acc[mi][ni][2] + b0, acc[mi][ni][3] + b1);
            *(float2*)(Out + (size_t)r0 * CH + c)       = v0;
            *(float2*)(Out + (size_t)(r0 + 8) * CH + c) = v1;
        }
    }
}

__global__ __launch_bounds__(256, 2) void gemm_qkv(
    const __half* __restrict__ Ahi, const __half* __restrict__ Alo,
    const __half* __restrict__ Wall,
    const float* __restrict__ bq, const float* __restrict__ bk,
    const float* __restrict__ bv,
    float* __restrict__ Qo, float* __restrict__ Ko, float* __restrict__ Vo)
{
    extern __shared__ char dsm[];
    const int bng = blockIdx.x * 128;
    const int sel = bng >> 10;
    const int bn  = bng & 1023;
    const int bm  = blockIdx.y * 128;
    const float* bias = (sel == 0) ? bq : (sel == 1) ? bk : bv;
    float* Out = (sel == 0) ? Qo : (sel == 1) ? Ko : Vo;
    const __half* Bh = Wall + (size_t)sel * CH * CH + (size_t)bn * CH;
    gemm_body(Ahi + (size_t)bm * CH, Alo + (size_t)bm * CH, Bh, bias, Out, bm, bn, dsm);
}

__global__ __launch_bounds__(256, 2) void gemm_hmma(
    const __half* __restrict__ Ahi, const __half* __restrict__ Alo,
    const __half* __restrict__ Bh,
    const float* __restrict__ bias, float* __restrict__ Out)
{
    extern __shared__ char dsm[];
    const int bm = blockIdx.y * 128;
    const int bn = blockIdx.x * 128;
    gemm_body(Ahi + (size_t)bm * CH, Alo + (size_t)bm * CH,
              Bh + (size_t)bn * CH, bias, Out, bm, bn, dsm);
}

// ---------------- attention: 128-col window (blocks n-1, n only) -----------
#define QT_STRIDE 68
#define KT_STRIDE 132
#define VS_STRIDE 68
#define PS_STRIDE 132
#define WIN 128
#define QT_OFF 0
#define KV_OFF (64 * QT_STRIDE)
#define KV_FLOATS 8704
#define PS_OFF (KV_OFF + KV_FLOATS)
#define SMEM_FLOATS (PS_OFF + (64 * PS_STRIDE) / 2)
#define ATTN_SMEM_BYTES (SMEM_FLOATS * 4)         // 69120

__global__ __launch_bounds__(256, 3) void attn_kernel(
    const float* __restrict__ Q, const float* __restrict__ K,
    const float* __restrict__ V,
    __half* __restrict__ Ohi, __half* __restrict__ Olo)
{
    extern __shared__ float sm[];
    float*  qT  = sm + QT_OFF;
    float*  kT  = sm + KV_OFF;
    float*  vs  = sm + KV_OFF;
    __half* Ps  = (__half*)(sm + PS_OFF);

    const int tid  = threadIdx.x;
    const int warp = tid >> 5;
    const int lane = tid & 31;
    const int n = blockIdx.x;
    const int h = blockIdx.y;
    const int b = blockIdx.z;
    const size_t base = (size_t)b * SEQ * CH + (size_t)h * HD;

#pragma unroll
    for (int p = 0; p < 4; p++) {
        int idx = tid + p * 256;
        int i   = idx >> 4;
        int dd0 = (idx & 15) << 2;
        float4 v4 = *(const float4*)(Q + base + (size_t)(n * BS + i) * CH + dd0);
        qT[(dd0 + 0) * QT_STRIDE + i] = v4.x;
        qT[(dd0 + 1) * QT_STRIDE + i] = v4.y;
        qT[(dd0 + 2) * QT_STRIDE + i] = v4.z;
        qT[(dd0 + 3) * QT_STRIDE + i] = v4.w;
    }
#pragma unroll
    for (int p = 0; p < 8; p++) {
        int idx = tid + p * 256;
        int j   = idx >> 4;
        int dd0 = (idx & 15) << 2;
        int kpos = (n - 1) * BS + j;
        float4 v4 = make_float4(0.f, 0.f, 0.f, 0.f);
        if (kpos >= 0)
            v4 = *(const float4*)(K + base + (size_t)kpos * CH + dd0);
        kT[(dd0 + 0) * KT_STRIDE + j] = v4.x;
        kT[(dd0 + 1) * KT_STRIDE + j] = v4.y;
        kT[(dd0 + 2) * KT_STRIDE + j] = v4.z;
        kT[(dd0 + 3) * KT_STRIDE + j] = v4.w;
    }
    __syncthreads();

    // ---- score: warp owns 8 rows (i0=warp*8), lane owns 4 cols (j0=lane*4)
    // packed f32x2 accumulators along ROW pairs: acc2[p][jj] = rows {2p,2p+1}
    const int i0 = warp << 3;
    const int j0 = lane << 2;
    unsigned long long acc2[4][4];
#pragma unroll
    for (int p = 0; p < 4; p++)
#pragma unroll
        for (int jj = 0; jj < 4; jj++) acc2[p][jj] = 0ull;

#pragma unroll 4
    for (int dd = 0; dd < 64; dd++) {
        // q row-pairs load naturally packed (16B aligned)
        ulonglong2 a01 = *(const ulonglong2*)&qT[dd * QT_STRIDE + i0];      // rows 0-3
        ulonglong2 a23 = *(const ulonglong2*)&qT[dd * QT_STRIDE + i0 + 4];  // rows 4-7
        float4 b4 = *(const float4*)&kT[dd * KT_STRIDE + j0];
        unsigned long long ap[4] = {a01.x, a01.y, a23.x, a23.y};
        unsigned long long bb[4] = {pack2(b4.x, b4.x), pack2(b4.y, b4.y),
                                    pack2(b4.z, b4.z), pack2(b4.w, b4.w)};
#pragma unroll
        for (int p = 0; p < 4; p++)
#pragma unroll
            for (int jj = 0; jj < 4; jj++)
                fma2(acc2[p][jj], ap[p], bb[jj]);
    }

    // unpack to scalars for mask/softmax
    float acc[8][4];
#pragma unroll
    for (int p = 0; p < 4; p++)
#pragma unroll
        for (int jj = 0; jj < 4; jj++)
            unpack2(acc2[p][jj], acc[2 * p][jj], acc[2 * p + 1][jj]);

    const float scale = 0.125f;
    float mrow[8];
#pragma unroll
    for (int ii = 0; ii < 8; ii++) {
        const int i = i0 + ii;
        mrow[ii] = -1e30f;
#pragma unroll
        for (int jj = 0; jj < 4; jj++) {
            const int j = j0 + jj;
            bool valid = (j <= i + BS) && (n > 0 || j >= BS);
            acc[ii][jj] = valid ? acc[ii][jj] * scale : -1e30f;
            mrow[ii] = fmaxf(mrow[ii], acc[ii][jj]);
        }
    }
#pragma unroll
    for (int ii = 0; ii < 8; ii++) {
        mrow[ii] = fmaxf(mrow[ii], __shfl_xor_sync(0xffffffffu, mrow[ii], 1));
        mrow[ii] = fmaxf(mrow[ii], __shfl_xor_sync(0xffffffffu, mrow[ii], 2));
        mrow[ii] = fmaxf(mrow[ii], __shfl_xor_sync(0xffffffffu, mrow[ii], 4));
        mrow[ii] = fmaxf(mrow[ii], __shfl_xor_sync(0xffffffffu, mrow[ii], 8));
        mrow[ii] = fmaxf(mrow[ii], __shfl_xor_sync(0xffffffffu, mrow[ii], 16));
    }
    float srow[8];
#pragma unroll
    for (int ii = 0; ii < 8; ii++) {
        srow[ii] = 0.f;
#pragma unroll
        for (int jj = 0; jj < 4; jj++) {
            acc[ii][jj] = __expf(acc[ii][jj] - mrow[ii]);
            srow[ii] += acc[ii][jj];
        }
    }
#pragma unroll
    for (int ii = 0; ii < 8; ii++) {
        srow[ii] += __shfl_xor_sync(0xffffffffu, srow[ii], 1);
        srow[ii] += __shfl_xor_sync(0xffffffffu, srow[ii], 2);
        srow[ii] += __shfl_xor_sync(0xffffffffu, srow[ii], 4);
        srow[ii] += __shfl_xor_sync(0xffffffffu, srow[ii], 8);
        srow[ii] += __shfl_xor_sync(0xffffffffu, srow[ii], 16);
        const float inv = 1.0f / srow[ii];
        __half2 p01, p23;
        p01.x = __float2half(acc[ii][0] * inv);
        p01.y = __float2half(acc[ii][1] * inv);
        p23.x = __float2half(acc[ii][2] * inv);
        p23.y = __float2half(acc[ii][3] * inv);
        __half* prow = Ps + (i0 + ii) * PS_STRIDE + j0;
        *(__half2*)(prow)     = p01;
        *(__half2*)(prow + 2) = p23;
    }
    __syncthreads();

    // v window over kT region
#pragma unroll
    for (int p = 0; p < 8; p++) {
        int idx = tid + p * 256;
        int j   = idx >> 4;
        int dd0 = (idx & 15) << 2;
        int kpos = (n - 1) * BS + j;
        float4 v4 = make_float4(0.f, 0.f, 0.f, 0.f);
        if (kpos >= 0)
            v4 = *(const float4*)(V + base + (size_t)kpos * CH + dd0);
        *(float4*)&vs[j * VS_STRIDE + dd0] = v4;
    }
    __syncthreads();

    // ---- PV: 4 rows per 16-thread group; packed f32x2 along col pairs
    const int i0p = (tid >> 4) << 2;
    const int c0  = (tid & 15) << 2;
    unsigned long long o2[4][2];
#pragma unroll
    for (int ii = 0; ii < 4; ii++) { o2[ii][0] = 0ull; o2[ii][1] = 0ull; }

    const int jlim = (i0p + 68 < WIN) ? (i0p + 68) : WIN;   // even
#pragma unroll 2
    for (int j = 0; j < jlim; j += 2) {
        ulonglong2 va = *(const ulonglong2*)&vs[j * VS_STRIDE + c0];
        ulonglong2 vb = *(const ulonglong2*)&vs[(j + 1) * VS_STRIDE + c0];
#pragma unroll
        for (int ii = 0; ii < 4; ii++) {
            float2 pf = __half22float2(*(const __half2*)&Ps[(i0p + ii) * PS_STRIDE + j]);
            unsigned long long px = pack2(pf.x, pf.x);
            unsigned long long py = pack2(pf.y, pf.y);
            fma2(o2[ii][0], px, va.x);
            fma2(o2[ii][1], px, va.y);
            fma2(o2[ii][0], py, vb.x);
            fma2(o2[ii][1], py, vb.y);
        }
    }
#pragma unroll
    for (int ii = 0; ii < 4; ii++) {
        float o0, o1, o2f, o3;
        unpack2(o2[ii][0], o0, o1);
        unpack2(o2[ii][1], o2f, o3);
        const size_t oidx = base + (size_t)(n * BS + i0p + ii) * CH + c0;
        __half h0 = __float2half(o0);
        __half h1 = __float2half(o1);
        __half h2 = __float2half(o2f);
        __half h3 = __float2half(o3);
        __half2 hp0; hp0.x = h0; hp0.y = h1;
        __half2 hp1; hp1.x = h2; hp1.y = h3;
        __half2 lp0, lp1;
        lp0.x = __float2half(o0 - __half2float(h0));
        lp0.y = __float2half(o1 - __half2float(h1));
        lp1.x = __float2half(o2f - __half2float(h2));
        lp1.y = __float2half(o3 - __half2float(h3));
        *(__half2*)(Ohi + oidx)     = hp0;
        *(__half2*)(Ohi + oidx + 2) = hp1;
        *(__half2*)(Olo + oidx)     = lp0;
        *(__half2*)(Olo + oidx + 2) = lp1;
    }
}

// ---------------------------------------------------------------------------
extern "C" void kernel_launch(void* const* d_in, const int* in_sizes, int n_in,
                              void* d_out, int out_size)
{
    const float* x  = (const float*)d_in[0];
    const float* Wq = (const float*)d_in[1];
    const float* bq = (const float*)d_in[2];
    const float* Wk = (const float*)d_in[3];
    const float* bk = (const float*)d_in[4];
    const float* Wv = (const float*)d_in[5];
    const float* bv = (const float*)d_in[6];
    const float* Wo = (const float*)d_in[7];
    const float* bo = (const float*)d_in[8];
    float* out = (float*)d_out;

    float *qp, *kp, *vp;
    __half *ahi, *alo, *phi, *plo, *whi;
    cudaGetSymbolAddress((void**)&qp,  g_Q);
    cudaGetSymbolAddress((void**)&kp,  g_K);
    cudaGetSymbolAddress((void**)&vp,  g_V);
    cudaGetSymbolAddress((void**)&ahi, g_Ahi);
    cudaGetSymbolAddress((void**)&alo, g_Alo);
    cudaGetSymbolAddress((void**)&phi, g_Phi);
    cudaGetSymbolAddress((void**)&plo, g_Plo);
    cudaGetSymbolAddress((void**)&whi, g_Whi);

    cudaFuncSetAttribute(attn_kernel,
                         cudaFuncAttributeMaxDynamicSharedMemorySize, ATTN_SMEM_BYTES);
    cudaFuncSetAttribute(gemm_hmma,
                         cudaFuncAttributeMaxDynamicSharedMemorySize, HGEMM_SMEM);
    cudaFuncSetAttribute(gemm_qkv,
                         cudaFuncAttributeMaxDynamicSharedMemorySize, HGEMM_SMEM);

    const int NX = MROWS * CH;
    const int NW = CH * CH;

    split_f16<<<NX / 1024, 256>>>(x, ahi, alo, NX);
    to_f16_w4<<<4096, 256>>>(Wq, Wk, Wv, Wo, whi);

    gemm_qkv<<<dim3(24, MROWS / 128), 256, HGEMM_SMEM>>>(
        ahi, alo, whi, bq, bk, bv, qp, kp, vp);

    attn_kernel<<<dim3(NB, NH, BATCH), 256, ATTN_SMEM_BYTES>>>(qp, kp, vp, phi, plo);

    gemm_hmma<<<dim3(8, MROWS / 128), 256, HGEMM_SMEM>>>(
        phi, plo, whi + 3 * (size_t)NW, bo, out);
}

// round 12
// speedup vs baseline: 1.0544x; 1.0012x over previous
#include <cuda_runtime.h>
#include <cuda_fp16.h>
#include <cstdint>

#define BATCH 4
#define SEQ   4096
#define CH    1024
#define NH    16
#define HD    64
#define BS    64
#define NB    (SEQ / BS)          // 64
#define MROWS (BATCH * SEQ)       // 16384

// ---------------- scratch (device globals: allocation-free) ----------------
__device__ float g_Q[(size_t)MROWS * CH];
__device__ float g_K[(size_t)MROWS * CH];
__device__ float g_V[(size_t)MROWS * CH];
__device__ __half g_Ahi[(size_t)MROWS * CH];
__device__ __half g_Alo[(size_t)MROWS * CH];
__device__ __half g_Phi[(size_t)MROWS * CH];
__device__ __half g_Plo[(size_t)MROWS * CH];
__device__ __half g_Whi[(size_t)4 * CH * CH];

// =================== helpers ===================
__device__ __forceinline__ uint32_t smem_u32(const void* p) {
    uint32_t a;
    asm("{ .reg .u64 t; cvta.to.shared.u64 t, %1; cvt.u32.u64 %0, t; }"
        : "=r"(a) : "l"(p));
    return a;
}
__device__ __forceinline__ void cp16(uint32_t dst, const void* src) {
    asm volatile("cp.async.cg.shared.global [%0], [%1], 16;" :: "r"(dst), "l"(src));
}
__device__ __forceinline__ void cp_commit() {
    asm volatile("cp.async.commit_group;" ::: "memory");
}
template <int N>
__device__ __forceinline__ void cp_wait() {
    asm volatile("cp.async.wait_group %0;" :: "n"(N) : "memory");
}
__device__ __forceinline__ void ldsm4(uint32_t& r0, uint32_t& r1, uint32_t& r2,
                                      uint32_t& r3, uint32_t addr) {
    asm volatile("ldmatrix.sync.aligned.m8n8.x4.shared.b16 {%0,%1,%2,%3}, [%4];"
                 : "=r"(r0), "=r"(r1), "=r"(r2), "=r"(r3) : "r"(addr));
}
__device__ __forceinline__ void mma16816(float* c, const uint32_t* a,
                                         uint32_t b0, uint32_t b1) {
    asm volatile(
        "mma.sync.aligned.m16n8k16.row.col.f32.f16.f16.f32 "
        "{%0,%1,%2,%3}, {%4,%5,%6,%7}, {%8,%9}, {%0,%1,%2,%3};"
        : "+f"(c[0]), "+f"(c[1]), "+f"(c[2]), "+f"(c[3])
        : "r"(a[0]), "r"(a[1]), "r"(a[2]), "r"(a[3]), "r"(b0), "r"(b1));
}
// ---- packed f32x2 (FFMA2) helpers ----
__device__ __forceinline__ unsigned long long pack2(float x, float y) {
    unsigned long long r;
    asm("mov.b64 %0, {%1, %2};" : "=l"(r) : "f"(x), "f"(y));
    return r;
}
__device__ __forceinline__ void unpack2(unsigned long long v, float& x, float& y) {
    asm("mov.b64 {%0, %1}, %2;" : "=f"(x), "=f"(y) : "l"(v));
}
__device__ __forceinline__ void fma2(unsigned long long& d, unsigned long long a,
                                     unsigned long long b) {
    asm("fma.rn.f32x2 %0, %1, %2, %0;" : "+l"(d) : "l"(a), "l"(b));
}

// =================== fp32 -> fp16 hi/lo splitter (8 elems, 16B stores) =====
__global__ __launch_bounds__(256) void split_f16(
    const float* __restrict__ in, __half* __restrict__ hi,
    __half* __restrict__ lo, int n)
{
    int i = (blockIdx.x * 256 + threadIdx.x) * 8;
    if (i >= n) return;
    float4 v0 = *(const float4*)(in + i);
    float4 v1 = *(const float4*)(in + i + 4);
    float vv[8] = {v0.x, v0.y, v0.z, v0.w, v1.x, v1.y, v1.z, v1.w};
    __half2 hp[4], lp[4];
#pragma unroll
    for (int t = 0; t < 4; t++) {
        __half h0 = __float2half(vv[2 * t]);
        __half h1 = __float2half(vv[2 * t + 1]);
        hp[t].x = h0; hp[t].y = h1;
        lp[t].x = __float2half(vv[2 * t]     - __half2float(h0));
        lp[t].y = __float2half(vv[2 * t + 1] - __half2float(h1));
    }
    *(uint4*)(hi + i) = *(uint4*)hp;
    *(uint4*)(lo + i) = *(uint4*)lp;
}
// all 4 weight matrices; 8 elems/thread, one 16B store
__global__ __launch_bounds__(256) void to_f16_w4(
    const float* __restrict__ w0, const float* __restrict__ w1,
    const float* __restrict__ w2, const float* __restrict__ w3,
    __half* __restrict__ hi)
{
    const int seg = blockIdx.x >> 9;             // 0..3
    const int loc = (int)(blockIdx.x & 511) * 2048 + threadIdx.x * 8;
    const float* in = (seg == 0) ? w0 : (seg == 1) ? w1 : (seg == 2) ? w2 : w3;
    float4 v0 = *(const float4*)(in + loc);
    float4 v1 = *(const float4*)(in + loc + 4);
    __half2 hp[4];
    hp[0].x = __float2half(v0.x); hp[0].y = __float2half(v0.y);
    hp[1].x = __float2half(v0.z); hp[1].y = __float2half(v0.w);
    hp[2].x = __float2half(v1.x); hp[2].y = __float2half(v1.y);
    hp[3].x = __float2half(v1.z); hp[3].y = __float2half(v1.w);
    *(uint4*)(hi + (size_t)seg * CH * CH + loc) = *(uint4*)hp;
}

// =================== HMMA GEMM core (BM=BN=128, BK=32, 8 warps) =============
#define BKH 32
#define NKC (CH / BKH)            // 32
#define HT_BYTES 8192
#define HSTAGE (3 * HT_BYTES)
#define HGEMM_SMEM (3 * HSTAGE)   // 73728

__device__ __forceinline__ uint32_t sw_off(int row, int chunk) {
    return (uint32_t)(row * 64 + ((chunk ^ ((row >> 1) & 3)) << 4));
}

__device__ __forceinline__ void gemm_body(
    const __half* __restrict__ Ahi_t, const __half* __restrict__ Alo_t,
    const __half* __restrict__ Bh_t,
    const float* __restrict__ bias, float* __restrict__ Out,
    int bm, int bn, char* dsm)
{
    const uint32_t base = smem_u32(dsm);
    const int tid  = threadIdx.x;
    const int wid  = tid >> 5;
    const int lane = tid & 31;
    const int wm = (wid & 3) * 32;
    const int wn = (wid >> 2) * 64;

    const __half* srcs[3] = { Ahi_t, Alo_t, Bh_t };

    auto load_stage = [&](int st, int kc) {
        const uint32_t sb = base + st * HSTAGE;
#pragma unroll
        for (int p = 0; p < 6; p++) {
            int idx = p * 256 + tid;
            int buf = idx >> 9;
            int rem = idx & 511;
            int row = rem >> 2;
            int ch  = rem & 3;
            const __half* s = srcs[buf] + (size_t)row * CH + kc * BKH + ch * 8;
            cp16(sb + buf * HT_BYTES + sw_off(row, ch), s);
        }
        cp_commit();
    };

    float acc[2][8][4];
#pragma unroll
    for (int mi = 0; mi < 2; mi++)
#pragma unroll
        for (int ni = 0; ni < 8; ni++)
#pragma unroll
            for (int t = 0; t < 4; t++) acc[mi][ni][t] = 0.0f;

    load_stage(0, 0);
    load_stage(1, 1);

    const int lr = lane & 15;
    const int lc = lane >> 4;

    for (int kc = 0; kc < NKC; kc++) {
        if (kc < NKC - 1) cp_wait<1>(); else cp_wait<0>();
        __syncthreads();

        const uint32_t sb = base + (kc % 3) * HSTAGE;
        const uint32_t aHib = sb;
        const uint32_t aLob = sb + HT_BYTES;
        const uint32_t bHib = sb + 2 * HT_BYTES;

#pragma unroll
        for (int ks = 0; ks < 2; ks++) {
            const int chnk = ks * 2 + lc;
            uint32_t ah[2][4], al[2][4], bh[4][4];
#pragma unroll
            for (int mi = 0; mi < 2; mi++) {
                uint32_t off = sw_off(wm + mi * 16 + lr, chnk);
                ldsm4(ah[mi][0], ah[mi][1], ah[mi][2], ah[mi][3], aHib + off);
                ldsm4(al[mi][0], al[mi][1], al[mi][2], al[mi][3], aLob + off);
            }
#pragma unroll
            for (int g = 0; g < 4; g++) {
                uint32_t off = sw_off(wn + g * 16 + lr, chnk);
                ldsm4(bh[g][0], bh[g][1], bh[g][2], bh[g][3], bHib + off);
            }
#pragma unroll
            for (int mi = 0; mi < 2; mi++)
#pragma unroll
                for (int ni = 0; ni < 8; ni++) {
                    const int g = ni >> 1, w = ni & 1;
                    mma16816(acc[mi][ni], ah[mi], bh[g][w], bh[g][w + 2]);
                    mma16816(acc[mi][ni], al[mi], bh[g][w], bh[g][w + 2]);
                }
        }
        if (kc + 2 < NKC) load_stage((kc + 2) % 3, kc + 2);
    }

#pragma unroll
    for (int mi = 0; mi < 2; mi++) {
        const int r0 = bm + wm + mi * 16 + (lane >> 2);
#pragma unroll
        for (int ni = 0; ni < 8; ni++) {
            const int c = bn + wn + ni * 8 + (lane & 3) * 2;
            const float b0 = bias[c], b1 = bias[c + 1];
            float2 v0 = make_float2(acc[mi][ni][0] + b0, acc[mi][ni][1] + b1);
            float2 v1 = make_float2(acc[mi][ni][2] + b0, acc[mi][ni][3] + b1);
            *(float2*)(Out + (size_t)r0 * CH + c)       = v0;
            *(float2*)(Out + (size_t)(r0 + 8) * CH + c) = v1;
        }
    }
}

__global__ __launch_bounds__(256, 2) void gemm_qkv(
    const __half* __restrict__ Ahi, const __half* __restrict__ Alo,
    const __half* __restrict__ Wall,
    const float* __restrict__ bq, const float* __restrict__ bk,
    const float* __restrict__ bv,
    float* __restrict__ Qo, float* __restrict__ Ko, float* __restrict__ Vo)
{
    extern __shared__ char dsm[];
    const int bng = blockIdx.x * 128;
    const int sel = bng >> 10;
    const int bn  = bng & 1023;
    const int bm  = blockIdx.y * 128;
    const float* bias = (sel == 0) ? bq : (sel == 1) ? bk : bv;
    float* Out = (sel == 0) ? Qo : (sel == 1) ? Ko : Vo;
    const __half* Bh = Wall + (size_t)sel * CH * CH + (size_t)bn * CH;
    gemm_body(Ahi + (size_t)bm * CH, Alo + (size_t)bm * CH, Bh, bias, Out, bm, bn, dsm);
}

__global__ __launch_bounds__(256, 2) void gemm_hmma(
    const __half* __restrict__ Ahi, const __half* __restrict__ Alo,
    const __half* __restrict__ Bh,
    const float* __restrict__ bias, float* __restrict__ Out)
{
    extern __shared__ char dsm[];
    const int bm = blockIdx.y * 128;
    const int bn = blockIdx.x * 128;
    gemm_body(Ahi + (size_t)bm * CH, Alo + (size_t)bm * CH,
              Bh + (size_t)bn * CH, bias, Out, bm, bn, dsm);
}

// ---------------- attention: 128-col window (blocks n-1, n only) -----------
#define QT_STRIDE 68
#define KT_STRIDE 132
#define VS_STRIDE 68
#define PS_STRIDE 132
#define WIN 128
#define QT_OFF 0
#define KV_OFF (64 * QT_STRIDE)
#define KV_FLOATS 8704
#define PS_OFF (KV_OFF + KV_FLOATS)
#define SMEM_FLOATS (PS_OFF + (64 * PS_STRIDE) / 2)
#define ATTN_SMEM_BYTES (SMEM_FLOATS * 4)         // 69120

__global__ __launch_bounds__(256, 3) void attn_kernel(
    const float* __restrict__ Q, const float* __restrict__ K,
    const float* __restrict__ V,
    __half* __restrict__ Ohi, __half* __restrict__ Olo)
{
    extern __shared__ float sm[];
    float*  qT  = sm + QT_OFF;
    float*  kT  = sm + KV_OFF;
    float*  vs  = sm + KV_OFF;
    __half* Ps  = (__half*)(sm + PS_OFF);

    const int tid  = threadIdx.x;
    const int warp = tid >> 5;
    const int lane = tid & 31;
    const int n = blockIdx.x;
    const int h = blockIdx.y;
    const int b = blockIdx.z;
    const size_t base = (size_t)b * SEQ * CH + (size_t)h * HD;

#pragma unroll
    for (int p = 0; p < 4; p++) {
        int idx = tid + p * 256;
        int i   = idx >> 4;
        int dd0 = (idx & 15) << 2;
        float4 v4 = *(const float4*)(Q + base + (size_t)(n * BS + i) * CH + dd0);
        qT[(dd0 + 0) * QT_STRIDE + i] = v4.x;
        qT[(dd0 + 1) * QT_STRIDE + i] = v4.y;
        qT[(dd0 + 2) * QT_STRIDE + i] = v4.z;
        qT[(dd0 + 3) * QT_STRIDE + i] = v4.w;
    }
#pragma unroll
    for (int p = 0; p < 8; p++) {
        int idx = tid + p * 256;
        int j   = idx >> 4;
        int dd0 = (idx & 15) << 2;
        int kpos = (n - 1) * BS + j;
        float4 v4 = make_float4(0.f, 0.f, 0.f, 0.f);
        if (kpos >= 0)
            v4 = *(const float4*)(K + base + (size_t)kpos * CH + dd0);
        kT[(dd0 + 0) * KT_STRIDE + j] = v4.x;
        kT[(dd0 + 1) * KT_STRIDE + j] = v4.y;
        kT[(dd0 + 2) * KT_STRIDE + j] = v4.z;
        kT[(dd0 + 3) * KT_STRIDE + j] = v4.w;
    }
    __syncthreads();

    // ---- score: warp owns 8 rows (i0), lane owns 4 cols (j0); FFMA2 packed
    const int i0 = warp << 3;
    const int j0 = lane << 2;
    unsigned long long acc2[4][4];
#pragma unroll
    for (int p = 0; p < 4; p++)
#pragma unroll
        for (int jj = 0; jj < 4; jj++) acc2[p][jj] = 0ull;

#pragma unroll 4
    for (int dd = 0; dd < 64; dd++) {
        ulonglong2 a01 = *(const ulonglong2*)&qT[dd * QT_STRIDE + i0];
        ulonglong2 a23 = *(const ulonglong2*)&qT[dd * QT_STRIDE + i0 + 4];
        float4 b4 = *(const float4*)&kT[dd * KT_STRIDE + j0];
        unsigned long long ap[4] = {a01.x, a01.y, a23.x, a23.y};
        unsigned long long bb[4] = {pack2(b4.x, b4.x), pack2(b4.y, b4.y),
                                    pack2(b4.z, b4.z), pack2(b4.w, b4.w)};
#pragma unroll
        for (int p = 0; p < 4; p++)
#pragma unroll
            for (int jj = 0; jj < 4; jj++)
                fma2(acc2[p][jj], ap[p], bb[jj]);
    }

    float acc[8][4];
#pragma unroll
    for (int p = 0; p < 4; p++)
#pragma unroll
        for (int jj = 0; jj < 4; jj++)
            unpack2(acc2[p][jj], acc[2 * p][jj], acc[2 * p + 1][jj]);

    const float scale = 0.125f;
    float mrow[8];
#pragma unroll
    for (int ii = 0; ii < 8; ii++) {
        const int i = i0 + ii;
        mrow[ii] = -1e30f;
#pragma unroll
        for (int jj = 0; jj < 4; jj++) {
            const int j = j0 + jj;
            bool valid = (j <= i + BS) && (n > 0 || j >= BS);
            acc[ii][jj] = valid ? acc[ii][jj] * scale : -1e30f;
            mrow[ii] = fmaxf(mrow[ii], acc[ii][jj]);
        }
    }
#pragma unroll
    for (int ii = 0; ii < 8; ii++) {
        mrow[ii] = fmaxf(mrow[ii], __shfl_xor_sync(0xffffffffu, mrow[ii], 1));
        mrow[ii] = fmaxf(mrow[ii], __shfl_xor_sync(0xffffffffu, mrow[ii], 2));
        mrow[ii] = fmaxf(mrow[ii], __shfl_xor_sync(0xffffffffu, mrow[ii], 4));
        mrow[ii] = fmaxf(mrow[ii], __shfl_xor_sync(0xffffffffu, mrow[ii], 8));
        mrow[ii] = fmaxf(mrow[ii], __shfl_xor_sync(0xffffffffu, mrow[ii], 16));
    }
    float srow[8];
#pragma unroll
    for (int ii = 0; ii < 8; ii++) {
        srow[ii] = 0.f;
#pragma unroll
        for (int jj = 0; jj < 4; jj++) {
            acc[ii][jj] = __expf(acc[ii][jj] - mrow[ii]);
            srow[ii] += acc[ii][jj];
        }
    }
#pragma unroll
    for (int ii = 0; ii < 8; ii++) {
        srow[ii] += __shfl_xor_sync(0xffffffffu, srow[ii], 1);
        srow[ii] += __shfl_xor_sync(0xffffffffu, srow[ii], 2);
        srow[ii] += __shfl_xor_sync(0xffffffffu, srow[ii], 4);
        srow[ii] += __shfl_xor_sync(0xffffffffu, srow[ii], 8);
        srow[ii] += __shfl_xor_sync(0xffffffffu, srow[ii], 16);
        const float inv = 1.0f / srow[ii];
        __half2 p01, p23;
        p01.x = __float2half(acc[ii][0] * inv);
        p01.y = __float2half(acc[ii][1] * inv);
        p23.x = __float2half(acc[ii][2] * inv);
        p23.y = __float2half(acc[ii][3] * inv);
        __half* prow = Ps + (i0 + ii) * PS_STRIDE + j0;
        *(__half2*)(prow)     = p01;
        *(__half2*)(prow + 2) = p23;
    }
    __syncthreads();

    // v window over kT region
#pragma unroll
    for (int p = 0; p < 8; p++) {
        int idx = tid + p * 256;
        int j   = idx >> 4;
        int dd0 = (idx & 15) << 2;
        int kpos = (n - 1) * BS + j;
        float4 v4 = make_float4(0.f, 0.f, 0.f, 0.f);
        if (kpos >= 0)
            v4 = *(const float4*)(V + base + (size_t)kpos * CH + dd0);
        *(float4*)&vs[j * VS_STRIDE + dd0] = v4;
    }
    __syncthreads();

    // ---- PV: 4 rows per 16-thread group; j-quads, 8B Ps reads, FFMA2
    const int i0p = (tid >> 4) << 2;
    const int c0  = (tid & 15) << 2;
    unsigned long long o2[4][2];
#pragma unroll
    for (int ii = 0; ii < 4; ii++) { o2[ii][0] = 0ull; o2[ii][1] = 0ull; }

    const int jlim = (i0p + 68 < WIN) ? (i0p + 68) : WIN;   // multiple of 4
#pragma unroll 1
    for (int j = 0; j < jlim; j += 4) {
        ulonglong2 va = *(const ulonglong2*)&vs[(j + 0) * VS_STRIDE + c0];
        ulonglong2 vb = *(const ulonglong2*)&vs[(j + 1) * VS_STRIDE + c0];
        ulonglong2 vc = *(const ulonglong2*)&vs[(j + 2) * VS_STRIDE + c0];
        ulonglong2 vd = *(const ulonglong2*)&vs[(j + 3) * VS_STRIDE + c0];
#pragma unroll
        for (int ii = 0; ii < 4; ii++) {
            uint2 pq = *(const uint2*)&Ps[(i0p + ii) * PS_STRIDE + j];
            float2 p01 = __half22float2(*reinterpret_cast<__half2*>(&pq.x));
            float2 p23 = __half22float2(*reinterpret_cast<__half2*>(&pq.y));
            unsigned long long px = pack2(p01.x, p01.x);
            unsigned long long py = pack2(p01.y, p01.y);
            unsigned long long pz = pack2(p23.x, p23.x);
            unsigned long long pw = pack2(p23.y, p23.y);
            fma2(o2[ii][0], px, va.x); fma2(o2[ii][1], px, va.y);
            fma2(o2[ii][0], py, vb.x); fma2(o2[ii][1], py, vb.y);
            fma2(o2[ii][0], pz, vc.x); fma2(o2[ii][1], pz, vc.y);
            fma2(o2[ii][0], pw, vd.x); fma2(o2[ii][1], pw, vd.y);
        }
    }
#pragma unroll
    for (int ii = 0; ii < 4; ii++) {
        float o0, o1, o2f, o3;
        unpack2(o2[ii][0], o0, o1);
        unpack2(o2[ii][1], o2f, o3);
        const size_t oidx = base + (size_t)(n * BS + i0p + ii) * CH + c0;
        __half h0 = __float2half(o0);
        __half h1 = __float2half(o1);
        __half h2 = __float2half(o2f);
        __half h3 = __float2half(o3);
        __half2 hp0; hp0.x = h0; hp0.y = h1;
        __half2 hp1; hp1.x = h2; hp1.y = h3;
        __half2 lp0, lp1;
        lp0.x = __float2half(o0 - __half2float(h0));
        lp0.y = __float2half(o1 - __half2float(h1));
        lp1.x = __float2half(o2f - __half2float(h2));
        lp1.y = __float2half(o3 - __half2float(h3));
        *(__half2*)(Ohi + oidx)     = hp0;
        *(__half2*)(Ohi + oidx + 2) = hp1;
        *(__half2*)(Olo + oidx)     = lp0;
        *(__half2*)(Olo + oidx + 2) = lp1;
    }
}

// ---------------------------------------------------------------------------
extern "C" void kernel_launch(void* const* d_in, const int* in_sizes, int n_in,
                              void* d_out, int out_size)
{
    const float* x  = (const float*)d_in[0];
    const float* Wq = (const float*)d_in[1];
    const float* bq = (const float*)d_in[2];
    const float* Wk = (const float*)d_in[3];
    const float* bk = (const float*)d_in[4];
    const float* Wv = (const float*)d_in[5];
    const float* bv = (const float*)d_in[6];
    const float* Wo = (const float*)d_in[7];
    const float* bo = (const float*)d_in[8];
    float* out = (float*)d_out;

    float *qp, *kp, *vp;
    __half *ahi, *alo, *phi, *plo, *whi;
    cudaGetSymbolAddress((void**)&qp,  g_Q);
    cudaGetSymbolAddress((void**)&kp,  g_K);
    cudaGetSymbolAddress((void**)&vp,  g_V);
    cudaGetSymbolAddress((void**)&ahi, g_Ahi);
    cudaGetSymbolAddress((void**)&alo, g_Alo);
    cudaGetSymbolAddress((void**)&phi, g_Phi);
    cudaGetSymbolAddress((void**)&plo, g_Plo);
    cudaGetSymbolAddress((void**)&whi, g_Whi);

    cudaFuncSetAttribute(attn_kernel,
                         cudaFuncAttributeMaxDynamicSharedMemorySize, ATTN_SMEM_BYTES);
    cudaFuncSetAttribute(gemm_hmma,
                         cudaFuncAttributeMaxDynamicSharedMemorySize, HGEMM_SMEM);
    cudaFuncSetAttribute(gemm_qkv,
                         cudaFuncAttributeMaxDynamicSharedMemorySize, HGEMM_SMEM);

    const int NX = MROWS * CH;
    const int NW = CH * CH;

    split_f16<<<NX / 2048, 256>>>(x, ahi, alo, NX);
    to_f16_w4<<<2048, 256>>>(Wq, Wk, Wv, Wo, whi);

    gemm_qkv<<<dim3(24, MROWS / 128), 256, HGEMM_SMEM>>>(
        ahi, alo, whi, bq, bk, bv, qp, kp, vp);

    attn_kernel<<<dim3(NB, NH, BATCH), 256, ATTN_SMEM_BYTES>>>(qp, kp, vp, phi, plo);

    gemm_hmma<<<dim3(8, MROWS / 128), 256, HGEMM_SMEM>>>(
        phi, plo, whi + 3 * (size_t)NW, bo, out);
}

// round 13
// speedup vs baseline: 1.1798x; 1.1190x over previous
#include <cuda_runtime.h>
#include <cuda_fp16.h>
#include <cstdint>

#define BATCH 4
#define SEQ   4096
#define CH    1024
#define NH    16
#define HD    64
#define BS    64
#define NB    (SEQ / BS)          // 64
#define MROWS (BATCH * SEQ)       // 16384

// ---------------- scratch (device globals: allocation-free) ----------------
__device__ float  g_V [(size_t)MROWS * CH];
__device__ __half g_Qh[(size_t)MROWS * CH];
__device__ __half g_Ql[(size_t)MROWS * CH];
__device__ __half g_Kh[(size_t)MROWS * CH];
__device__ __half g_Ahi[(size_t)MROWS * CH];
__device__ __half g_Alo[(size_t)MROWS * CH];
__device__ __half g_Phi[(size_t)MROWS * CH];
__device__ __half g_Plo[(size_t)MROWS * CH];
__device__ __half g_Whi[(size_t)4 * CH * CH];

// =================== helpers ===================
__device__ __forceinline__ uint32_t smem_u32(const void* p) {
    uint32_t a;
    asm("{ .reg .u64 t; cvta.to.shared.u64 t, %1; cvt.u32.u64 %0, t; }"
        : "=r"(a) : "l"(p));
    return a;
}
__device__ __forceinline__ void cp16(uint32_t dst, const void* src) {
    asm volatile("cp.async.cg.shared.global [%0], [%1], 16;" :: "r"(dst), "l"(src));
}
__device__ __forceinline__ void cp_commit() {
    asm volatile("cp.async.commit_group;" ::: "memory");
}
template <int N>
__device__ __forceinline__ void cp_wait() {
    asm volatile("cp.async.wait_group %0;" :: "n"(N) : "memory");
}
__device__ __forceinline__ void ldsm4(uint32_t& r0, uint32_t& r1, uint32_t& r2,
                                      uint32_t& r3, uint32_t addr) {
    asm volatile("ldmatrix.sync.aligned.m8n8.x4.shared.b16 {%0,%1,%2,%3}, [%4];"
                 : "=r"(r0), "=r"(r1), "=r"(r2), "=r"(r3) : "r"(addr));
}
__device__ __forceinline__ void mma16816(float* c, const uint32_t* a,
                                         uint32_t b0, uint32_t b1) {
    asm volatile(
        "mma.sync.aligned.m16n8k16.row.col.f32.f16.f16.f32 "
        "{%0,%1,%2,%3}, {%4,%5,%6,%7}, {%8,%9}, {%0,%1,%2,%3};"
        : "+f"(c[0]), "+f"(c[1]), "+f"(c[2]), "+f"(c[3])
        : "r"(a[0]), "r"(a[1]), "r"(a[2]), "r"(a[3]), "r"(b0), "r"(b1));
}
// ---- packed f32x2 (FFMA2) helpers ----
__device__ __forceinline__ unsigned long long pack2(float x, float y) {
    unsigned long long r;
    asm("mov.b64 %0, {%1, %2};" : "=l"(r) : "f"(x), "f"(y));
    return r;
}
__device__ __forceinline__ void unpack2(unsigned long long v, float& x, float& y) {
    asm("mov.b64 {%0, %1}, %2;" : "=f"(x), "=f"(y) : "l"(v));
}
__device__ __forceinline__ void fma2(unsigned long long& d, unsigned long long a,
                                     unsigned long long b) {
    asm("fma.rn.f32x2 %0, %1, %2, %0;" : "+l"(d) : "l"(a), "l"(b));
}

// =================== fp32 -> fp16 hi/lo splitter (8 elems, 16B stores) =====
__global__ __launch_bounds__(256) void split_f16(
    const float* __restrict__ in, __half* __restrict__ hi,
    __half* __restrict__ lo, int n)
{
    int i = (blockIdx.x * 256 + threadIdx.x) * 8;
    if (i >= n) return;
    float4 v0 = *(const float4*)(in + i);
    float4 v1 = *(const float4*)(in + i + 4);
    float vv[8] = {v0.x, v0.y, v0.z, v0.w, v1.x, v1.y, v1.z, v1.w};
    __half2 hp[4], lp[4];
#pragma unroll
    for (int t = 0; t < 4; t++) {
        __half h0 = __float2half(vv[2 * t]);
        __half h1 = __float2half(vv[2 * t + 1]);
        hp[t].x = h0; hp[t].y = h1;
        lp[t].x = __float2half(vv[2 * t]     - __half2float(h0));
        lp[t].y = __float2half(vv[2 * t + 1] - __half2float(h1));
    }
    *(uint4*)(hi + i) = *(uint4*)hp;
    *(uint4*)(lo + i) = *(uint4*)lp;
}
__global__ __launch_bounds__(256) void to_f16_w4(
    const float* __restrict__ w0, const float* __restrict__ w1,
    const float* __restrict__ w2, const float* __restrict__ w3,
    __half* __restrict__ hi)
{
    const int seg = blockIdx.x >> 9;
    const int loc = (int)(blockIdx.x & 511) * 2048 + threadIdx.x * 8;
    const float* in = (seg == 0) ? w0 : (seg == 1) ? w1 : (seg == 2) ? w2 : w3;
    float4 v0 = *(const float4*)(in + loc);
    float4 v1 = *(const float4*)(in + loc + 4);
    __half2 hp[4];
    hp[0].x = __float2half(v0.x); hp[0].y = __float2half(v0.y);
    hp[1].x = __float2half(v0.z); hp[1].y = __float2half(v0.w);
    hp[2].x = __float2half(v1.x); hp[2].y = __float2half(v1.y);
    hp[3].x = __float2half(v1.z); hp[3].y = __float2half(v1.w);
    *(uint4*)(hi + (size_t)seg * CH * CH + loc) = *(uint4*)hp;
}

// =================== HMMA GEMM core (BM=BN=128, BK=32, 8 warps) =============
#define BKH 32
#define NKC (CH / BKH)            // 32
#define HT_BYTES 8192
#define HSTAGE (3 * HT_BYTES)
#define HGEMM_SMEM (3 * HSTAGE)   // 73728

__device__ __forceinline__ uint32_t sw_off(int row, int chunk) {
    return (uint32_t)(row * 64 + ((chunk ^ ((row >> 1) & 3)) << 4));
}

// MODE 0: fp32 Out; MODE 1: fp16 hi/lo; MODE 2: fp16 hi only
template <int MODE>
__device__ __forceinline__ void gemm_body(
    const __half* __restrict__ Ahi_t, const __half* __restrict__ Alo_t,
    const __half* __restrict__ Bh_t,
    const float* __restrict__ bias,
    float* __restrict__ OutF, __half* __restrict__ OutH, __half* __restrict__ OutL,
    int bm, int bn, char* dsm)
{
    const uint32_t base = smem_u32(dsm);
    const int tid  = threadIdx.x;
    const int wid  = tid >> 5;
    const int lane = tid & 31;
    const int wm = (wid & 3) * 32;
    const int wn = (wid >> 2) * 64;

    const __half* srcs[3] = { Ahi_t, Alo_t, Bh_t };

    auto load_stage = [&](int st, int kc) {
        const uint32_t sb = base + st * HSTAGE;
#pragma unroll
        for (int p = 0; p < 6; p++) {
            int idx = p * 256 + tid;
            int buf = idx >> 9;
            int rem = idx & 511;
            int row = rem >> 2;
            int ch  = rem & 3;
            const __half* s = srcs[buf] + (size_t)row * CH + kc * BKH + ch * 8;
            cp16(sb + buf * HT_BYTES + sw_off(row, ch), s);
        }
        cp_commit();
    };

    float acc[2][8][4];
#pragma unroll
    for (int mi = 0; mi < 2; mi++)
#pragma unroll
        for (int ni = 0; ni < 8; ni++)
#pragma unroll
            for (int t = 0; t < 4; t++) acc[mi][ni][t] = 0.0f;

    load_stage(0, 0);
    load_stage(1, 1);

    const int lr = lane & 15;
    const int lc = lane >> 4;

    for (int kc = 0; kc < NKC; kc++) {
        if (kc < NKC - 1) cp_wait<1>(); else cp_wait<0>();
        __syncthreads();

        const uint32_t sb = base + (kc % 3) * HSTAGE;
        const uint32_t aHib = sb;
        const uint32_t aLob = sb + HT_BYTES;
        const uint32_t bHib = sb + 2 * HT_BYTES;

#pragma unroll
        for (int ks = 0; ks < 2; ks++) {
            const int chnk = ks * 2 + lc;
            uint32_t ah[2][4], al[2][4], bh[4][4];
#pragma unroll
            for (int mi = 0; mi < 2; mi++) {
                uint32_t off = sw_off(wm + mi * 16 + lr, chnk);
                ldsm4(ah[mi][0], ah[mi][1], ah[mi][2], ah[mi][3], aHib + off);
                ldsm4(al[mi][0], al[mi][1], al[mi][2], al[mi][3], aLob + off);
            }
#pragma unroll
            for (int g = 0; g < 4; g++) {
                uint32_t off = sw_off(wn + g * 16 + lr, chnk);
                ldsm4(bh[g][0], bh[g][1], bh[g][2], bh[g][3], bHib + off);
            }
#pragma unroll
            for (int mi = 0; mi < 2; mi++)
#pragma unroll
                for (int ni = 0; ni < 8; ni++) {
                    const int g = ni >> 1, w = ni & 1;
                    mma16816(acc[mi][ni], ah[mi], bh[g][w], bh[g][w + 2]);
                    mma16816(acc[mi][ni], al[mi], bh[g][w], bh[g][w + 2]);
                }
        }
        if (kc + 2 < NKC) load_stage((kc + 2) % 3, kc + 2);
    }

#pragma unroll
    for (int mi = 0; mi < 2; mi++) {
        const int r0 = bm + wm + mi * 16 + (lane >> 2);
#pragma unroll
        for (int ni = 0; ni < 8; ni++) {
            const int c = bn + wn + ni * 8 + (lane & 3) * 2;
            const float b0 = bias[c], b1 = bias[c + 1];
            float q0 = acc[mi][ni][0] + b0, q1 = acc[mi][ni][1] + b1;
            float q2 = acc[mi][ni][2] + b0, q3 = acc[mi][ni][3] + b1;
            if (MODE == 0) {
                *(float2*)(OutF + (size_t)r0 * CH + c)       = make_float2(q0, q1);
                *(float2*)(OutF + (size_t)(r0 + 8) * CH + c) = make_float2(q2, q3);
            } else {
                __half2 h01, h23;
                h01.x = __float2half(q0); h01.y = __float2half(q1);
                h23.x = __float2half(q2); h23.y = __float2half(q3);
                *(__half2*)(OutH + (size_t)r0 * CH + c)       = h01;
                *(__half2*)(OutH + (size_t)(r0 + 8) * CH + c) = h23;
                if (MODE == 1) {
                    __half2 l01, l23;
                    l01.x = __float2half(q0 - __half2float(h01.x));
                    l01.y = __float2half(q1 - __half2float(h01.y));
                    l23.x = __float2half(q2 - __half2float(h23.x));
                    l23.y = __float2half(q3 - __half2float(h23.y));
                    *(__half2*)(OutL + (size_t)r0 * CH + c)       = l01;
                    *(__half2*)(OutL + (size_t)(r0 + 8) * CH + c) = l23;
                }
            }
        }
    }
}

// fused QKV GEMM: Q -> fp16 hi/lo, K -> fp16 hi, V -> fp32
__global__ __launch_bounds__(256, 2) void gemm_qkv(
    const __half* __restrict__ Ahi, const __half* __restrict__ Alo,
    const __half* __restrict__ Wall,
    const float* __restrict__ bq, const float* __restrict__ bk,
    const float* __restrict__ bv,
    __half* __restrict__ Qh, __half* __restrict__ Ql,
    __half* __restrict__ Kh, float* __restrict__ Vf)
{
    extern __shared__ char dsm[];
    const int bng = blockIdx.x * 128;
    const int sel = bng >> 10;
    const int bn  = bng & 1023;
    const int bm  = blockIdx.y * 128;
    const __half* Bh = Wall + (size_t)sel * CH * CH + (size_t)bn * CH;
    const __half* Ah = Ahi + (size_t)bm * CH;
    const __half* Al = Alo + (size_t)bm * CH;
    if (sel == 0)
        gemm_body<1>(Ah, Al, Bh, bq, nullptr, Qh, Ql, bm, bn, dsm);
    else if (sel == 1)
        gemm_body<2>(Ah, Al, Bh, bk, nullptr, Kh, nullptr, bm, bn, dsm);
    else
        gemm_body<0>(Ah, Al, Bh, bv, Vf, nullptr, nullptr, bm, bn, dsm);
}

__global__ __launch_bounds__(256, 2) void gemm_hmma(
    const __half* __restrict__ Ahi, const __half* __restrict__ Alo,
    const __half* __restrict__ Bh,
    const float* __restrict__ bias, float* __restrict__ Out)
{
    extern __shared__ char dsm[];
    const int bm = blockIdx.y * 128;
    const int bn = blockIdx.x * 128;
    gemm_body<0>(Ahi + (size_t)bm * CH, Alo + (size_t)bm * CH,
                 Bh + (size_t)bn * CH, bias, Out, nullptr, nullptr, bm, bn, dsm);
}

// ---------------- attention: HMMA scores + FFMA2 PV ------------------------
// smem bytes:
//  [0, 16896)      QH tiles (0,4096) + QL tiles (8192,12288); later Ps fp16 [64][132]
//  [16896, 33280)  KH tiles (2 x [128][32]h)
//  [33280, 68096)  vs fp32 [128][68]
//  [68096, 69120)  maxbuf[2][64], sumbuf[2][64]
#define A_QH 0
#define A_QL 8192
#define A_KH 16896
#define A_VS 33280
#define A_RED 68096
#define PS_STRIDE 132
#define VS_STRIDE 68
#define WIN 128
#define ATTN_SMEM_BYTES 69120

__global__ __launch_bounds__(256, 3) void attn_kernel(
    const __half* __restrict__ Qh, const __half* __restrict__ Ql,
    const __half* __restrict__ Kh, const float* __restrict__ V,
    __half* __restrict__ Ohi, __half* __restrict__ Olo)
{
    extern __shared__ char dsm[];
    const uint32_t sbase = smem_u32(dsm);
    float*  vs   = (float*)(dsm + A_VS);
    __half* Ps   = (__half*)(dsm + 0);
    float*  maxb = (float*)(dsm + A_RED);
    float*  sumb = maxb + 128;

    const int tid  = threadIdx.x;
    const int warp = tid >> 5;
    const int lane = tid & 31;
    const int n = blockIdx.x;
    const int h = blockIdx.y;
    const int b = blockIdx.z;
    const size_t rowbase = (size_t)b * SEQ * CH + (size_t)h * HD;

    // ---- async loads: Q hi/lo (64 rows x 8 chunks), K hi (128 x 8)
#pragma unroll
    for (int p = 0; p < 2; p++) {
        int idx = tid + p * 256;          // 0..511
        int i  = idx >> 3;
        int ch = idx & 7;
        int kc = ch >> 2, cc = ch & 3;
        const __half* sh = Qh + rowbase + (size_t)(n * BS + i) * CH + ch * 8;
        const __half* sl = Ql + rowbase + (size_t)(n * BS + i) * CH + ch * 8;
        cp16(sbase + A_QH + kc * 4096 + sw_off(i, cc), sh);
        cp16(sbase + A_QL + kc * 4096 + sw_off(i, cc), sl);
    }
#pragma unroll
    for (int p = 0; p < 4; p++) {
        int idx = tid + p * 256;          // 0..1023
        int j  = idx >> 3;
        int ch = idx & 7;
        int kc = ch >> 2, cc = ch & 3;
        int kpos = (n - 1) * BS + j;
        uint32_t off = A_KH + kc * 8192 + sw_off(j, cc);
        if (kpos >= 0)
            cp16(sbase + off, Kh + rowbase + (size_t)kpos * CH + ch * 8);
        else
            *(uint4*)(dsm + off) = make_uint4(0, 0, 0, 0);
    }
    cp_commit();
    // V fp32 (plain LDG/STS)
#pragma unroll
    for (int p = 0; p < 8; p++) {
        int idx = tid + p * 256;
        int j   = idx >> 4;
        int dd0 = (idx & 15) << 2;
        int kpos = (n - 1) * BS + j;
        float4 v4 = make_float4(0.f, 0.f, 0.f, 0.f);
        if (kpos >= 0)
            v4 = *(const float4*)(V + rowbase + (size_t)kpos * CH + dd0);
        *(float4*)&vs[j * VS_STRIDE + dd0] = v4;
    }
    cp_wait<0>();
    __syncthreads();

    // ---- scores via HMMA: warp = (m-band w&3)*16 rows x (n-half w>>2)*64 cols
    const int wm = (warp & 3) * 16;
    const int wn = (warp >> 2) * 64;
    const int wh = warp >> 2;
    const int lr = lane & 15;
    const int lc = lane >> 4;

    float acc[8][4];
#pragma unroll
    for (int nf = 0; nf < 8; nf++)
#pragma unroll
        for (int t = 0; t < 4; t++) acc[nf][t] = 0.0f;

#pragma unroll
    for (int kc = 0; kc < 2; kc++)
#pragma unroll
        for (int ks = 0; ks < 2; ks++) {
            const int chnk = ks * 2 + lc;
            uint32_t ah[4], al[4], bh[4][4];
            uint32_t qoff = sw_off(wm + lr, chnk);
            ldsm4(ah[0], ah[1], ah[2], ah[3], sbase + A_QH + kc * 4096 + qoff);
            ldsm4(al[0], al[1], al[2], al[3], sbase + A_QL + kc * 4096 + qoff);
#pragma unroll
            for (int g = 0; g < 4; g++) {
                uint32_t off = sw_off(wn + g * 16 + lr, chnk);
                ldsm4(bh[g][0], bh[g][1], bh[g][2], bh[g][3],
                      sbase + A_KH + kc * 8192 + off);
            }
#pragma unroll
            for (int nf = 0; nf < 8; nf++) {
                const int g = nf >> 1, w = nf & 1;
                mma16816(acc[nf], ah, bh[g][w], bh[g][w + 2]);
                mma16816(acc[nf], al, bh[g][w], bh[g][w + 2]);
            }
        }

    // ---- mask + scale; fragment rows r0 = wm+(lane>>2), r1 = r0+8
    const float scale = 0.125f;
    const int r0 = wm + (lane >> 2);
    const int r1 = r0 + 8;
    float rm0 = -1e30f, rm1 = -1e30f;
#pragma unroll
    for (int nf = 0; nf < 8; nf++) {
        const int j0 = wn + nf * 8 + ((lane & 3) << 1);
        const int j1 = j0 + 1;
        bool w0 = (n > 0 || j0 >= BS);
        bool w1 = (n > 0 || j1 >= BS);
        acc[nf][0] = (w0 && j0 <= r0 + BS) ? acc[nf][0] * scale : -1e30f;
        acc[nf][1] = (w1 && j1 <= r0 + BS) ? acc[nf][1] * scale : -1e30f;
        acc[nf][2] = (w0 && j0 <= r1 + BS) ? acc[nf][2] * scale : -1e30f;
        acc[nf][3] = (w1 && j1 <= r1 + BS) ? acc[nf][3] * scale : -1e30f;
        rm0 = fmaxf(rm0, fmaxf(acc[nf][0], acc[nf][1]));
        rm1 = fmaxf(rm1, fmaxf(acc[nf][2], acc[nf][3]));
    }
    rm0 = fmaxf(rm0, __shfl_xor_sync(0xffffffffu, rm0, 1));
    rm0 = fmaxf(rm0, __shfl_xor_sync(0xffffffffu, rm0, 2));
    rm1 = fmaxf(rm1, __shfl_xor_sync(0xffffffffu, rm1, 1));
    rm1 = fmaxf(rm1, __shfl_xor_sync(0xffffffffu, rm1, 2));
    if ((lane & 3) == 0) {
        maxb[wh * 64 + r0] = rm0;
        maxb[wh * 64 + r1] = rm1;
    }
    __syncthreads();
    const float m0 = fmaxf(maxb[r0], maxb[64 + r0]);
    const float m1 = fmaxf(maxb[r1], maxb[64 + r1]);

    float s0 = 0.f, s1 = 0.f;
#pragma unroll
    for (int nf = 0; nf < 8; nf++) {
        acc[nf][0] = __expf(acc[nf][0] - m0);
        acc[nf][1] = __expf(acc[nf][1] - m0);
        acc[nf][2] = __expf(acc[nf][2] - m1);
        acc[nf][3] = __expf(acc[nf][3] - m1);
        s0 += acc[nf][0] + acc[nf][1];
        s1 += acc[nf][2] + acc[nf][3];
    }
    s0 += __shfl_xor_sync(0xffffffffu, s0, 1);
    s0 += __shfl_xor_sync(0xffffffffu, s0, 2);
    s1 += __shfl_xor_sync(0xffffffffu, s1, 1);
    s1 += __shfl_xor_sync(0xffffffffu, s1, 2);
    if ((lane & 3) == 0) {
        sumb[wh * 64 + r0] = s0;
        sumb[wh * 64 + r1] = s1;
    }
    __syncthreads();
    const float inv0 = 1.0f / (sumb[r0] + sumb[64 + r0]);
    const float inv1 = 1.0f / (sumb[r1] + sumb[64 + r1]);

    // store P (fp16) into the Ps region (aliases Q tiles; all Q reads done)
#pragma unroll
    for (int nf = 0; nf < 8; nf++) {
        const int j0 = wn + nf * 8 + ((lane & 3) << 1);
        __half2 p0, p1;
        p0.x = __float2half(acc[nf][0] * inv0);
        p0.y = __float2half(acc[nf][1] * inv0);
        p1.x = __float2half(acc[nf][2] * inv1);
        p1.y = __float2half(acc[nf][3] * inv1);
        *(__half2*)&Ps[r0 * PS_STRIDE + j0] = p0;
        *(__half2*)&Ps[r1 * PS_STRIDE + j0] = p1;
    }
    __syncthreads();

    // ---- PV: 4 rows per 16-thread group; j-quads, FFMA2
    const int i0p = (tid >> 4) << 2;
    const int c0  = (tid & 15) << 2;
    unsigned long long o2[4][2];
#pragma unroll
    for (int ii = 0; ii < 4; ii++) { o2[ii][0] = 0ull; o2[ii][1] = 0ull; }

    const int jlim = (i0p + 68 < WIN) ? (i0p + 68) : WIN;
#pragma unroll 1
    for (int j = 0; j < jlim; j += 4) {
        ulonglong2 va = *(const ulonglong2*)&vs[(j + 0) * VS_STRIDE + c0];
        ulonglong2 vb = *(const ulonglong2*)&vs[(j + 1) * VS_STRIDE + c0];
        ulonglong2 vc = *(const ulonglong2*)&vs[(j + 2) * VS_STRIDE + c0];
        ulonglong2 vd = *(const ulonglong2*)&vs[(j + 3) * VS_STRIDE + c0];
#pragma unroll
        for (int ii = 0; ii < 4; ii++) {
            uint2 pq = *(const uint2*)&Ps[(i0p + ii) * PS_STRIDE + j];
            float2 p01 = __half22float2(*reinterpret_cast<__half2*>(&pq.x));
            float2 p23 = __half22float2(*reinterpret_cast<__half2*>(&pq.y));
            unsigned long long px = pack2(p01.x, p01.x);
            unsigned long long py = pack2(p01.y, p01.y);
            unsigned long long pz = pack2(p23.x, p23.x);
            unsigned long long pw = pack2(p23.y, p23.y);
            fma2(o2[ii][0], px, va.x); fma2(o2[ii][1], px, va.y);
            fma2(o2[ii][0], py, vb.x); fma2(o2[ii][1], py, vb.y);
            fma2(o2[ii][0], pz, vc.x); fma2(o2[ii][1], pz, vc.y);
            fma2(o2[ii][0], pw, vd.x); fma2(o2[ii][1], pw, vd.y);
        }
    }
#pragma unroll
    for (int ii = 0; ii < 4; ii++) {
        float o0, o1, o2f, o3;
        unpack2(o2[ii][0], o0, o1);
        unpack2(o2[ii][1], o2f, o3);
        const size_t oidx = rowbase + (size_t)(n * BS + i0p + ii) * CH + c0;
        __half h0 = __float2half(o0);
        __half h1 = __float2half(o1);
        __half h2 = __float2half(o2f);
        __half h3 = __float2half(o3);
        __half2 hp0; hp0.x = h0; hp0.y = h1;
        __half2 hp1; hp1.x = h2; hp1.y = h3;
        __half2 lp0, lp1;
        lp0.x = __float2half(o0 - __half2float(h0));
        lp0.y = __float2half(o1 - __half2float(h1));
        lp1.x = __float2half(o2f - __half2float(h2));
        lp1.y = __float2half(o3 - __half2float(h3));
        *(__half2*)(Ohi + oidx)     = hp0;
        *(__half2*)(Ohi + oidx + 2) = hp1;
        *(__half2*)(Olo + oidx)     = lp0;
        *(__half2*)(Olo + oidx + 2) = lp1;
    }
}

// ---------------------------------------------------------------------------
extern "C" void kernel_launch(void* const* d_in, const int* in_sizes, int n_in,
                              void* d_out, int out_size)
{
    const float* x  = (const float*)d_in[0];
    const float* Wq = (const float*)d_in[1];
    const float* bq = (const float*)d_in[2];
    const float* Wk = (const float*)d_in[3];
    const float* bk = (const float*)d_in[4];
    const float* Wv = (const float*)d_in[5];
    const float* bv = (const float*)d_in[6];
    const float* Wo = (const float*)d_in[7];
    const float* bo = (const float*)d_in[8];
    float* out = (float*)d_out;

    float *vp;
    __half *qh, *ql, *kh, *ahi, *alo, *phi, *plo, *whi;
    cudaGetSymbolAddress((void**)&vp,  g_V);
    cudaGetSymbolAddress((void**)&qh,  g_Qh);
    cudaGetSymbolAddress((void**)&ql,  g_Ql);
    cudaGetSymbolAddress((void**)&kh,  g_Kh);
    cudaGetSymbolAddress((void**)&ahi, g_Ahi);
    cudaGetSymbolAddress((void**)&alo, g_Alo);
    cudaGetSymbolAddress((void**)&phi, g_Phi);
    cudaGetSymbolAddress((void**)&plo, g_Plo);
    cudaGetSymbolAddress((void**)&whi, g_Whi);

    cudaFuncSetAttribute(attn_kernel,
                         cudaFuncAttributeMaxDynamicSharedMemorySize, ATTN_SMEM_BYTES);
    cudaFuncSetAttribute(gemm_hmma,
                         cudaFuncAttributeMaxDynamicSharedMemorySize, HGEMM_SMEM);
    cudaFuncSetAttribute(gemm_qkv,
                         cudaFuncAttributeMaxDynamicSharedMemorySize, HGEMM_SMEM);

    const int NX = MROWS * CH;
    const int NW = CH * CH;

    split_f16<<<NX / 2048, 256>>>(x, ahi, alo, NX);
    to_f16_w4<<<2048, 256>>>(Wq, Wk, Wv, Wo, whi);

    gemm_qkv<<<dim3(24, MROWS / 128), 256, HGEMM_SMEM>>>(
        ahi, alo, whi, bq, bk, bv, qh, ql, kh, vp);

    attn_kernel<<<dim3(NB, NH, BATCH), 256, ATTN_SMEM_BYTES>>>(
        qh, ql, kh, vp, phi, plo);

    gemm_hmma<<<dim3(8, MROWS / 128), 256, HGEMM_SMEM>>>(
        phi, plo, whi + 3 * (size_t)NW, bo, out);
}

// round 14
// speedup vs baseline: 1.5948x; 1.3518x over previous
#include <cuda_runtime.h>
#include <cuda_fp16.h>
#include <cstdint>

#define BATCH 4
#define SEQ   4096
#define CH    1024
#define NH    16
#define HD    64
#define BS    64
#define NB    (SEQ / BS)          // 64
#define MROWS (BATCH * SEQ)       // 16384

// ---------------- scratch (device globals: allocation-free) ----------------
__device__ float  g_V [(size_t)MROWS * CH];
__device__ __half g_Qh[(size_t)MROWS * CH];
__device__ __half g_Ql[(size_t)MROWS * CH];
__device__ __half g_Kh[(size_t)MROWS * CH];
__device__ __half g_Ahi[(size_t)MROWS * CH];
__device__ __half g_Phi[(size_t)MROWS * CH];
__device__ __half g_Plo[(size_t)MROWS * CH];
__device__ __half g_Whi[(size_t)4 * CH * CH];

// =================== helpers ===================
__device__ __forceinline__ uint32_t smem_u32(const void* p) {
    uint32_t a;
    asm("{ .reg .u64 t; cvta.to.shared.u64 t, %1; cvt.u32.u64 %0, t; }"
        : "=r"(a) : "l"(p));
    return a;
}
__device__ __forceinline__ void cp16(uint32_t dst, const void* src) {
    asm volatile("cp.async.cg.shared.global [%0], [%1], 16;" :: "r"(dst), "l"(src));
}
__device__ __forceinline__ void cp_commit() {
    asm volatile("cp.async.commit_group;" ::: "memory");
}
template <int N>
__device__ __forceinline__ void cp_wait() {
    asm volatile("cp.async.wait_group %0;" :: "n"(N) : "memory");
}
__device__ __forceinline__ void ldsm4(uint32_t& r0, uint32_t& r1, uint32_t& r2,
                                      uint32_t& r3, uint32_t addr) {
    asm volatile("ldmatrix.sync.aligned.m8n8.x4.shared.b16 {%0,%1,%2,%3}, [%4];"
                 : "=r"(r0), "=r"(r1), "=r"(r2), "=r"(r3) : "r"(addr));
}
__device__ __forceinline__ void mma16816(float* c, const uint32_t* a,
                                         uint32_t b0, uint32_t b1) {
    asm volatile(
        "mma.sync.aligned.m16n8k16.row.col.f32.f16.f16.f32 "
        "{%0,%1,%2,%3}, {%4,%5,%6,%7}, {%8,%9}, {%0,%1,%2,%3};"
        : "+f"(c[0]), "+f"(c[1]), "+f"(c[2]), "+f"(c[3])
        : "r"(a[0]), "r"(a[1]), "r"(a[2]), "r"(a[3]), "r"(b0), "r"(b1));
}
// ---- packed f32x2 (FFMA2) helpers ----
__device__ __forceinline__ unsigned long long pack2(float x, float y) {
    unsigned long long r;
    asm("mov.b64 %0, {%1, %2};" : "=l"(r) : "f"(x), "f"(y));
    return r;
}
__device__ __forceinline__ void unpack2(unsigned long long v, float& x, float& y) {
    asm("mov.b64 {%0, %1}, %2;" : "=f"(x), "=f"(y) : "l"(v));
}
__device__ __forceinline__ void fma2(unsigned long long& d, unsigned long long a,
                                     unsigned long long b) {
    asm("fma.rn.f32x2 %0, %1, %2, %0;" : "+l"(d) : "l"(a), "l"(b));
}

// =================== fp32 -> fp16 converters (8 elems, 16B stores) =========
__global__ __launch_bounds__(256) void to_f16_x(
    const float* __restrict__ in, __half* __restrict__ hi)
{
    int i = (blockIdx.x * 256 + threadIdx.x) * 8;
    float4 v0 = *(const float4*)(in + i);
    float4 v1 = *(const float4*)(in + i + 4);
    __half2 hp[4];
    hp[0].x = __float2half(v0.x); hp[0].y = __float2half(v0.y);
    hp[1].x = __float2half(v0.z); hp[1].y = __float2half(v0.w);
    hp[2].x = __float2half(v1.x); hp[2].y = __float2half(v1.y);
    hp[3].x = __float2half(v1.z); hp[3].y = __float2half(v1.w);
    *(uint4*)(hi + i) = *(uint4*)hp;
}
__global__ __launch_bounds__(256) void to_f16_w4(
    const float* __restrict__ w0, const float* __restrict__ w1,
    const float* __restrict__ w2, const float* __restrict__ w3,
    __half* __restrict__ hi)
{
    const int seg = blockIdx.x >> 9;
    const int loc = (int)(blockIdx.x & 511) * 2048 + threadIdx.x * 8;
    const float* in = (seg == 0) ? w0 : (seg == 1) ? w1 : (seg == 2) ? w2 : w3;
    float4 v0 = *(const float4*)(in + loc);
    float4 v1 = *(const float4*)(in + loc + 4);
    __half2 hp[4];
    hp[0].x = __float2half(v0.x); hp[0].y = __float2half(v0.y);
    hp[1].x = __float2half(v0.z); hp[1].y = __float2half(v0.w);
    hp[2].x = __float2half(v1.x); hp[2].y = __float2half(v1.y);
    hp[3].x = __float2half(v1.z); hp[3].y = __float2half(v1.w);
    *(uint4*)(hi + (size_t)seg * CH * CH + loc) = *(uint4*)hp;
}

// =================== HMMA GEMM core (BM=BN=128, BK=32, 8 warps) =============
#define BKH 32
#define NKC (CH / BKH)            // 32
#define HT_BYTES 8192

__device__ __forceinline__ uint32_t sw_off(int row, int chunk) {
    return (uint32_t)(row * 64 + ((chunk ^ ((row >> 1) & 3)) << 4));
}

// MODE 0: fp32 Out; MODE 1: fp16 hi/lo; MODE 2: fp16 hi only
// AMODE 0: A = hi+lo (2 MMAs); AMODE 1: A = hi only (1 MMA)
template <int MODE, int AMODE>
__device__ __forceinline__ void gemm_body(
    const __half* __restrict__ Ahi_t, const __half* __restrict__ Alo_t,
    const __half* __restrict__ Bh_t,
    const float* __restrict__ bias,
    float* __restrict__ OutF, __half* __restrict__ OutH, __half* __restrict__ OutL,
    int bm, int bn, char* dsm)
{
    constexpr int NBUF  = (AMODE == 0) ? 3 : 2;
    constexpr int STAGE = NBUF * HT_BYTES;

    const uint32_t base = smem_u32(dsm);
    const int tid  = threadIdx.x;
    const int wid  = tid >> 5;
    const int lane = tid & 31;
    const int wm = (wid & 3) * 32;
    const int wn = (wid >> 2) * 64;

    const __half* srcs[3] = { Ahi_t, (AMODE == 0) ? Alo_t : Bh_t, Bh_t };

    auto load_stage = [&](int st, int kc) {
        const uint32_t sb = base + st * STAGE;
#pragma unroll
        for (int p = 0; p < 2 * NBUF; p++) {
            int idx = p * 256 + tid;
            int buf = idx >> 9;            // 0..NBUF-1
            int rem = idx & 511;
            int row = rem >> 2;
            int ch  = rem & 3;
            const __half* s = srcs[buf] + (size_t)row * CH + kc * BKH + ch * 8;
            cp16(sb + buf * HT_BYTES + sw_off(row, ch), s);
        }
        cp_commit();
    };

    float acc[2][8][4];
#pragma unroll
    for (int mi = 0; mi < 2; mi++)
#pragma unroll
        for (int ni = 0; ni < 8; ni++)
#pragma unroll
            for (int t = 0; t < 4; t++) acc[mi][ni][t] = 0.0f;

    load_stage(0, 0);
    load_stage(1, 1);

    const int lr = lane & 15;
    const int lc = lane >> 4;

    for (int kc = 0; kc < NKC; kc++) {
        if (kc < NKC - 1) cp_wait<1>(); else cp_wait<0>();
        __syncthreads();

        const uint32_t sb = base + (kc % 3) * STAGE;
        const uint32_t aHib = sb;
        const uint32_t aLob = sb + HT_BYTES;
        const uint32_t bHib = sb + (NBUF - 1) * HT_BYTES;

#pragma unroll
        for (int ks = 0; ks < 2; ks++) {
            const int chnk = ks * 2 + lc;
            uint32_t ah[2][4], al[2][4], bh[4][4];
#pragma unroll
            for (int mi = 0; mi < 2; mi++) {
                uint32_t off = sw_off(wm + mi * 16 + lr, chnk);
                ldsm4(ah[mi][0], ah[mi][1], ah[mi][2], ah[mi][3], aHib + off);
                if (AMODE == 0)
                    ldsm4(al[mi][0], al[mi][1], al[mi][2], al[mi][3], aLob + off);
            }
#pragma unroll
            for (int g = 0; g < 4; g++) {
                uint32_t off = sw_off(wn + g * 16 + lr, chnk);
                ldsm4(bh[g][0], bh[g][1], bh[g][2], bh[g][3], bHib + off);
            }
#pragma unroll
            for (int mi = 0; mi < 2; mi++)
#pragma unroll
                for (int ni = 0; ni < 8; ni++) {
                    const int g = ni >> 1, w = ni & 1;
                    mma16816(acc[mi][ni], ah[mi], bh[g][w], bh[g][w + 2]);
                    if (AMODE == 0)
                        mma16816(acc[mi][ni], al[mi], bh[g][w], bh[g][w + 2]);
                }
        }
        if (kc + 2 < NKC) load_stage((kc + 2) % 3, kc + 2);
    }

#pragma unroll
    for (int mi = 0; mi < 2; mi++) {
        const int r0 = bm + wm + mi * 16 + (lane >> 2);
#pragma unroll
        for (int ni = 0; ni < 8; ni++) {
            const int c = bn + wn + ni * 8 + (lane & 3) * 2;
            const float b0 = bias[c], b1 = bias[c + 1];
            float q0 = acc[mi][ni][0] + b0, q1 = acc[mi][ni][1] + b1;
            float q2 = acc[mi][ni][2] + b0, q3 = acc[mi][ni][3] + b1;
            if (MODE == 0) {
                *(float2*)(OutF + (size_t)r0 * CH + c)       = make_float2(q0, q1);
                *(float2*)(OutF + (size_t)(r0 + 8) * CH + c) = make_float2(q2, q3);
            } else {
                __half2 h01, h23;
                h01.x = __float2half(q0); h01.y = __float2half(q1);
                h23.x = __float2half(q2); h23.y = __float2half(q3);
                *(__half2*)(OutH + (size_t)r0 * CH + c)       = h01;
                *(__half2*)(OutH + (size_t)(r0 + 8) * CH + c) = h23;
                if (MODE == 1) {
                    __half2 l01, l23;
                    l01.x = __float2half(q0 - __half2float(h01.x));
                    l01.y = __float2half(q1 - __half2float(h01.y));
                    l23.x = __float2half(q2 - __half2float(h23.x));
                    l23.y = __float2half(q3 - __half2float(h23.y));
                    *(__half2*)(OutL + (size_t)r0 * CH + c)       = l01;
                    *(__half2*)(OutL + (size_t)(r0 + 8) * CH + c) = l23;
                }
            }
        }
    }
}

#define QKV_SMEM (3 * 2 * HT_BYTES)   // 49152
#define OUT_SMEM (3 * 3 * HT_BYTES)   // 73728

// fused QKV GEMM (A = x hi only): Q -> fp16 hi/lo, K -> fp16 hi, V -> fp32
__global__ __launch_bounds__(256, 2) void gemm_qkv(
    const __half* __restrict__ Ahi, const __half* __restrict__ Wall,
    const float* __restrict__ bq, const float* __restrict__ bk,
    const float* __restrict__ bv,
    __half* __restrict__ Qh, __half* __restrict__ Ql,
    __half* __restrict__ Kh, float* __restrict__ Vf)
{
    extern __shared__ char dsm[];
    const int bng = blockIdx.x * 128;
    const int sel = bng >> 10;
    const int bn  = bng & 1023;
    const int bm  = blockIdx.y * 128;
    const __half* Bh = Wall + (size_t)sel * CH * CH + (size_t)bn * CH;
    const __half* Ah = Ahi + (size_t)bm * CH;
    if (sel == 0)
        gemm_body<1, 1>(Ah, nullptr, Bh, bq, nullptr, Qh, Ql, bm, bn, dsm);
    else if (sel == 1)
        gemm_body<2, 1>(Ah, nullptr, Bh, bk, nullptr, Kh, nullptr, bm, bn, dsm);
    else
        gemm_body<0, 1>(Ah, nullptr, Bh, bv, Vf, nullptr, nullptr, bm, bn, dsm);
}

// output projection (A = attention out, hi+lo)
__global__ __launch_bounds__(256, 2) void gemm_hmma(
    const __half* __restrict__ Ahi, const __half* __restrict__ Alo,
    const __half* __restrict__ Bh,
    const float* __restrict__ bias, float* __restrict__ Out)
{
    extern __shared__ char dsm[];
    const int bm = blockIdx.y * 128;
    const int bn = blockIdx.x * 128;
    gemm_body<0, 0>(Ahi + (size_t)bm * CH, Alo + (size_t)bm * CH,
                    Bh + (size_t)bn * CH, bias, Out, nullptr, nullptr, bm, bn, dsm);
}

// ---------------- attention: HMMA scores + FFMA2 PV ------------------------
#define A_QH 0
#define A_QL 8192
#define A_KH 16896
#define A_VS 33280
#define A_RED 68096
#define PS_STRIDE 132
#define VS_STRIDE 68
#define WIN 128
#define ATTN_SMEM_BYTES 69120

__global__ __launch_bounds__(256, 3) void attn_kernel(
    const __half* __restrict__ Qh, const __half* __restrict__ Ql,
    const __half* __restrict__ Kh, const float* __restrict__ V,
    __half* __restrict__ Ohi, __half* __restrict__ Olo)
{
    extern __shared__ char dsm[];
    const uint32_t sbase = smem_u32(dsm);
    float*  vs   = (float*)(dsm + A_VS);
    __half* Ps   = (__half*)(dsm + 0);
    float*  maxb = (float*)(dsm + A_RED);
    float*  sumb = maxb + 128;

    const int tid  = threadIdx.x;
    const int warp = tid >> 5;
    const int lane = tid & 31;
    const int n = blockIdx.x;
    const int h = blockIdx.y;
    const int b = blockIdx.z;
    const size_t rowbase = (size_t)b * SEQ * CH + (size_t)h * HD;

#pragma unroll
    for (int p = 0; p < 2; p++) {
        int idx = tid + p * 256;
        int i  = idx >> 3;
        int ch = idx & 7;
        int kc = ch >> 2, cc = ch & 3;
        const __half* sh = Qh + rowbase + (size_t)(n * BS + i) * CH + ch * 8;
        const __half* sl = Ql + rowbase + (size_t)(n * BS + i) * CH + ch * 8;
        cp16(sbase + A_QH + kc * 4096 + sw_off(i, cc), sh);
        cp16(sbase + A_QL + kc * 4096 + sw_off(i, cc), sl);
    }
#pragma unroll
    for (int p = 0; p < 4; p++) {
        int idx = tid + p * 256;
        int j  = idx >> 3;
        int ch = idx & 7;
        int kc = ch >> 2, cc = ch & 3;
        int kpos = (n - 1) * BS + j;
        uint32_t off = A_KH + kc * 8192 + sw_off(j, cc);
        if (kpos >= 0)
            cp16(sbase + off, Kh + rowbase + (size_t)kpos * CH + ch * 8);
        else
            *(uint4*)(dsm + off) = make_uint4(0, 0, 0, 0);
    }
    cp_commit();
#pragma unroll
    for (int p = 0; p < 8; p++) {
        int idx = tid + p * 256;
        int j   = idx >> 4;
        int dd0 = (idx & 15) << 2;
        int kpos = (n - 1) * BS + j;
        float4 v4 = make_float4(0.f, 0.f, 0.f, 0.f);
        if (kpos >= 0)
            v4 = *(const float4*)(V + rowbase + (size_t)kpos * CH + dd0);
        *(float4*)&vs[j * VS_STRIDE + dd0] = v4;
    }
    cp_wait<0>();
    __syncthreads();

    const int wm = (warp & 3) * 16;
    const int wn = (warp >> 2) * 64;
    const int wh = warp >> 2;
    const int lr = lane & 15;
    const int lc = lane >> 4;

    float acc[8][4];
#pragma unroll
    for (int nf = 0; nf < 8; nf++)
#pragma unroll
        for (int t = 0; t < 4; t++) acc[nf][t] = 0.0f;

#pragma unroll
    for (int kc = 0; kc < 2; kc++)
#pragma unroll
        for (int ks = 0; ks < 2; ks++) {
            const int chnk = ks * 2 + lc;
            uint32_t ah[4], al[4], bh[4][4];
            uint32_t qoff = sw_off(wm + lr, chnk);
            ldsm4(ah[0], ah[1], ah[2], ah[3], sbase + A_QH + kc * 4096 + qoff);
            ldsm4(al[0], al[1], al[2], al[3], sbase + A_QL + kc * 4096 + qoff);
#pragma unroll
            for (int g = 0; g < 4; g++) {
                uint32_t off = sw_off(wn + g * 16 + lr, chnk);
                ldsm4(bh[g][0], bh[g][1], bh[g][2], bh[g][3],
                      sbase + A_KH + kc * 8192 + off);
            }
#pragma unroll
            for (int nf = 0; nf < 8; nf++) {
                const int g = nf >> 1, w = nf & 1;
                mma16816(acc[nf], ah, bh[g][w], bh[g][w + 2]);
                mma16816(acc[nf], al, bh[g][w], bh[g][w + 2]);
            }
        }

    const float scale = 0.125f;
    const int r0 = wm + (lane >> 2);
    const int r1 = r0 + 8;
    float rm0 = -1e30f, rm1 = -1e30f;
#pragma unroll
    for (int nf = 0; nf < 8; nf++) {
        const int j0 = wn + nf * 8 + ((lane & 3) << 1);
        const int j1 = j0 + 1;
        bool w0 = (n > 0 || j0 >= BS);
        bool w1 = (n > 0 || j1 >= BS);
        acc[nf][0] = (w0 && j0 <= r0 + BS) ? acc[nf][0] * scale : -1e30f;
        acc[nf][1] = (w1 && j1 <= r0 + BS) ? acc[nf][1] * scale : -1e30f;
        acc[nf][2] = (w0 && j0 <= r1 + BS) ? acc[nf][2] * scale : -1e30f;
        acc[nf][3] = (w1 && j1 <= r1 + BS) ? acc[nf][3] * scale : -1e30f;
        rm0 = fmaxf(rm0, fmaxf(acc[nf][0], acc[nf][1]));
        rm1 = fmaxf(rm1, fmaxf(acc[nf][2], acc[nf][3]));
    }
    rm0 = fmaxf(rm0, __shfl_xor_sync(0xffffffffu, rm0, 1));
    rm0 = fmaxf(rm0, __shfl_xor_sync(0xffffffffu, rm0, 2));
    rm1 = fmaxf(rm1, __shfl_xor_sync(0xffffffffu, rm1, 1));
    rm1 = fmaxf(rm1, __shfl_xor_sync(0xffffffffu, rm1, 2));
    if ((lane & 3) == 0) {
        maxb[wh * 64 + r0] = rm0;
        maxb[wh * 64 + r1] = rm1;
    }
    __syncthreads();
    const float m0 = fmaxf(maxb[r0], maxb[64 + r0]);
    const float m1 = fmaxf(maxb[r1], maxb[64 + r1]);

    float s0 = 0.f, s1 = 0.f;
#pragma unroll
    for (int nf = 0; nf < 8; nf++) {
        acc[nf][0] = __expf(acc[nf][0] - m0);
        acc[nf][1] = __expf(acc[nf][1] - m0);
        acc[nf][2] = __expf(acc[nf][2] - m1);
        acc[nf][3] = __expf(acc[nf][3] - m1);
        s0 += acc[nf][0] + acc[nf][1];
        s1 += acc[nf][2] + acc[nf][3];
    }
    s0 += __shfl_xor_sync(0xffffffffu, s0, 1);
    s0 += __shfl_xor_sync(0xffffffffu, s0, 2);
    s1 += __shfl_xor_sync(0xffffffffu, s1, 1);
    s1 += __shfl_xor_sync(0xffffffffu, s1, 2);
    if ((lane & 3) == 0) {
        sumb[wh * 64 + r0] = s0;
        sumb[wh * 64 + r1] = s1;
    }
    __syncthreads();
    const float inv0 = 1.0f / (sumb[r0] + sumb[64 + r0]);
    const float inv1 = 1.0f / (sumb[r1] + sumb[64 + r1]);

#pragma unroll
    for (int nf = 0; nf < 8; nf++) {
        const int j0 = wn + nf * 8 + ((lane & 3) << 1);
        __half2 p0, p1;
        p0.x = __float2half(acc[nf][0] * inv0);
        p0.y = __float2half(acc[nf][1] * inv0);
        p1.x = __float2half(acc[nf][2] * inv1);
        p1.y = __float2half(acc[nf][3] * inv1);
        *(__half2*)&Ps[r0 * PS_STRIDE + j0] = p0;
        *(__half2*)&Ps[r1 * PS_STRIDE + j0] = p1;
    }
    __syncthreads();

    const int i0p = (tid >> 4) << 2;
    const int c0  = (tid & 15) << 2;
    unsigned long long o2[4][2];
#pragma unroll
    for (int ii = 0; ii < 4; ii++) { o2[ii][0] = 0ull; o2[ii][1] = 0ull; }

    const int jlim = (i0p + 68 < WIN) ? (i0p + 68) : WIN;
#pragma unroll 1
    for (int j = 0; j < jlim; j += 4) {
        ulonglong2 va = *(const ulonglong2*)&vs[(j + 0) * VS_STRIDE + c0];
        ulonglong2 vb = *(const ulonglong2*)&vs[(j + 1) * VS_STRIDE + c0];
        ulonglong2 vc = *(const ulonglong2*)&vs[(j + 2) * VS_STRIDE + c0];
        ulonglong2 vd = *(const ulonglong2*)&vs[(j + 3) * VS_STRIDE + c0];
#pragma unroll
        for (int ii = 0; ii < 4; ii++) {
            uint2 pq = *(const uint2*)&Ps[(i0p + ii) * PS_STRIDE + j];
            float2 p01 = __half22float2(*reinterpret_cast<__half2*>(&pq.x));
            float2 p23 = __half22float2(*reinterpret_cast<__half2*>(&pq.y));
            unsigned long long px = pack2(p01.x, p01.x);
            unsigned long long py = pack2(p01.y, p01.y);
            unsigned long long pz = pack2(p23.x, p23.x);
            unsigned long long pw = pack2(p23.y, p23.y);
            fma2(o2[ii][0], px, va.x); fma2(o2[ii][1], px, va.y);
            fma2(o2[ii][0], py, vb.x); fma2(o2[ii][1], py, vb.y);
            fma2(o2[ii][0], pz, vc.x); fma2(o2[ii][1], pz, vc.y);
            fma2(o2[ii][0], pw, vd.x); fma2(o2[ii][1], pw, vd.y);
        }
    }
#pragma unroll
    for (int ii = 0; ii < 4; ii++) {
        float o0, o1, o2f, o3;
        unpack2(o2[ii][0], o0, o1);
        unpack2(o2[ii][1], o2f, o3);
        const size_t oidx = rowbase + (size_t)(n * BS + i0p + ii) * CH + c0;
        __half h0 = __float2half(o0);
        __half h1 = __float2half(o1);
        __half h2 = __float2half(o2f);
        __half h3 = __float2half(o3);
        __half2 hp0; hp0.x = h0; hp0.y = h1;
        __half2 hp1; hp1.x = h2; hp1.y = h3;
        __half2 lp0, lp1;
        lp0.x = __float2half(o0 - __half2float(h0));
        lp0.y = __float2half(o1 - __half2float(h1));
        lp1.x = __float2half(o2f - __half2float(h2));
        lp1.y = __float2half(o3 - __half2float(h3));
        *(__half2*)(Ohi + oidx)     = hp0;
        *(__half2*)(Ohi + oidx + 2) = hp1;
        *(__half2*)(Olo + oidx)     = lp0;
        *(__half2*)(Olo + oidx + 2) = lp1;
    }
}

// ---------------------------------------------------------------------------
extern "C" void kernel_launch(void* const* d_in, const int* in_sizes, int n_in,
                              void* d_out, int out_size)
{
    const float* x  = (const float*)d_in[0];
    const float* Wq = (const float*)d_in[1];
    const float* bq = (const float*)d_in[2];
    const float* Wk = (const float*)d_in[3];
    const float* bk = (const float*)d_in[4];
    const float* Wv = (const float*)d_in[5];
    const float* bv = (const float*)d_in[6];
    const float* Wo = (const float*)d_in[7];
    const float* bo = (const float*)d_in[8];
    float* out = (float*)d_out;

    float *vp;
    __half *qh, *ql, *kh, *ahi, *phi, *plo, *whi;
    cudaGetSymbolAddress((void**)&vp,  g_V);
    cudaGetSymbolAddress((void**)&qh,  g_Qh);
    cudaGetSymbolAddress((void**)&ql,  g_Ql);
    cudaGetSymbolAddress((void**)&kh,  g_Kh);
    cudaGetSymbolAddress((void**)&ahi, g_Ahi);
    cudaGetSymbolAddress((void**)&phi, g_Phi);
    cudaGetSymbolAddress((void**)&plo, g_Plo);
    cudaGetSymbolAddress((void**)&whi, g_Whi);

    cudaFuncSetAttribute(attn_kernel,
                         cudaFuncAttributeMaxDynamicSharedMemorySize, ATTN_SMEM_BYTES);
    cudaFuncSetAttribute(gemm_hmma,
                         cudaFuncAttributeMaxDynamicSharedMemorySize, OUT_SMEM);
    cudaFuncSetAttribute(gemm_qkv,
                         cudaFuncAttributeMaxDynamicSharedMemorySize, QKV_SMEM);

    const int NX = MROWS * CH;
    const int NW = CH * CH;

    to_f16_x<<<NX / 2048, 256>>>(x, ahi);
    to_f16_w4<<<2048, 256>>>(Wq, Wk, Wv, Wo, whi);

    gemm_qkv<<<dim3(24, MROWS / 128), 256, QKV_SMEM>>>(
        ahi, whi, bq, bk, bv, qh, ql, kh, vp);

    attn_kernel<<<dim3(NB, NH, BATCH), 256, ATTN_SMEM_BYTES>>>(
        qh, ql, kh, vp, phi, plo);

    gemm_hmma<<<dim3(8, MROWS / 128), 256, OUT_SMEM>>>(
        phi, plo, whi + 3 * (size_t)NW, bo, out);
}

// round 15
// speedup vs baseline: 1.8082x; 1.1338x over previous
#include <cuda_runtime.h>
#include <cuda_fp16.h>
#include <cstdint>

#define BATCH 4
#define SEQ   4096
#define CH    1024
#define NH    16
#define HD    64
#define BS    64
#define NB    (SEQ / BS)          // 64
#define MROWS (BATCH * SEQ)       // 16384

// ---------------- scratch (device globals: allocation-free) ----------------
__device__ float  g_V [(size_t)MROWS * CH];
__device__ __half g_Qh[(size_t)MROWS * CH];
__device__ __half g_Ql[(size_t)MROWS * CH];
__device__ __half g_Kh[(size_t)MROWS * CH];
__device__ __half g_Ahi[(size_t)MROWS * CH];
__device__ __half g_Phi[(size_t)MROWS * CH];
__device__ __half g_Whi[(size_t)4 * CH * CH];

// =================== helpers ===================
__device__ __forceinline__ uint32_t smem_u32(const void* p) {
    uint32_t a;
    asm("{ .reg .u64 t; cvta.to.shared.u64 t, %1; cvt.u32.u64 %0, t; }"
        : "=r"(a) : "l"(p));
    return a;
}
__device__ __forceinline__ void cp16(uint32_t dst, const void* src) {
    asm volatile("cp.async.cg.shared.global [%0], [%1], 16;" :: "r"(dst), "l"(src));
}
__device__ __forceinline__ void cp_commit() {
    asm volatile("cp.async.commit_group;" ::: "memory");
}
template <int N>
__device__ __forceinline__ void cp_wait() {
    asm volatile("cp.async.wait_group %0;" :: "n"(N) : "memory");
}
__device__ __forceinline__ void ldsm4(uint32_t& r0, uint32_t& r1, uint32_t& r2,
                                      uint32_t& r3, uint32_t addr) {
    asm volatile("ldmatrix.sync.aligned.m8n8.x4.shared.b16 {%0,%1,%2,%3}, [%4];"
                 : "=r"(r0), "=r"(r1), "=r"(r2), "=r"(r3) : "r"(addr));
}
__device__ __forceinline__ void mma16816(float* c, const uint32_t* a,
                                         uint32_t b0, uint32_t b1) {
    asm volatile(
        "mma.sync.aligned.m16n8k16.row.col.f32.f16.f16.f32 "
        "{%0,%1,%2,%3}, {%4,%5,%6,%7}, {%8,%9}, {%0,%1,%2,%3};"
        : "+f"(c[0]), "+f"(c[1]), "+f"(c[2]), "+f"(c[3])
        : "r"(a[0]), "r"(a[1]), "r"(a[2]), "r"(a[3]), "r"(b0), "r"(b1));
}
// ---- packed f32x2 (FFMA2) helpers ----
__device__ __forceinline__ unsigned long long pack2(float x, float y) {
    unsigned long long r;
    asm("mov.b64 %0, {%1, %2};" : "=l"(r) : "f"(x), "f"(y));
    return r;
}
__device__ __forceinline__ void unpack2(unsigned long long v, float& x, float& y) {
    asm("mov.b64 {%0, %1}, %2;" : "=f"(x), "=f"(y) : "l"(v));
}
__device__ __forceinline__ void fma2(unsigned long long& d, unsigned long long a,
                                     unsigned long long b) {
    asm("fma.rn.f32x2 %0, %1, %2, %0;" : "+l"(d) : "l"(a), "l"(b));
}

// =================== fp32 -> fp16 converters (8 elems, 16B stores) =========
__global__ __launch_bounds__(256) void to_f16_x(
    const float* __restrict__ in, __half* __restrict__ hi)
{
    int i = (blockIdx.x * 256 + threadIdx.x) * 8;
    float4 v0 = *(const float4*)(in + i);
    float4 v1 = *(const float4*)(in + i + 4);
    __half2 hp[4];
    hp[0].x = __float2half(v0.x); hp[0].y = __float2half(v0.y);
    hp[1].x = __float2half(v0.z); hp[1].y = __float2half(v0.w);
    hp[2].x = __float2half(v1.x); hp[2].y = __float2half(v1.y);
    hp[3].x = __float2half(v1.z); hp[3].y = __float2half(v1.w);
    *(uint4*)(hi + i) = *(uint4*)hp;
}
__global__ __launch_bounds__(256) void to_f16_w4(
    const float* __restrict__ w0, const float* __restrict__ w1,
    const float* __restrict__ w2, const float* __restrict__ w3,
    __half* __restrict__ hi)
{
    const int seg = blockIdx.x >> 9;
    const int loc = (int)(blockIdx.x & 511) * 2048 + threadIdx.x * 8;
    const float* in = (seg == 0) ? w0 : (seg == 1) ? w1 : (seg == 2) ? w2 : w3;
    float4 v0 = *(const float4*)(in + loc);
    float4 v1 = *(const float4*)(in + loc + 4);
    __half2 hp[4];
    hp[0].x = __float2half(v0.x); hp[0].y = __float2half(v0.y);
    hp[1].x = __float2half(v0.z); hp[1].y = __float2half(v0.w);
    hp[2].x = __float2half(v1.x); hp[2].y = __float2half(v1.y);
    hp[3].x = __float2half(v1.z); hp[3].y = __float2half(v1.w);
    *(uint4*)(hi + (size_t)seg * CH * CH + loc) = *(uint4*)hp;
}

// =================== HMMA GEMM core (BM=BN=128, BK=32, 8 warps) =============
#define BKH 32
#define NKC (CH / BKH)            // 32
#define HT_BYTES 8192

__device__ __forceinline__ uint32_t sw_off(int row, int chunk) {
    return (uint32_t)(row * 64 + ((chunk ^ ((row >> 1) & 3)) << 4));
}

// MODE 0: fp32 Out; MODE 1: fp16 hi/lo; MODE 2: fp16 hi only
// AMODE 0: A = hi+lo (2 MMAs); AMODE 1: A = hi only (1 MMA)
template <int MODE, int AMODE>
__device__ __forceinline__ void gemm_body(
    const __half* __restrict__ Ahi_t, const __half* __restrict__ Alo_t,
    const __half* __restrict__ Bh_t,
    const float* __restrict__ bias,
    float* __restrict__ OutF, __half* __restrict__ OutH, __half* __restrict__ OutL,
    int bm, int bn, char* dsm)
{
    constexpr int NBUF  = (AMODE == 0) ? 3 : 2;
    constexpr int STAGE = NBUF * HT_BYTES;

    const uint32_t base = smem_u32(dsm);
    const int tid  = threadIdx.x;
    const int wid  = tid >> 5;
    const int lane = tid & 31;
    const int wm = (wid & 3) * 32;
    const int wn = (wid >> 2) * 64;

    const __half* srcs[3] = { Ahi_t, (AMODE == 0) ? Alo_t : Bh_t, Bh_t };

    auto load_stage = [&](int st, int kc) {
        const uint32_t sb = base + st * STAGE;
#pragma unroll
        for (int p = 0; p < 2 * NBUF; p++) {
            int idx = p * 256 + tid;
            int buf = idx >> 9;
            int rem = idx & 511;
            int row = rem >> 2;
            int ch  = rem & 3;
            const __half* s = srcs[buf] + (size_t)row * CH + kc * BKH + ch * 8;
            cp16(sb + buf * HT_BYTES + sw_off(row, ch), s);
        }
        cp_commit();
    };

    float acc[2][8][4];
#pragma unroll
    for (int mi = 0; mi < 2; mi++)
#pragma unroll
        for (int ni = 0; ni < 8; ni++)
#pragma unroll
            for (int t = 0; t < 4; t++) acc[mi][ni][t] = 0.0f;

    load_stage(0, 0);
    load_stage(1, 1);

    const int lr = lane & 15;
    const int lc = lane >> 4;

    for (int kc = 0; kc < NKC; kc++) {
        if (kc < NKC - 1) cp_wait<1>(); else cp_wait<0>();
        __syncthreads();

        const uint32_t sb = base + (kc % 3) * STAGE;
        const uint32_t aHib = sb;
        const uint32_t aLob = sb + HT_BYTES;
        const uint32_t bHib = sb + (NBUF - 1) * HT_BYTES;

#pragma unroll
        for (int ks = 0; ks < 2; ks++) {
            const int chnk = ks * 2 + lc;
            uint32_t ah[2][4], al[2][4], bh[4][4];
#pragma unroll
            for (int mi = 0; mi < 2; mi++) {
                uint32_t off = sw_off(wm + mi * 16 + lr, chnk);
                ldsm4(ah[mi][0], ah[mi][1], ah[mi][2], ah[mi][3], aHib + off);
                if (AMODE == 0)
                    ldsm4(al[mi][0], al[mi][1], al[mi][2], al[mi][3], aLob + off);
            }
#pragma unroll
            for (int g = 0; g < 4; g++) {
                uint32_t off = sw_off(wn + g * 16 + lr, chnk);
                ldsm4(bh[g][0], bh[g][1], bh[g][2], bh[g][3], bHib + off);
            }
#pragma unroll
            for (int mi = 0; mi < 2; mi++)
#pragma unroll
                for (int ni = 0; ni < 8; ni++) {
                    const int g = ni >> 1, w = ni & 1;
                    mma16816(acc[mi][ni], ah[mi], bh[g][w], bh[g][w + 2]);
                    if (AMODE == 0)
                        mma16816(acc[mi][ni], al[mi], bh[g][w], bh[g][w + 2]);
                }
        }
        if (kc + 2 < NKC) load_stage((kc + 2) % 3, kc + 2);
    }

#pragma unroll
    for (int mi = 0; mi < 2; mi++) {
        const int r0 = bm + wm + mi * 16 + (lane >> 2);
#pragma unroll
        for (int ni = 0; ni < 8; ni++) {
            const int c = bn + wn + ni * 8 + (lane & 3) * 2;
            const float b0 = bias[c], b1 = bias[c + 1];
            float q0 = acc[mi][ni][0] + b0, q1 = acc[mi][ni][1] + b1;
            float q2 = acc[mi][ni][2] + b0, q3 = acc[mi][ni][3] + b1;
            if (MODE == 0) {
                *(float2*)(OutF + (size_t)r0 * CH + c)       = make_float2(q0, q1);
                *(float2*)(OutF + (size_t)(r0 + 8) * CH + c) = make_float2(q2, q3);
            } else {
                __half2 h01, h23;
                h01.x = __float2half(q0); h01.y = __float2half(q1);
                h23.x = __float2half(q2); h23.y = __float2half(q3);
                *(__half2*)(OutH + (size_t)r0 * CH + c)       = h01;
                *(__half2*)(OutH + (size_t)(r0 + 8) * CH + c) = h23;
                if (MODE == 1) {
                    __half2 l01, l23;
                    l01.x = __float2half(q0 - __half2float(h01.x));
                    l01.y = __float2half(q1 - __half2float(h01.y));
                    l23.x = __float2half(q2 - __half2float(h23.x));
                    l23.y = __float2half(q3 - __half2float(h23.y));
                    *(__half2*)(OutL + (size_t)r0 * CH + c)       = l01;
                    *(__half2*)(OutL + (size_t)(r0 + 8) * CH + c) = l23;
                }
            }
        }
    }
}

#define QKV_SMEM (3 * 2 * HT_BYTES)   // 49152

// fused QKV GEMM (A = x hi only): Q -> fp16 hi/lo, K -> fp16 hi, V -> fp32
__global__ __launch_bounds__(256, 2) void gemm_qkv(
    const __half* __restrict__ Ahi, const __half* __restrict__ Wall,
    const float* __restrict__ bq, const float* __restrict__ bk,
    const float* __restrict__ bv,
    __half* __restrict__ Qh, __half* __restrict__ Ql,
    __half* __restrict__ Kh, float* __restrict__ Vf)
{
    extern __shared__ char dsm[];
    const int bng = blockIdx.x * 128;
    const int sel = bng >> 10;
    const int bn  = bng & 1023;
    const int bm  = blockIdx.y * 128;
    const __half* Bh = Wall + (size_t)sel * CH * CH + (size_t)bn * CH;
    const __half* Ah = Ahi + (size_t)bm * CH;
    if (sel == 0)
        gemm_body<1, 1>(Ah, nullptr, Bh, bq, nullptr, Qh, Ql, bm, bn, dsm);
    else if (sel == 1)
        gemm_body<2, 1>(Ah, nullptr, Bh, bk, nullptr, Kh, nullptr, bm, bn, dsm);
    else
        gemm_body<0, 1>(Ah, nullptr, Bh, bv, Vf, nullptr, nullptr, bm, bn, dsm);
}

// output projection (A = attention out, hi only)
__global__ __launch_bounds__(256, 2) void gemm_out(
    const __half* __restrict__ Ahi, const __half* __restrict__ Bh,
    const float* __restrict__ bias, float* __restrict__ Out)
{
    extern __shared__ char dsm[];
    const int bm = blockIdx.y * 128;
    const int bn = blockIdx.x * 128;
    gemm_body<0, 1>(Ahi + (size_t)bm * CH, nullptr,
                    Bh + (size_t)bn * CH, bias, Out, nullptr, nullptr, bm, bn, dsm);
}

// ---------------- attention: HMMA scores + FFMA2 PV ------------------------
#define A_QH 0
#define A_QL 8192
#define A_KH 16896
#define A_VS 33280
#define A_RED 68096
#define PS_STRIDE 132
#define VS_STRIDE 68
#define WIN 128
#define ATTN_SMEM_BYTES 69120

__global__ __launch_bounds__(256, 3) void attn_kernel(
    const __half* __restrict__ Qh, const __half* __restrict__ Ql,
    const __half* __restrict__ Kh, const float* __restrict__ V,
    __half* __restrict__ Ohi)
{
    extern __shared__ char dsm[];
    const uint32_t sbase = smem_u32(dsm);
    float*  vs   = (float*)(dsm + A_VS);
    __half* Ps   = (__half*)(dsm + 0);
    float*  maxb = (float*)(dsm + A_RED);
    float*  sumb = maxb + 128;

    const int tid  = threadIdx.x;
    const int warp = tid >> 5;
    const int lane = tid & 31;
    const int n = blockIdx.x;
    const int h = blockIdx.y;
    const int b = blockIdx.z;
    const size_t rowbase = (size_t)b * SEQ * CH + (size_t)h * HD;

#pragma unroll
    for (int p = 0; p < 2; p++) {
        int idx = tid + p * 256;
        int i  = idx >> 3;
        int ch = idx & 7;
        int kc = ch >> 2, cc = ch & 3;
        const __half* sh = Qh + rowbase + (size_t)(n * BS + i) * CH + ch * 8;
        const __half* sl = Ql + rowbase + (size_t)(n * BS + i) * CH + ch * 8;
        cp16(sbase + A_QH + kc * 4096 + sw_off(i, cc), sh);
        cp16(sbase + A_QL + kc * 4096 + sw_off(i, cc), sl);
    }
#pragma unroll
    for (int p = 0; p < 4; p++) {
        int idx = tid + p * 256;
        int j  = idx >> 3;
        int ch = idx & 7;
        int kc = ch >> 2, cc = ch & 3;
        int kpos = (n - 1) * BS + j;
        uint32_t off = A_KH + kc * 8192 + sw_off(j, cc);
        if (kpos >= 0)
            cp16(sbase + off, Kh + rowbase + (size_t)kpos * CH + ch * 8);
        else
            *(uint4*)(dsm + off) = make_uint4(0, 0, 0, 0);
    }
    cp_commit();
#pragma unroll
    for (int p = 0; p < 8; p++) {
        int idx = tid + p * 256;
        int j   = idx >> 4;
        int dd0 = (idx & 15) << 2;
        int kpos = (n - 1) * BS + j;
        float4 v4 = make_float4(0.f, 0.f, 0.f, 0.f);
        if (kpos >= 0)
            v4 = *(const float4*)(V + rowbase + (size_t)kpos * CH + dd0);
        *(float4*)&vs[j * VS_STRIDE + dd0] = v4;
    }
    cp_wait<0>();
    __syncthreads();

    const int wm = (warp & 3) * 16;
    const int wn = (warp >> 2) * 64;
    const int wh = warp >> 2;
    const int lr = lane & 15;
    const int lc = lane >> 4;

    float acc[8][4];
#pragma unroll
    for (int nf = 0; nf < 8; nf++)
#pragma unroll
        for (int t = 0; t < 4; t++) acc[nf][t] = 0.0f;

#pragma unroll
    for (int kc = 0; kc < 2; kc++)
#pragma unroll
        for (int ks = 0; ks < 2; ks++) {
            const int chnk = ks * 2 + lc;
            uint32_t ah[4], al[4], bh[4][4];
            uint32_t qoff = sw_off(wm + lr, chnk);
            ldsm4(ah[0], ah[1], ah[2], ah[3], sbase + A_QH + kc * 4096 + qoff);
            ldsm4(al[0], al[1], al[2], al[3], sbase + A_QL + kc * 4096 + qoff);
#pragma unroll
            for (int g = 0; g < 4; g++) {
                uint32_t off = sw_off(wn + g * 16 + lr, chnk);
                ldsm4(bh[g][0], bh[g][1], bh[g][2], bh[g][3],
                      sbase + A_KH + kc * 8192 + off);
            }
#pragma unroll
            for (int nf = 0; nf < 8; nf++) {
                const int g = nf >> 1, w = nf & 1;
                mma16816(acc[nf], ah, bh[g][w], bh[g][w + 2]);
                mma16816(acc[nf], al, bh[g][w], bh[g][w + 2]);
            }
        }

    const float scale = 0.125f;
    const int r0 = wm + (lane >> 2);
    const int r1 = r0 + 8;
    float rm0 = -1e30f, rm1 = -1e30f;
#pragma unroll
    for (int nf = 0; nf < 8; nf++) {
        const int j0 = wn + nf * 8 + ((lane & 3) << 1);
        const int j1 = j0 + 1;
        bool w0 = (n > 0 || j0 >= BS);
        bool w1 = (n > 0 || j1 >= BS);
        acc[nf][0] = (w0 && j0 <= r0 + BS) ? acc[nf][0] * scale : -1e30f;
        acc[nf][1] = (w1 && j1 <= r0 + BS) ? acc[nf][1] * scale : -1e30f;
        acc[nf][2] = (w0 && j0 <= r1 + BS) ? acc[nf][2] * scale : -1e30f;
        acc[nf][3] = (w1 && j1 <= r1 + BS) ? acc[nf][3] * scale : -1e30f;
        rm0 = fmaxf(rm0, fmaxf(acc[nf][0], acc[nf][1]));
        rm1 = fmaxf(rm1, fmaxf(acc[nf][2], acc[nf][3]));
    }
    rm0 = fmaxf(rm0, __shfl_xor_sync(0xffffffffu, rm0, 1));
    rm0 = fmaxf(rm0, __shfl_xor_sync(0xffffffffu, rm0, 2));
    rm1 = fmaxf(rm1, __shfl_xor_sync(0xffffffffu, rm1, 1));
    rm1 = fmaxf(rm1, __shfl_xor_sync(0xffffffffu, rm1, 2));
    if ((lane & 3) == 0) {
        maxb[wh * 64 + r0] = rm0;
        maxb[wh * 64 + r1] = rm1;
    }
    __syncthreads();
    const float m0 = fmaxf(maxb[r0], maxb[64 + r0]);
    const float m1 = fmaxf(maxb[r1], maxb[64 + r1]);

    float s0 = 0.f, s1 = 0.f;
#pragma unroll
    for (int nf = 0; nf < 8; nf++) {
        acc[nf][0] = __expf(acc[nf][0] - m0);
        acc[nf][1] = __expf(acc[nf][1] - m0);
        acc[nf][2] = __expf(acc[nf][2] - m1);
        acc[nf][3] = __expf(acc[nf][3] - m1);
        s0 += acc[nf][0] + acc[nf][1];
        s1 += acc[nf][2] + acc[nf][3];
    }
    s0 += __shfl_xor_sync(0xffffffffu, s0, 1);
    s0 += __shfl_xor_sync(0xffffffffu, s0, 2);
    s1 += __shfl_xor_sync(0xffffffffu, s1, 1);
    s1 += __shfl_xor_sync(0xffffffffu, s1, 2);
    if ((lane & 3) == 0) {
        sumb[wh * 64 + r0] = s0;
        sumb[wh * 64 + r1] = s1;
    }
    __syncthreads();
    const float inv0 = 1.0f / (sumb[r0] + sumb[64 + r0]);
    const float inv1 = 1.0f / (sumb[r1] + sumb[64 + r1]);

#pragma unroll
    for (int nf = 0; nf < 8; nf++) {
        const int j0 = wn + nf * 8 + ((lane & 3) << 1);
        __half2 p0, p1;
        p0.x = __float2half(acc[nf][0] * inv0);
        p0.y = __float2half(acc[nf][1] * inv0);
        p1.x = __float2half(acc[nf][2] * inv1);
        p1.y = __float2half(acc[nf][3] * inv1);
        *(__half2*)&Ps[r0 * PS_STRIDE + j0] = p0;
        *(__half2*)&Ps[r1 * PS_STRIDE + j0] = p1;
    }
    __syncthreads();

    const int i0p = (tid >> 4) << 2;
    const int c0  = (tid & 15) << 2;
    unsigned long long o2[4][2];
#pragma unroll
    for (int ii = 0; ii < 4; ii++) { o2[ii][0] = 0ull; o2[ii][1] = 0ull; }

    const int jlim = (i0p + 68 < WIN) ? (i0p + 68) : WIN;
#pragma unroll 1
    for (int j = 0; j < jlim; j += 4) {
        ulonglong2 va = *(const ulonglong2*)&vs[(j + 0) * VS_STRIDE + c0];
        ulonglong2 vb = *(const ulonglong2*)&vs[(j + 1) * VS_STRIDE + c0];
        ulonglong2 vc = *(const ulonglong2*)&vs[(j + 2) * VS_STRIDE + c0];
        ulonglong2 vd = *(const ulonglong2*)&vs[(j + 3) * VS_STRIDE + c0];
#pragma unroll
        for (int ii = 0; ii < 4; ii++) {
            uint2 pq = *(const uint2*)&Ps[(i0p + ii) * PS_STRIDE + j];
            float2 p01 = __half22float2(*reinterpret_cast<__half2*>(&pq.x));
            float2 p23 = __half22float2(*reinterpret_cast<__half2*>(&pq.y));
            unsigned long long px = pack2(p01.x, p01.x);
            unsigned long long py = pack2(p01.y, p01.y);
            unsigned long long pz = pack2(p23.x, p23.x);
            unsigned long long pw = pack2(p23.y, p23.y);
            fma2(o2[ii][0], px, va.x); fma2(o2[ii][1], px, va.y);
            fma2(o2[ii][0], py, vb.x); fma2(o2[ii][1], py, vb.y);
            fma2(o2[ii][0], pz, vc.x); fma2(o2[ii][1], pz, vc.y);
            fma2(o2[ii][0], pw, vd.x); fma2(o2[ii][1], pw, vd.y);
        }
    }
#pragma unroll
    for (int ii = 0; ii < 4; ii++) {
        float o0, o1, o2f, o3;
        unpack2(o2[ii][0], o0, o1);
        unpack2(o2[ii][1], o2f, o3);
        const size_t oidx = rowbase + (size_t)(n * BS + i0p + ii) * CH + c0;
        __half2 hp0, hp1;
        hp0.x = __float2half(o0);  hp0.y = __float2half(o1);
        hp1.x = __float2half(o2f); hp1.y = __float2half(o3);
        *(__half2*)(Ohi + oidx)     = hp0;
        *(__half2*)(Ohi + oidx + 2) = hp1;
    }
}

// ---------------------------------------------------------------------------
extern "C" void kernel_launch(void* const* d_in, const int* in_sizes, int n_in,
                              void* d_out, int out_size)
{
    const float* x  = (const float*)d_in[0];
    const float* Wq = (const float*)d_in[1];
    const float* bq = (const float*)d_in[2];
    const float* Wk = (const float*)d_in[3];
    const float* bk = (const float*)d_in[4];
    const float* Wv = (const float*)d_in[5];
    const float* bv = (const float*)d_in[6];
    const float* Wo = (const float*)d_in[7];
    const float* bo = (const float*)d_in[8];
    float* out = (float*)d_out;

    float *vp;
    __half *qh, *ql, *kh, *ahi, *phi, *whi;
    cudaGetSymbolAddress((void**)&vp,  g_V);
    cudaGetSymbolAddress((void**)&qh,  g_Qh);
    cudaGetSymbolAddress((void**)&ql,  g_Ql);
    cudaGetSymbolAddress((void**)&kh,  g_Kh);
    cudaGetSymbolAddress((void**)&ahi, g_Ahi);
    cudaGetSymbolAddress((void**)&phi, g_Phi);
    cudaGetSymbolAddress((void**)&whi, g_Whi);

    cudaFuncSetAttribute(attn_kernel,
                         cudaFuncAttributeMaxDynamicSharedMemorySize, ATTN_SMEM_BYTES);
    cudaFuncSetAttribute(gemm_out,
                         cudaFuncAttributeMaxDynamicSharedMemorySize, QKV_SMEM);
    cudaFuncSetAttribute(gemm_qkv,
                         cudaFuncAttributeMaxDynamicSharedMemorySize, QKV_SMEM);

    const int NX = MROWS * CH;
    const int NW = CH * CH;

    to_f16_x<<<NX / 2048, 256>>>(x, ahi);
    to_f16_w4<<<2048, 256>>>(Wq, Wk, Wv, Wo, whi);

    gemm_qkv<<<dim3(24, MROWS / 128), 256, QKV_SMEM>>>(
        ahi, whi, bq, bk, bv, qh, ql, kh, vp);

    attn_kernel<<<dim3(NB, NH, BATCH), 256, ATTN_SMEM_BYTES>>>(
        qh, ql, kh, vp, phi);

    gemm_out<<<dim3(8, MROWS / 128), 256, QKV_SMEM>>>(
        phi, whi + 3 * (size_t)NW, bo, out);
}

// round 16
// speedup vs baseline: 1.9653x; 1.0869x over previous
#include <cuda_runtime.h>
#include <cuda_fp16.h>
#include <cstdint>

#define BATCH 4
#define SEQ   4096
#define CH    1024
#define NH    16
#define HD    64
#define BS    64
#define NB    (SEQ / BS)          // 64
#define MROWS (BATCH * SEQ)       // 16384

// ---------------- scratch (device globals: allocation-free) ----------------
__device__ float  g_V [(size_t)MROWS * CH];
__device__ __half g_Qh[(size_t)MROWS * CH];
__device__ __half g_Ql[(size_t)MROWS * CH];
__device__ __half g_Kh[(size_t)MROWS * CH];
__device__ __half g_Ahi[(size_t)MROWS * CH];
__device__ __half g_Phi[(size_t)MROWS * CH];
__device__ __half g_Whi[(size_t)4 * CH * CH];

// =================== helpers ===================
__device__ __forceinline__ uint32_t smem_u32(const void* p) {
    uint32_t a;
    asm("{ .reg .u64 t; cvta.to.shared.u64 t, %1; cvt.u32.u64 %0, t; }"
        : "=r"(a) : "l"(p));
    return a;
}
__device__ __forceinline__ void cp16(uint32_t dst, const void* src) {
    asm volatile("cp.async.cg.shared.global [%0], [%1], 16;" :: "r"(dst), "l"(src));
}
__device__ __forceinline__ void cp_commit() {
    asm volatile("cp.async.commit_group;" ::: "memory");
}
template <int N>
__device__ __forceinline__ void cp_wait() {
    asm volatile("cp.async.wait_group %0;" :: "n"(N) : "memory");
}
__device__ __forceinline__ void ldsm4(uint32_t& r0, uint32_t& r1, uint32_t& r2,
                                      uint32_t& r3, uint32_t addr) {
    asm volatile("ldmatrix.sync.aligned.m8n8.x4.shared.b16 {%0,%1,%2,%3}, [%4];"
                 : "=r"(r0), "=r"(r1), "=r"(r2), "=r"(r3) : "r"(addr));
}
__device__ __forceinline__ void mma16816(float* c, const uint32_t* a,
                                         uint32_t b0, uint32_t b1) {
    asm volatile(
        "mma.sync.aligned.m16n8k16.row.col.f32.f16.f16.f32 "
        "{%0,%1,%2,%3}, {%4,%5,%6,%7}, {%8,%9}, {%0,%1,%2,%3};"
        : "+f"(c[0]), "+f"(c[1]), "+f"(c[2]), "+f"(c[3])
        : "r"(a[0]), "r"(a[1]), "r"(a[2]), "r"(a[3]), "r"(b0), "r"(b1));
}
// ---- packed f32x2 (FFMA2) helpers ----
__device__ __forceinline__ unsigned long long pack2(float x, float y) {
    unsigned long long r;
    asm("mov.b64 %0, {%1, %2};" : "=l"(r) : "f"(x), "f"(y));
    return r;
}
__device__ __forceinline__ void unpack2(unsigned long long v, float& x, float& y) {
    asm("mov.b64 {%0, %1}, %2;" : "=f"(x), "=f"(y) : "l"(v));
}
__device__ __forceinline__ void fma2(unsigned long long& d, unsigned long long a,
                                     unsigned long long b) {
    asm("fma.rn.f32x2 %0, %1, %2, %0;" : "+l"(d) : "l"(a), "l"(b));
}

// =================== fp32 -> fp16 converters (8 elems, 16B stores) =========
__global__ __launch_bounds__(256) void to_f16_x(
    const float* __restrict__ in, __half* __restrict__ hi)
{
    int i = (blockIdx.x * 256 + threadIdx.x) * 8;
    float4 v0 = *(const float4*)(in + i);
    float4 v1 = *(const float4*)(in + i + 4);
    __half2 hp[4];
    hp[0].x = __float2half(v0.x); hp[0].y = __float2half(v0.y);
    hp[1].x = __float2half(v0.z); hp[1].y = __float2half(v0.w);
    hp[2].x = __float2half(v1.x); hp[2].y = __float2half(v1.y);
    hp[3].x = __float2half(v1.z); hp[3].y = __float2half(v1.w);
    *(uint4*)(hi + i) = *(uint4*)hp;
}
__global__ __launch_bounds__(256) void to_f16_w4(
    const float* __restrict__ w0, const float* __restrict__ w1,
    const float* __restrict__ w2, const float* __restrict__ w3,
    __half* __restrict__ hi)
{
    const int seg = blockIdx.x >> 9;
    const int loc = (int)(blockIdx.x & 511) * 2048 + threadIdx.x * 8;
    const float* in = (seg == 0) ? w0 : (seg == 1) ? w1 : (seg == 2) ? w2 : w3;
    float4 v0 = *(const float4*)(in + loc);
    float4 v1 = *(const float4*)(in + loc + 4);
    __half2 hp[4];
    hp[0].x = __float2half(v0.x); hp[0].y = __float2half(v0.y);
    hp[1].x = __float2half(v0.z); hp[1].y = __float2half(v0.w);
    hp[2].x = __float2half(v1.x); hp[2].y = __float2half(v1.y);
    hp[3].x = __float2half(v1.z); hp[3].y = __float2half(v1.w);
    *(uint4*)(hi + (size_t)seg * CH * CH + loc) = *(uint4*)hp;
}

// =================== HMMA GEMM core (BM=BN=128, BK=64, 8 warps) =============
#define BKH 64
#define NKC (CH / BKH)            // 16
#define GT_BYTES 16384            // 128 rows * 128 B
#define GSTAGE (2 * GT_BYTES)     // A-hi, B-hi
#define GEMM_SMEM (3 * GSTAGE)    // 98304

// full SW128 swizzle for 128B rows (8 x 16B chunks)
__device__ __forceinline__ uint32_t sw128(int row, int ch) {
    return (uint32_t)(row * 128 + ((ch ^ (row & 7)) << 4));
}
// 64B-row swizzle (attention tiles, unchanged)
__device__ __forceinline__ uint32_t sw_off(int row, int chunk) {
    return (uint32_t)(row * 64 + ((chunk ^ ((row >> 1) & 3)) << 4));
}

// MODE 0: fp32 Out; MODE 1: fp16 hi/lo; MODE 2: fp16 hi only (A = hi only)
template <int MODE>
__device__ __forceinline__ void gemm_body(
    const __half* __restrict__ Ahi_t, const __half* __restrict__ Bh_t,
    const float* __restrict__ bias,
    float* __restrict__ OutF, __half* __restrict__ OutH, __half* __restrict__ OutL,
    int bm, int bn, char* dsm)
{
    const uint32_t base = smem_u32(dsm);
    const int tid  = threadIdx.x;
    const int wid  = tid >> 5;
    const int lane = tid & 31;
    const int wm = (wid & 3) * 32;
    const int wn = (wid >> 2) * 64;

    const __half* srcs[2] = { Ahi_t, Bh_t };

    auto load_stage = [&](int st, int kc) {
        const uint32_t sb = base + st * GSTAGE;
#pragma unroll
        for (int p = 0; p < 8; p++) {
            int idx = p * 256 + tid;       // 0..2047
            int buf = idx >> 10;           // 0..1
            int rem = idx & 1023;
            int row = rem >> 3;            // 0..127
            int ch  = rem & 7;             // 0..7
            const __half* s = srcs[buf] + (size_t)row * CH + kc * BKH + ch * 8;
            cp16(sb + buf * GT_BYTES + sw128(row, ch), s);
        }
        cp_commit();
    };

    float acc[2][8][4];
#pragma unroll
    for (int mi = 0; mi < 2; mi++)
#pragma unroll
        for (int ni = 0; ni < 8; ni++)
#pragma unroll
            for (int t = 0; t < 4; t++) acc[mi][ni][t] = 0.0f;

    load_stage(0, 0);
    load_stage(1, 1);

    const int lr = lane & 15;
    const int lc = lane >> 4;

    for (int kc = 0; kc < NKC; kc++) {
        if (kc < NKC - 1) cp_wait<1>(); else cp_wait<0>();
        __syncthreads();

        const uint32_t sb = base + (kc % 3) * GSTAGE;
        const uint32_t aB = sb;
        const uint32_t bB = sb + GT_BYTES;

#pragma unroll
        for (int ks = 0; ks < 4; ks++) {
            const int chnk = ks * 2 + lc;
            uint32_t ah[2][4], bh[4][4];
#pragma unroll
            for (int mi = 0; mi < 2; mi++) {
                uint32_t off = sw128(wm + mi * 16 + lr, chnk);
                ldsm4(ah[mi][0], ah[mi][1], ah[mi][2], ah[mi][3], aB + off);
            }
#pragma unroll
            for (int g = 0; g < 4; g++) {
                uint32_t off = sw128(wn + g * 16 + lr, chnk);
                ldsm4(bh[g][0], bh[g][1], bh[g][2], bh[g][3], bB + off);
            }
#pragma unroll
            for (int mi = 0; mi < 2; mi++)
#pragma unroll
                for (int ni = 0; ni < 8; ni++) {
                    const int g = ni >> 1, w = ni & 1;
                    mma16816(acc[mi][ni], ah[mi], bh[g][w], bh[g][w + 2]);
                }
        }
        if (kc + 2 < NKC) load_stage((kc + 2) % 3, kc + 2);
    }

#pragma unroll
    for (int mi = 0; mi < 2; mi++) {
        const int r0 = bm + wm + mi * 16 + (lane >> 2);
#pragma unroll
        for (int ni = 0; ni < 8; ni++) {
            const int c = bn + wn + ni * 8 + (lane & 3) * 2;
            const float b0 = bias[c], b1 = bias[c + 1];
            float q0 = acc[mi][ni][0] + b0, q1 = acc[mi][ni][1] + b1;
            float q2 = acc[mi][ni][2] + b0, q3 = acc[mi][ni][3] + b1;
            if (MODE == 0) {
                *(float2*)(OutF + (size_t)r0 * CH + c)       = make_float2(q0, q1);
                *(float2*)(OutF + (size_t)(r0 + 8) * CH + c) = make_float2(q2, q3);
            } else {
                __half2 h01, h23;
                h01.x = __float2half(q0); h01.y = __float2half(q1);
                h23.x = __float2half(q2); h23.y = __float2half(q3);
                *(__half2*)(OutH + (size_t)r0 * CH + c)       = h01;
                *(__half2*)(OutH + (size_t)(r0 + 8) * CH + c) = h23;
                if (MODE == 1) {
                    __half2 l01, l23;
                    l01.x = __float2half(q0 - __half2float(h01.x));
                    l01.y = __float2half(q1 - __half2float(h01.y));
                    l23.x = __float2half(q2 - __half2float(h23.x));
                    l23.y = __float2half(q3 - __half2float(h23.y));
                    *(__half2*)(OutL + (size_t)r0 * CH + c)       = l01;
                    *(__half2*)(OutL + (size_t)(r0 + 8) * CH + c) = l23;
                }
            }
        }
    }
}

// fused QKV GEMM (A = x hi only): Q -> fp16 hi/lo, K -> fp16 hi, V -> fp32
__global__ __launch_bounds__(256, 2) void gemm_qkv(
    const __half* __restrict__ Ahi, const __half* __restrict__ Wall,
    const float* __restrict__ bq, const float* __restrict__ bk,
    const float* __restrict__ bv,
    __half* __restrict__ Qh, __half* __restrict__ Ql,
    __half* __restrict__ Kh, float* __restrict__ Vf)
{
    extern __shared__ char dsm[];
    const int bng = blockIdx.x * 128;
    const int sel = bng >> 10;
    const int bn  = bng & 1023;
    const int bm  = blockIdx.y * 128;
    const __half* Bh = Wall + (size_t)sel * CH * CH + (size_t)bn * CH;
    const __half* Ah = Ahi + (size_t)bm * CH;
    if (sel == 0)
        gemm_body<1>(Ah, Bh, bq, nullptr, Qh, Ql, bm, bn, dsm);
    else if (sel == 1)
        gemm_body<2>(Ah, Bh, bk, nullptr, Kh, nullptr, bm, bn, dsm);
    else
        gemm_body<0>(Ah, Bh, bv, Vf, nullptr, nullptr, bm, bn, dsm);
}

// output projection (A = attention out, hi only)
__global__ __launch_bounds__(256, 2) void gemm_out(
    const __half* __restrict__ Ahi, const __half* __restrict__ Bh,
    const float* __restrict__ bias, float* __restrict__ Out)
{
    extern __shared__ char dsm[];
    const int bm = blockIdx.y * 128;
    const int bn = blockIdx.x * 128;
    gemm_body<0>(Ahi + (size_t)bm * CH, Bh + (size_t)bn * CH,
                 bias, Out, nullptr, nullptr, bm, bn, dsm);
}

// ---------------- attention: HMMA scores + FFMA2 PV (unchanged) ------------
#define A_QH 0
#define A_QL 8192
#define A_KH 16896
#define A_VS 33280
#define A_RED 68096
#define PS_STRIDE 132
#define VS_STRIDE 68
#define WIN 128
#define ATTN_SMEM_BYTES 69120

__global__ __launch_bounds__(256, 3) void attn_kernel(
    const __half* __restrict__ Qh, const __half* __restrict__ Ql,
    const __half* __restrict__ Kh, const float* __restrict__ V,
    __half* __restrict__ Ohi)
{
    extern __shared__ char dsm[];
    const uint32_t sbase = smem_u32(dsm);
    float*  vs   = (float*)(dsm + A_VS);
    __half* Ps   = (__half*)(dsm + 0);
    float*  maxb = (float*)(dsm + A_RED);
    float*  sumb = maxb + 128;

    const int tid  = threadIdx.x;
    const int warp = tid >> 5;
    const int lane = tid & 31;
    const int n = blockIdx.x;
    const int h = blockIdx.y;
    const int b = blockIdx.z;
    const size_t rowbase = (size_t)b * SEQ * CH + (size_t)h * HD;

#pragma unroll
    for (int p = 0; p < 2; p++) {
        int idx = tid + p * 256;
        int i  = idx >> 3;
        int ch = idx & 7;
        int kc = ch >> 2, cc = ch & 3;
        const __half* sh = Qh + rowbase + (size_t)(n * BS + i) * CH + ch * 8;
        const __half* sl = Ql + rowbase + (size_t)(n * BS + i) * CH + ch * 8;
        cp16(sbase + A_QH + kc * 4096 + sw_off(i, cc), sh);
        cp16(sbase + A_QL + kc * 4096 + sw_off(i, cc), sl);
    }
#pragma unroll
    for (int p = 0; p < 4; p++) {
        int idx = tid + p * 256;
        int j  = idx >> 3;
        int ch = idx & 7;
        int kc = ch >> 2, cc = ch & 3;
        int kpos = (n - 1) * BS + j;
        uint32_t off = A_KH + kc * 8192 + sw_off(j, cc);
        if (kpos >= 0)
            cp16(sbase + off, Kh + rowbase + (size_t)kpos * CH + ch * 8);
        else
            *(uint4*)(dsm + off) = make_uint4(0, 0, 0, 0);
    }
    cp_commit();
#pragma unroll
    for (int p = 0; p < 8; p++) {
        int idx = tid + p * 256;
        int j   = idx >> 4;
        int dd0 = (idx & 15) << 2;
        int kpos = (n - 1) * BS + j;
        float4 v4 = make_float4(0.f, 0.f, 0.f, 0.f);
        if (kpos >= 0)
            v4 = *(const float4*)(V + rowbase + (size_t)kpos * CH + dd0);
        *(float4*)&vs[j * VS_STRIDE + dd0] = v4;
    }
    cp_wait<0>();
    __syncthreads();

    const int wm = (warp & 3) * 16;
    const int wn = (warp >> 2) * 64;
    const int wh = warp >> 2;
    const int lr = lane & 15;
    const int lc = lane >> 4;

    float acc[8][4];
#pragma unroll
    for (int nf = 0; nf < 8; nf++)
#pragma unroll
        for (int t = 0; t < 4; t++) acc[nf][t] = 0.0f;

#pragma unroll
    for (int kc = 0; kc < 2; kc++)
#pragma unroll
        for (int ks = 0; ks < 2; ks++) {
            const int chnk = ks * 2 + lc;
            uint32_t ah[4], al[4], bh[4][4];
            uint32_t qoff = sw_off(wm + lr, chnk);
            ldsm4(ah[0], ah[1], ah[2], ah[3], sbase + A_QH + kc * 4096 + qoff);
            ldsm4(al[0], al[1], al[2], al[3], sbase + A_QL + kc * 4096 + qoff);
#pragma unroll
            for (int g = 0; g < 4; g++) {
                uint32_t off = sw_off(wn + g * 16 + lr, chnk);
                ldsm4(bh[g][0], bh[g][1], bh[g][2], bh[g][3],
                      sbase + A_KH + kc * 8192 + off);
            }
#pragma unroll
            for (int nf = 0; nf < 8; nf++) {
                const int g = nf >> 1, w = nf & 1;
                mma16816(acc[nf], ah, bh[g][w], bh[g][w + 2]);
                mma16816(acc[nf], al, bh[g][w], bh[g][w + 2]);
            }
        }

    const float scale = 0.125f;
    const int r0 = wm + (lane >> 2);
    const int r1 = r0 + 8;
    float rm0 = -1e30f, rm1 = -1e30f;
#pragma unroll
    for (int nf = 0; nf < 8; nf++) {
        const int j0 = wn + nf * 8 + ((lane & 3) << 1);
        const int j1 = j0 + 1;
        bool w0 = (n > 0 || j0 >= BS);
        bool w1 = (n > 0 || j1 >= BS);
        acc[nf][0] = (w0 && j0 <= r0 + BS) ? acc[nf][0] * scale : -1e30f;
        acc[nf][1] = (w1 && j1 <= r0 + BS) ? acc[nf][1] * scale : -1e30f;
        acc[nf][2] = (w0 && j0 <= r1 + BS) ? acc[nf][2] * scale : -1e30f;
        acc[nf][3] = (w1 && j1 <= r1 + BS) ? acc[nf][3] * scale : -1e30f;
        rm0 = fmaxf(rm0, fmaxf(acc[nf][0], acc[nf][1]));
        rm1 = fmaxf(rm1, fmaxf(acc[nf][2], acc[nf][3]));
    }
    rm0 = fmaxf(rm0, __shfl_xor_sync(0xffffffffu, rm0, 1));
    rm0 = fmaxf(rm0, __shfl_xor_sync(0xffffffffu, rm0, 2));
    rm1 = fmaxf(rm1, __shfl_xor_sync(0xffffffffu, rm1, 1));
    rm1 = fmaxf(rm1, __shfl_xor_sync(0xffffffffu, rm1, 2));
    if ((lane & 3) == 0) {
        maxb[wh * 64 + r0] = rm0;
        maxb[wh * 64 + r1] = rm1;
    }
    __syncthreads();
    const float m0 = fmaxf(maxb[r0], maxb[64 + r0]);
    const float m1 = fmaxf(maxb[r1], maxb[64 + r1]);

    float s0 = 0.f, s1 = 0.f;
#pragma unroll
    for (int nf = 0; nf < 8; nf++) {
        acc[nf][0] = __expf(acc[nf][0] - m0);
        acc[nf][1] = __expf(acc[nf][1] - m0);
        acc[nf][2] = __expf(acc[nf][2] - m1);
        acc[nf][3] = __expf(acc[nf][3] - m1);
        s0 += acc[nf][0] + acc[nf][1];
        s1 += acc[nf][2] + acc[nf][3];
    }
    s0 += __shfl_xor_sync(0xffffffffu, s0, 1);
    s0 += __shfl_xor_sync(0xffffffffu, s0, 2);
    s1 += __shfl_xor_sync(0xffffffffu, s1, 1);
    s1 += __shfl_xor_sync(0xffffffffu, s1, 2);
    if ((lane & 3) == 0) {
        sumb[wh * 64 + r0] = s0;
        sumb[wh * 64 + r1] = s1;
    }
    __syncthreads();
    const float inv0 = 1.0f / (sumb[r0] + sumb[64 + r0]);
    const float inv1 = 1.0f / (sumb[r1] + sumb[64 + r1]);

#pragma unroll
    for (int nf = 0; nf < 8; nf++) {
        const int j0 = wn + nf * 8 + ((lane & 3) << 1);
        __half2 p0, p1;
        p0.x = __float2half(acc[nf][0] * inv0);
        p0.y = __float2half(acc[nf][1] * inv0);
        p1.x = __float2half(acc[nf][2] * inv1);
        p1.y = __float2half(acc[nf][3] * inv1);
        *(__half2*)&Ps[r0 * PS_STRIDE + j0] = p0;
        *(__half2*)&Ps[r1 * PS_STRIDE + j0] = p1;
    }
    __syncthreads();

    const int i0p = (tid >> 4) << 2;
    const int c0  = (tid & 15) << 2;
    unsigned long long o2[4][2];
#pragma unroll
    for (int ii = 0; ii < 4; ii++) { o2[ii][0] = 0ull; o2[ii][1] = 0ull; }

    const int jlim = (i0p + 68 < WIN) ? (i0p + 68) : WIN;
#pragma unroll 1
    for (int j = 0; j < jlim; j += 4) {
        ulonglong2 va = *(const ulonglong2*)&vs[(j + 0) * VS_STRIDE + c0];
        ulonglong2 vb = *(const ulonglong2*)&vs[(j + 1) * VS_STRIDE + c0];
        ulonglong2 vc = *(const ulonglong2*)&vs[(j + 2) * VS_STRIDE + c0];
        ulonglong2 vd = *(const ulonglong2*)&vs[(j + 3) * VS_STRIDE + c0];
#pragma unroll
        for (int ii = 0; ii < 4; ii++) {
            uint2 pq = *(const uint2*)&Ps[(i0p + ii) * PS_STRIDE + j];
            float2 p01 = __half22float2(*reinterpret_cast<__half2*>(&pq.x));
            float2 p23 = __half22float2(*reinterpret_cast<__half2*>(&pq.y));
            unsigned long long px = pack2(p01.x, p01.x);
            unsigned long long py = pack2(p01.y, p01.y);
            unsigned long long pz = pack2(p23.x, p23.x);
            unsigned long long pw = pack2(p23.y, p23.y);
            fma2(o2[ii][0], px, va.x); fma2(o2[ii][1], px, va.y);
            fma2(o2[ii][0], py, vb.x); fma2(o2[ii][1], py, vb.y);
            fma2(o2[ii][0], pz, vc.x); fma2(o2[ii][1], pz, vc.y);
            fma2(o2[ii][0], pw, vd.x); fma2(o2[ii][1], pw, vd.y);
        }
    }
#pragma unroll
    for (int ii = 0; ii < 4; ii++) {
        float o0, o1, o2f, o3;
        unpack2(o2[ii][0], o0, o1);
        unpack2(o2[ii][1], o2f, o3);
        const size_t oidx = rowbase + (size_t)(n * BS + i0p + ii) * CH + c0;
        __half2 hp0, hp1;
        hp0.x = __float2half(o0);  hp0.y = __float2half(o1);
        hp1.x = __float2half(o2f); hp1.y = __float2half(o3);
        *(__half2*)(Ohi + oidx)     = hp0;
        *(__half2*)(Ohi + oidx + 2) = hp1;
    }
}

// ---------------------------------------------------------------------------
extern "C" void kernel_launch(void* const* d_in, const int* in_sizes, int n_in,
                              void* d_out, int out_size)
{
    const float* x  = (const float*)d_in[0];
    const float* Wq = (const float*)d_in[1];
    const float* bq = (const float*)d_in[2];
    const float* Wk = (const float*)d_in[3];
    const float* bk = (const float*)d_in[4];
    const float* Wv = (const float*)d_in[5];
    const float* bv = (const float*)d_in[6];
    const float* Wo = (const float*)d_in[7];
    const float* bo = (const float*)d_in[8];
    float* out = (float*)d_out;

    float *vp;
    __half *qh, *ql, *kh, *ahi, *phi, *whi;
    cudaGetSymbolAddress((void**)&vp,  g_V);
    cudaGetSymbolAddress((void**)&qh,  g_Qh);
    cudaGetSymbolAddress((void**)&ql,  g_Ql);
    cudaGetSymbolAddress((void**)&kh,  g_Kh);
    cudaGetSymbolAddress((void**)&ahi, g_Ahi);
    cudaGetSymbolAddress((void**)&phi, g_Phi);
    cudaGetSymbolAddress((void**)&whi, g_Whi);

    cudaFuncSetAttribute(attn_kernel,
                         cudaFuncAttributeMaxDynamicSharedMemorySize, ATTN_SMEM_BYTES);
    cudaFuncSetAttribute(gemm_out,
                         cudaFuncAttributeMaxDynamicSharedMemorySize, GEMM_SMEM);
    cudaFuncSetAttribute(gemm_qkv,
                         cudaFuncAttributeMaxDynamicSharedMemorySize, GEMM_SMEM);

    const int NX = MROWS * CH;
    const int NW = CH * CH;

    to_f16_x<<<NX / 2048, 256>>>(x, ahi);
    to_f16_w4<<<2048, 256>>>(Wq, Wk, Wv, Wo, whi);

    gemm_qkv<<<dim3(24, MROWS / 128), 256, GEMM_SMEM>>>(
        ahi, whi, bq, bk, bv, qh, ql, kh, vp);

    attn_kernel<<<dim3(NB, NH, BATCH), 256, ATTN_SMEM_BYTES>>>(
        qh, ql, kh, vp, phi);

    gemm_out<<<dim3(8, MROWS / 128), 256, GEMM_SMEM>>>(
        phi, whi + 3 * (size_t)NW, bo, out);
}

// round 17
// speedup vs baseline: 2.0165x; 1.0260x over previous
#include <cuda_runtime.h>
#include <cuda_fp16.h>
#include <cstdint>

#define BATCH 4
#define SEQ   4096
#define CH    1024
#define NH    16
#define HD    64
#define BS    64
#define NB    (SEQ / BS)          // 64
#define MROWS (BATCH * SEQ)       // 16384

// ---------------- scratch (device globals: allocation-free) ----------------
__device__ __half g_Qh[(size_t)MROWS * CH];
__device__ __half g_Kh[(size_t)MROWS * CH];
__device__ __half g_Vh[(size_t)MROWS * CH];
__device__ __half g_Ahi[(size_t)MROWS * CH];
__device__ __half g_Phi[(size_t)MROWS * CH];
__device__ __half g_Whi[(size_t)4 * CH * CH];

// =================== helpers ===================
__device__ __forceinline__ uint32_t smem_u32(const void* p) {
    uint32_t a;
    asm("{ .reg .u64 t; cvta.to.shared.u64 t, %1; cvt.u32.u64 %0, t; }"
        : "=r"(a) : "l"(p));
    return a;
}
__device__ __forceinline__ void cp16(uint32_t dst, const void* src) {
    asm volatile("cp.async.cg.shared.global [%0], [%1], 16;" :: "r"(dst), "l"(src));
}
__device__ __forceinline__ void cp_commit() {
    asm volatile("cp.async.commit_group;" ::: "memory");
}
template <int N>
__device__ __forceinline__ void cp_wait() {
    asm volatile("cp.async.wait_group %0;" :: "n"(N) : "memory");
}
__device__ __forceinline__ void ldsm4(uint32_t& r0, uint32_t& r1, uint32_t& r2,
                                      uint32_t& r3, uint32_t addr) {
    asm volatile("ldmatrix.sync.aligned.m8n8.x4.shared.b16 {%0,%1,%2,%3}, [%4];"
                 : "=r"(r0), "=r"(r1), "=r"(r2), "=r"(r3) : "r"(addr));
}
__device__ __forceinline__ void mma16816(float* c, const uint32_t* a,
                                         uint32_t b0, uint32_t b1) {
    asm volatile(
        "mma.sync.aligned.m16n8k16.row.col.f32.f16.f16.f32 "
        "{%0,%1,%2,%3}, {%4,%5,%6,%7}, {%8,%9}, {%0,%1,%2,%3};"
        : "+f"(c[0]), "+f"(c[1]), "+f"(c[2]), "+f"(c[3])
        : "r"(a[0]), "r"(a[1]), "r"(a[2]), "r"(a[3]), "r"(b0), "r"(b1));
}
// ---- packed f32x2 (FFMA2) helpers ----
__device__ __forceinline__ unsigned long long pack2(float x, float y) {
    unsigned long long r;
    asm("mov.b64 %0, {%1, %2};" : "=l"(r) : "f"(x), "f"(y));
    return r;
}
__device__ __forceinline__ void unpack2(unsigned long long v, float& x, float& y) {
    asm("mov.b64 {%0, %1}, %2;" : "=f"(x), "=f"(y) : "l"(v));
}
__device__ __forceinline__ void fma2(unsigned long long& d, unsigned long long a,
                                     unsigned long long b) {
    asm("fma.rn.f32x2 %0, %1, %2, %0;" : "+l"(d) : "l"(a), "l"(b));
}

// =================== fp32 -> fp16 converters (8 elems, 16B stores) =========
__global__ __launch_bounds__(256) void to_f16_x(
    const float* __restrict__ in, __half* __restrict__ hi)
{
    int i = (blockIdx.x * 256 + threadIdx.x) * 8;
    float4 v0 = *(const float4*)(in + i);
    float4 v1 = *(const float4*)(in + i + 4);
    __half2 hp[4];
    hp[0].x = __float2half(v0.x); hp[0].y = __float2half(v0.y);
    hp[1].x = __float2half(v0.z); hp[1].y = __float2half(v0.w);
    hp[2].x = __float2half(v1.x); hp[2].y = __float2half(v1.y);
    hp[3].x = __float2half(v1.z); hp[3].y = __float2half(v1.w);
    *(uint4*)(hi + i) = *(uint4*)hp;
}
__global__ __launch_bounds__(256) void to_f16_w4(
    const float* __restrict__ w0, const float* __restrict__ w1,
    const float* __restrict__ w2, const float* __restrict__ w3,
    __half* __restrict__ hi)
{
    const int seg = blockIdx.x >> 9;
    const int loc = (int)(blockIdx.x & 511) * 2048 + threadIdx.x * 8;
    const float* in = (seg == 0) ? w0 : (seg == 1) ? w1 : (seg == 2) ? w2 : w3;
    float4 v0 = *(const float4*)(in + loc);
    float4 v1 = *(const float4*)(in + loc + 4);
    __half2 hp[4];
    hp[0].x = __float2half(v0.x); hp[0].y = __float2half(v0.y);
    hp[1].x = __float2half(v0.z); hp[1].y = __float2half(v0.w);
    hp[2].x = __float2half(v1.x); hp[2].y = __float2half(v1.y);
    hp[3].x = __float2half(v1.z); hp[3].y = __float2half(v1.w);
    *(uint4*)(hi + (size_t)seg * CH * CH + loc) = *(uint4*)hp;
}

// =================== HMMA GEMM core (BM=BN=128, BK=64, 8 warps) =============
#define BKH 64
#define NKC (CH / BKH)            // 16
#define GT_BYTES 16384            // 128 rows * 128 B
#define GSTAGE (2 * GT_BYTES)
#define GEMM_SMEM (3 * GSTAGE)    // 98304

__device__ __forceinline__ uint32_t sw128(int row, int ch) {
    return (uint32_t)(row * 128 + ((ch ^ (row & 7)) << 4));
}
__device__ __forceinline__ uint32_t sw_off(int row, int chunk) {
    return (uint32_t)(row * 64 + ((chunk ^ ((row >> 1) & 3)) << 4));
}

// MODE 0: fp32 Out; MODE 2: fp16 hi only (A = hi only)
template <int MODE>
__device__ __forceinline__ void gemm_body(
    const __half* __restrict__ Ahi_t, const __half* __restrict__ Bh_t,
    const float* __restrict__ bias,
    float* __restrict__ OutF, __half* __restrict__ OutH,
    int bm, int bn, char* dsm)
{
    const uint32_t base = smem_u32(dsm);
    const int tid  = threadIdx.x;
    const int wid  = tid >> 5;
    const int lane = tid & 31;
    const int wm = (wid & 3) * 32;
    const int wn = (wid >> 2) * 64;

    const __half* srcs[2] = { Ahi_t, Bh_t };

    auto load_stage = [&](int st, int kc) {
        const uint32_t sb = base + st * GSTAGE;
#pragma unroll
        for (int p = 0; p < 8; p++) {
            int idx = p * 256 + tid;
            int buf = idx >> 10;
            int rem = idx & 1023;
            int row = rem >> 3;
            int ch  = rem & 7;
            const __half* s = srcs[buf] + (size_t)row * CH + kc * BKH + ch * 8;
            cp16(sb + buf * GT_BYTES + sw128(row, ch), s);
        }
        cp_commit();
    };

    float acc[2][8][4];
#pragma unroll
    for (int mi = 0; mi < 2; mi++)
#pragma unroll
        for (int ni = 0; ni < 8; ni++)
#pragma unroll
            for (int t = 0; t < 4; t++) acc[mi][ni][t] = 0.0f;

    load_stage(0, 0);
    load_stage(1, 1);

    const int lr = lane & 15;
    const int lc = lane >> 4;

    for (int kc = 0; kc < NKC; kc++) {
        if (kc < NKC - 1) cp_wait<1>(); else cp_wait<0>();
        __syncthreads();

        const uint32_t sb = base + (kc % 3) * GSTAGE;
        const uint32_t aB = sb;
        const uint32_t bB = sb + GT_BYTES;

#pragma unroll
        for (int ks = 0; ks < 4; ks++) {
            const int chnk = ks * 2 + lc;
            uint32_t ah[2][4], bh[4][4];
#pragma unroll
            for (int mi = 0; mi < 2; mi++) {
                uint32_t off = sw128(wm + mi * 16 + lr, chnk);
                ldsm4(ah[mi][0], ah[mi][1], ah[mi][2], ah[mi][3], aB + off);
            }
#pragma unroll
            for (int g = 0; g < 4; g++) {
                uint32_t off = sw128(wn + g * 16 + lr, chnk);
                ldsm4(bh[g][0], bh[g][1], bh[g][2], bh[g][3], bB + off);
            }
#pragma unroll
            for (int mi = 0; mi < 2; mi++)
#pragma unroll
                for (int ni = 0; ni < 8; ni++) {
                    const int g = ni >> 1, w = ni & 1;
                    mma16816(acc[mi][ni], ah[mi], bh[g][w], bh[g][w + 2]);
                }
        }
        if (kc + 2 < NKC) load_stage((kc + 2) % 3, kc + 2);
    }

#pragma unroll
    for (int mi = 0; mi < 2; mi++) {
        const int r0 = bm + wm + mi * 16 + (lane >> 2);
#pragma unroll
        for (int ni = 0; ni < 8; ni++) {
            const int c = bn + wn + ni * 8 + (lane & 3) * 2;
            const float b0 = bias[c], b1 = bias[c + 1];
            float q0 = acc[mi][ni][0] + b0, q1 = acc[mi][ni][1] + b1;
            float q2 = acc[mi][ni][2] + b0, q3 = acc[mi][ni][3] + b1;
            if (MODE == 0) {
                *(float2*)(OutF + (size_t)r0 * CH + c)       = make_float2(q0, q1);
                *(float2*)(OutF + (size_t)(r0 + 8) * CH + c) = make_float2(q2, q3);
            } else {
                __half2 h01, h23;
                h01.x = __float2half(q0); h01.y = __float2half(q1);
                h23.x = __float2half(q2); h23.y = __float2half(q3);
                *(__half2*)(OutH + (size_t)r0 * CH + c)       = h01;
                *(__half2*)(OutH + (size_t)(r0 + 8) * CH + c) = h23;
            }
        }
    }
}

// fused QKV GEMM: all outputs fp16 hi
__global__ __launch_bounds__(256, 2) void gemm_qkv(
    const __half* __restrict__ Ahi, const __half* __restrict__ Wall,
    const float* __restrict__ bq, const float* __restrict__ bk,
    const float* __restrict__ bv,
    __half* __restrict__ Qh, __half* __restrict__ Kh, __half* __restrict__ Vh)
{
    extern __shared__ char dsm[];
    const int bng = blockIdx.x * 128;
    const int sel = bng >> 10;
    const int bn  = bng & 1023;
    const int bm  = blockIdx.y * 128;
    const __half* Bh = Wall + (size_t)sel * CH * CH + (size_t)bn * CH;
    const __half* Ah = Ahi + (size_t)bm * CH;
    const float* bias = (sel == 0) ? bq : (sel == 1) ? bk : bv;
    __half* OutH = (sel == 0) ? Qh : (sel == 1) ? Kh : Vh;
    gemm_body<2>(Ah, Bh, bias, nullptr, OutH, bm, bn, dsm);
}

// output projection (A = attention out, hi only) -> fp32
__global__ __launch_bounds__(256, 2) void gemm_out(
    const __half* __restrict__ Ahi, const __half* __restrict__ Bh,
    const float* __restrict__ bias, float* __restrict__ Out)
{
    extern __shared__ char dsm[];
    const int bm = blockIdx.y * 128;
    const int bn = blockIdx.x * 128;
    gemm_body<0>(Ahi + (size_t)bm * CH, Bh + (size_t)bn * CH,
                 bias, Out, nullptr, bm, bn, dsm);
}

// ---------------- attention: HMMA scores (Q,K fp16) + FFMA2 PV (V fp16) ----
// smem bytes:
//  [0, 8192)       QH tiles (2 x [64][32]h); later Ps fp16 [64][132] (0..16896,
//                  also covering dead KH space)
//  [8192, 24576)   KH tiles (2 x [128][32]h)
//  [24576, 40960)  Vh fp16 [128][64] (row = 128 B)
//  [40960, 41984)  maxbuf[2][64], sumbuf[2][64]
#define A_QH 0
#define A_KH 8192
#define A_VS 24576
#define A_RED 40960
#define PS_STRIDE 132
#define WIN 128
#define ATTN_SMEM_BYTES 41984

__global__ __launch_bounds__(256, 4) void attn_kernel(
    const __half* __restrict__ Qh, const __half* __restrict__ Kh,
    const __half* __restrict__ Vh, __half* __restrict__ Ohi)
{
    extern __shared__ char dsm[];
    const uint32_t sbase = smem_u32(dsm);
    const __half* vsh = (const __half*)(dsm + A_VS);
    __half* Ps   = (__half*)(dsm + 0);
    float*  maxb = (float*)(dsm + A_RED);
    float*  sumb = maxb + 128;

    const int tid  = threadIdx.x;
    const int warp = tid >> 5;
    const int lane = tid & 31;
    const int n = blockIdx.x;
    const int h = blockIdx.y;
    const int b = blockIdx.z;
    const size_t rowbase = (size_t)b * SEQ * CH + (size_t)h * HD;

    // Q hi (64 rows x 8 chunks)
#pragma unroll
    for (int p = 0; p < 2; p++) {
        int idx = tid + p * 256;
        int i  = idx >> 3;
        int ch = idx & 7;
        int kc = ch >> 2, cc = ch & 3;
        cp16(sbase + A_QH + kc * 4096 + sw_off(i, cc),
             Qh + rowbase + (size_t)(n * BS + i) * CH + ch * 8);
    }
    // K hi (128 x 8)
#pragma unroll
    for (int p = 0; p < 4; p++) {
        int idx = tid + p * 256;
        int j  = idx >> 3;
        int ch = idx & 7;
        int kc = ch >> 2, cc = ch & 3;
        int kpos = (n - 1) * BS + j;
        uint32_t off = A_KH + kc * 8192 + sw_off(j, cc);
        if (kpos >= 0)
            cp16(sbase + off, Kh + rowbase + (size_t)kpos * CH + ch * 8);
        else
            *(uint4*)(dsm + off) = make_uint4(0, 0, 0, 0);
    }
    // V fp16 (128 rows x 8 chunks, natural [j][64] layout)
#pragma unroll
    for (int p = 0; p < 4; p++) {
        int idx = tid + p * 256;
        int j  = idx >> 3;
        int ch = idx & 7;
        int kpos = (n - 1) * BS + j;
        uint32_t off = A_VS + j * 128 + ch * 16;
        if (kpos >= 0)
            cp16(sbase + off, Vh + rowbase + (size_t)kpos * CH + ch * 8);
        else
            *(uint4*)(dsm + off) = make_uint4(0, 0, 0, 0);
    }
    cp_commit();
    cp_wait<0>();
    __syncthreads();

    // ---- scores via HMMA
    const int wm = (warp & 3) * 16;
    const int wn = (warp >> 2) * 64;
    const int wh = warp >> 2;
    const int lr = lane & 15;
    const int lc = lane >> 4;

    float acc[8][4];
#pragma unroll
    for (int nf = 0; nf < 8; nf++)
#pragma unroll
        for (int t = 0; t < 4; t++) acc[nf][t] = 0.0f;

#pragma unroll
    for (int kc = 0; kc < 2; kc++)
#pragma unroll
        for (int ks = 0; ks < 2; ks++) {
            const int chnk = ks * 2 + lc;
            uint32_t ah[4], bh[4][4];
            ldsm4(ah[0], ah[1], ah[2], ah[3],
                  sbase + A_QH + kc * 4096 + sw_off(wm + lr, chnk));
#pragma unroll
            for (int g = 0; g < 4; g++) {
                uint32_t off = sw_off(wn + g * 16 + lr, chnk);
                ldsm4(bh[g][0], bh[g][1], bh[g][2], bh[g][3],
                      sbase + A_KH + kc * 8192 + off);
            }
#pragma unroll
            for (int nf = 0; nf < 8; nf++) {
                const int g = nf >> 1, w = nf & 1;
                mma16816(acc[nf], ah, bh[g][w], bh[g][w + 2]);
            }
        }

    const float scale = 0.125f;
    const int r0 = wm + (lane >> 2);
    const int r1 = r0 + 8;
    float rm0 = -1e30f, rm1 = -1e30f;
#pragma unroll
    for (int nf = 0; nf < 8; nf++) {
        const int j0 = wn + nf * 8 + ((lane & 3) << 1);
        const int j1 = j0 + 1;
        bool w0 = (n > 0 || j0 >= BS);
        bool w1 = (n > 0 || j1 >= BS);
        acc[nf][0] = (w0 && j0 <= r0 + BS) ? acc[nf][0] * scale : -1e30f;
        acc[nf][1] = (w1 && j1 <= r0 + BS) ? acc[nf][1] * scale : -1e30f;
        acc[nf][2] = (w0 && j0 <= r1 + BS) ? acc[nf][2] * scale : -1e30f;
        acc[nf][3] = (w1 && j1 <= r1 + BS) ? acc[nf][3] * scale : -1e30f;
        rm0 = fmaxf(rm0, fmaxf(acc[nf][0], acc[nf][1]));
        rm1 = fmaxf(rm1, fmaxf(acc[nf][2], acc[nf][3]));
    }
    rm0 = fmaxf(rm0, __shfl_xor_sync(0xffffffffu, rm0, 1));
    rm0 = fmaxf(rm0, __shfl_xor_sync(0xffffffffu, rm0, 2));
    rm1 = fmaxf(rm1, __shfl_xor_sync(0xffffffffu, rm1, 1));
    rm1 = fmaxf(rm1, __shfl_xor_sync(0xffffffffu, rm1, 2));
    if ((lane & 3) == 0) {
        maxb[wh * 64 + r0] = rm0;
        maxb[wh * 64 + r1] = rm1;
    }
    __syncthreads();
    const float m0 = fmaxf(maxb[r0], maxb[64 + r0]);
    const float m1 = fmaxf(maxb[r1], maxb[64 + r1]);

    float s0 = 0.f, s1 = 0.f;
#pragma unroll
    for (int nf = 0; nf < 8; nf++) {
        acc[nf][0] = __expf(acc[nf][0] - m0);
        acc[nf][1] = __expf(acc[nf][1] - m0);
        acc[nf][2] = __expf(acc[nf][2] - m1);
        acc[nf][3] = __expf(acc[nf][3] - m1);
        s0 += acc[nf][0] + acc[nf][1];
        s1 += acc[nf][2] + acc[nf][3];
    }
    s0 += __shfl_xor_sync(0xffffffffu, s0, 1);
    s0 += __shfl_xor_sync(0xffffffffu, s0, 2);
    s1 += __shfl_xor_sync(0xffffffffu, s1, 1);
    s1 += __shfl_xor_sync(0xffffffffu, s1, 2);
    if ((lane & 3) == 0) {
        sumb[wh * 64 + r0] = s0;
        sumb[wh * 64 + r1] = s1;
    }
    __syncthreads();
    const float inv0 = 1.0f / (sumb[r0] + sumb[64 + r0]);
    const float inv1 = 1.0f / (sumb[r1] + sumb[64 + r1]);

    // store P fp16 (aliases dead Q/K tiles)
#pragma unroll
    for (int nf = 0; nf < 8; nf++) {
        const int j0 = wn + nf * 8 + ((lane & 3) << 1);
        __half2 p0, p1;
        p0.x = __float2half(acc[nf][0] * inv0);
        p0.y = __float2half(acc[nf][1] * inv0);
        p1.x = __float2half(acc[nf][2] * inv1);
        p1.y = __float2half(acc[nf][3] * inv1);
        *(__half2*)&Ps[r0 * PS_STRIDE + j0] = p0;
        *(__half2*)&Ps[r1 * PS_STRIDE + j0] = p1;
    }
    __syncthreads();

    // ---- PV: 4 rows per 16-thread group; j-quads, FFMA2 (V fp16 -> f32)
    const int i0p = (tid >> 4) << 2;
    const int c0  = (tid & 15) << 2;
    unsigned long long o2[4][2];
#pragma unroll
    for (int ii = 0; ii < 4; ii++) { o2[ii][0] = 0ull; o2[ii][1] = 0ull; }

    const int jlim = (i0p + 68 < WIN) ? (i0p + 68) : WIN;
#pragma unroll 1
    for (int j = 0; j < jlim; j += 4) {
        uint2 va = *(const uint2*)&vsh[(j + 0) * 64 + c0];
        uint2 vb = *(const uint2*)&vsh[(j + 1) * 64 + c0];
        uint2 vc = *(const uint2*)&vsh[(j + 2) * 64 + c0];
        uint2 vd = *(const uint2*)&vsh[(j + 3) * 64 + c0];
        float2 a01 = __half22float2(*reinterpret_cast<__half2*>(&va.x));
        float2 a23 = __half22float2(*reinterpret_cast<__half2*>(&va.y));
        float2 b01 = __half22float2(*reinterpret_cast<__half2*>(&vb.x));
        float2 b23 = __half22float2(*reinterpret_cast<__half2*>(&vb.y));
        float2 c01 = __half22float2(*reinterpret_cast<__half2*>(&vc.x));
        float2 c23 = __half22float2(*reinterpret_cast<__half2*>(&vc.y));
        float2 d01 = __half22float2(*reinterpret_cast<__half2*>(&vd.x));
        float2 d23 = __half22float2(*reinterpret_cast<__half2*>(&vd.y));
        unsigned long long A0 = pack2(a01.x, a01.y), A1 = pack2(a23.x, a23.y);
        unsigned long long B0 = pack2(b01.x, b01.y), B1 = pack2(b23.x, b23.y);
        unsigned long long C0 = pack2(c01.x, c01.y), C1 = pack2(c23.x, c23.y);
        unsigned long long D0 = pack2(d01.x, d01.y), D1 = pack2(d23.x, d23.y);
#pragma unroll
        for (int ii = 0; ii < 4; ii++) {
            uint2 pq = *(const uint2*)&Ps[(i0p + ii) * PS_STRIDE + j];
            float2 p01 = __half22float2(*reinterpret_cast<__half2*>(&pq.x));
            float2 p23 = __half22float2(*reinterpret_cast<__half2*>(&pq.y));
            unsigned long long px = pack2(p01.x, p01.x);
            unsigned long long py = pack2(p01.y, p01.y);
            unsigned long long pz = pack2(p23.x, p23.x);
            unsigned long long pw = pack2(p23.y, p23.y);
            fma2(o2[ii][0], px, A0); fma2(o2[ii][1], px, A1);
            fma2(o2[ii][0], py, B0); fma2(o2[ii][1], py, B1);
            fma2(o2[ii][0], pz, C0); fma2(o2[ii][1], pz, C1);
            fma2(o2[ii][0], pw, D0); fma2(o2[ii][1], pw, D1);
        }
    }
#pragma unroll
    for (int ii = 0; ii < 4; ii++) {
        float o0, o1, o2f, o3;
        unpack2(o2[ii][0], o0, o1);
        unpack2(o2[ii][1], o2f, o3);
        const size_t oidx = rowbase + (size_t)(n * BS + i0p + ii) * CH + c0;
        __half2 hp0, hp1;
        hp0.x = __float2half(o0);  hp0.y = __float2half(o1);
        hp1.x = __float2half(o2f); hp1.y = __float2half(o3);
        *(__half2*)(Ohi + oidx)     = hp0;
        *(__half2*)(Ohi + oidx + 2) = hp1;
    }
}

// ---------------------------------------------------------------------------
extern "C" void kernel_launch(void* const* d_in, const int* in_sizes, int n_in,
                              void* d_out, int out_size)
{
    const float* x  = (const float*)d_in[0];
    const float* Wq = (const float*)d_in[1];
    const float* bq = (const float*)d_in[2];
    const float* Wk = (const float*)d_in[3];
    const float* bk = (const float*)d_in[4];
    const float* Wv = (const float*)d_in[5];
    const float* bv = (const float*)d_in[6];
    const float* Wo = (const float*)d_in[7];
    const float* bo = (const float*)d_in[8];
    float* out = (float*)d_out;

    __half *qh, *kh, *vh, *ahi, *phi, *whi;
    cudaGetSymbolAddress((void**)&qh,  g_Qh);
    cudaGetSymbolAddress((void**)&kh,  g_Kh);
    cudaGetSymbolAddress((void**)&vh,  g_Vh);
    cudaGetSymbolAddress((void**)&ahi, g_Ahi);
    cudaGetSymbolAddress((void**)&phi, g_Phi);
    cudaGetSymbolAddress((void**)&whi, g_Whi);

    cudaFuncSetAttribute(attn_kernel,
                         cudaFuncAttributeMaxDynamicSharedMemorySize, ATTN_SMEM_BYTES);
    cudaFuncSetAttribute(gemm_out,
                         cudaFuncAttributeMaxDynamicSharedMemorySize, GEMM_SMEM);
    cudaFuncSetAttribute(gemm_qkv,
                         cudaFuncAttributeMaxDynamicSharedMemorySize, GEMM_SMEM);

    const int NX = MROWS * CH;
    const int NW = CH * CH;

    to_f16_x<<<NX / 2048, 256>>>(x, ahi);
    to_f16_w4<<<2048, 256>>>(Wq, Wk, Wv, Wo, whi);

    gemm_qkv<<<dim3(24, MROWS / 128), 256, GEMM_SMEM>>>(
        ahi, whi, bq, bk, bv, qh, kh, vh);

    attn_kernel<<<dim3(NB, NH, BATCH), 256, ATTN_SMEM_BYTES>>>(
        qh, kh, vh, phi);

    gemm_out<<<dim3(8, MROWS / 128), 256, GEMM_SMEM>>>(
        phi, whi + 3 * (size_t)NW, bo, out);
}